// round 1
// baseline (speedup 1.0000x reference)
#include <cuda_runtime.h>
#include <cuda_bf16.h>
#include <math.h>

// ---------------- problem constants ----------------
#define B    8
#define S    512
#define E    768
#define NH   12
#define DH   64
#define FF   3072
#define L    6
#define VV   32000
#define CC   10
#define M4   (B*S)          // 4096 rows
#define HSZ  (S*DH)         // 32768 per-head elems
#define EPSL 1e-5f

// ---------------- scratch (device globals; no allocation allowed) ----------------
__device__ float g_h [M4*E];
__device__ float g_q [M4*E];
__device__ float g_k [M4*E];
__device__ float g_v [M4*E];
__device__ float g_t [M4*E];          // ctx / pre-LN buffer
__device__ float g_ff[M4*FF];
__device__ float g_sc[(size_t)B*NH*S*S];   // 96*512*512 scores

// ---------------- embedding gather ----------------
__global__ void k_embed(const int* __restrict__ x, const float* __restrict__ emb,
                        float* __restrict__ h) {
    int row = blockIdx.x;                  // 0..4095
    int tok = x[row];
    const float4* src = (const float4*)(emb + (size_t)tok * E);
    float4*       dst = (float4*)(h + (size_t)row * E);
    dst[threadIdx.x] = src[threadIdx.x];   // 192 threads * 4 = 768
}

// ---------------- generic SGEMM: C = A[MxK] @ W[KxN] + bias (+res) (+relu) ------
// BM=BN=128, BK=8, 256 threads, 8x8 per thread (split 4x4 quadrants).
__global__ void k_sgemm(const float* __restrict__ A, const float* __restrict__ W,
                        const float* __restrict__ bias, const float* __restrict__ res,
                        float* __restrict__ C, int M, int N, int K, int relu) {
    __shared__ float As[8][128];
    __shared__ float Ws[8][128];

    const int tid = threadIdx.x;
    const int tx  = tid & 15;
    const int ty  = tid >> 4;
    const int bm  = blockIdx.y * 128;
    const int bn  = blockIdx.x * 128;

    float acc[8][8];
#pragma unroll
    for (int i = 0; i < 8; i++)
#pragma unroll
        for (int j = 0; j < 8; j++) acc[i][j] = 0.f;

    const int arow  = tid >> 1;            // 0..127
    const int acol4 = (tid & 1) * 4;       // 0 or 4
    const int wrow  = tid >> 5;            // 0..7
    const int wcol  = (tid & 31) * 4;      // 0..124

    const float* Aptr = A + (size_t)(bm + arow) * K + acol4;
    const float* Wptr = W + (size_t)wrow * N + bn + wcol;

    for (int k0 = 0; k0 < K; k0 += 8) {
        float4 av = *(const float4*)Aptr;  Aptr += 8;
        As[acol4 + 0][arow] = av.x;
        As[acol4 + 1][arow] = av.y;
        As[acol4 + 2][arow] = av.z;
        As[acol4 + 3][arow] = av.w;
        *(float4*)&Ws[wrow][wcol] = *(const float4*)Wptr;
        Wptr += (size_t)8 * N;
        __syncthreads();

#pragma unroll
        for (int kk = 0; kk < 8; kk++) {
            float a[8], b[8];
            *(float4*)&a[0] = *(const float4*)&As[kk][ty * 4];
            *(float4*)&a[4] = *(const float4*)&As[kk][64 + ty * 4];
            *(float4*)&b[0] = *(const float4*)&Ws[kk][tx * 4];
            *(float4*)&b[4] = *(const float4*)&Ws[kk][64 + tx * 4];
#pragma unroll
            for (int i = 0; i < 8; i++)
#pragma unroll
                for (int j = 0; j < 8; j++) acc[i][j] = fmaf(a[i], b[j], acc[i][j]);
        }
        __syncthreads();
    }

    // epilogue: quadrant (qi,qj) in {0,64}
#pragma unroll
    for (int i = 0; i < 8; i++) {
        int r = bm + ((i < 4) ? (ty * 4 + i) : (64 + ty * 4 + i - 4));
#pragma unroll
        for (int jq = 0; jq < 2; jq++) {
            int c = bn + jq * 64 + tx * 4;
            float4 o;
            float* ap = &acc[i][jq * 4];
            o.x = ap[0] + bias[c + 0];
            o.y = ap[1] + bias[c + 1];
            o.z = ap[2] + bias[c + 2];
            o.w = ap[3] + bias[c + 3];
            if (relu) {
                o.x = fmaxf(o.x, 0.f); o.y = fmaxf(o.y, 0.f);
                o.z = fmaxf(o.z, 0.f); o.w = fmaxf(o.w, 0.f);
            }
            if (res) {
                const float4 rv = *(const float4*)&res[(size_t)r * N + c];
                o.x += rv.x; o.y += rv.y; o.z += rv.z; o.w += rv.w;
            }
            *(float4*)&C[(size_t)r * N + c] = o;
        }
    }
}

// ---------------- attention scores: per head z, S[512,512] = Q[512,64] K^T * 1/8
__global__ void k_scores(const float* __restrict__ q, const float* __restrict__ kmat,
                         float* __restrict__ sc) {
    const int z  = blockIdx.z;                  // 0..95 ; head offset = z*32768
    const float* Q = q    + (size_t)z * HSZ;
    const float* K = kmat + (size_t)z * HSZ;
    const int bm = blockIdx.y * 64;
    const int bn = blockIdx.x * 64;

    __shared__ float Qs[64][65];
    __shared__ float Ks[64][65];

    const int tid = threadIdx.x;
    const int tx  = tid & 15;
    const int ty  = tid >> 4;

#pragma unroll
    for (int rr = 0; rr < 4; rr++) {
        int row = (tid >> 4) + rr * 16;
        int c4  = (tid & 15) * 4;
        float4 qv = *(const float4*)&Q[(size_t)(bm + row) * 64 + c4];
        Qs[row][c4 + 0] = qv.x; Qs[row][c4 + 1] = qv.y;
        Qs[row][c4 + 2] = qv.z; Qs[row][c4 + 3] = qv.w;
        float4 kv = *(const float4*)&K[(size_t)(bn + row) * 64 + c4];
        Ks[row][c4 + 0] = kv.x; Ks[row][c4 + 1] = kv.y;
        Ks[row][c4 + 2] = kv.z; Ks[row][c4 + 3] = kv.w;
    }
    __syncthreads();

    float acc[4][4];
#pragma unroll
    for (int i = 0; i < 4; i++)
#pragma unroll
        for (int j = 0; j < 4; j++) acc[i][j] = 0.f;

#pragma unroll 8
    for (int k = 0; k < 64; k++) {
        float a[4], b[4];
#pragma unroll
        for (int i = 0; i < 4; i++) a[i] = Qs[ty * 4 + i][k];
#pragma unroll
        for (int j = 0; j < 4; j++) b[j] = Ks[tx * 4 + j][k];
#pragma unroll
        for (int i = 0; i < 4; i++)
#pragma unroll
            for (int j = 0; j < 4; j++) acc[i][j] = fmaf(a[i], b[j], acc[i][j]);
    }

    const float scale = 0.125f; // 1/sqrt(64)
#pragma unroll
    for (int i = 0; i < 4; i++) {
        float4 o;
        o.x = acc[i][0] * scale; o.y = acc[i][1] * scale;
        o.z = acc[i][2] * scale; o.w = acc[i][3] * scale;
        size_t r = (size_t)z * S + bm + ty * 4 + i;
        *(float4*)&sc[r * S + bn + tx * 4] = o;
    }
}

// ---------------- softmax over rows of 512 ----------------
__global__ void k_softmax(float* __restrict__ sc) {
    __shared__ float red[256];
    float* p = sc + (size_t)blockIdx.x * S;
    int t = threadIdx.x;
    float v0 = p[t], v1 = p[t + 256];

    float m = fmaxf(v0, v1);
    red[t] = m; __syncthreads();
    for (int s = 128; s > 0; s >>= 1) {
        if (t < s) red[t] = fmaxf(red[t], red[t + s]);
        __syncthreads();
    }
    m = red[0]; __syncthreads();

    float e0 = expf(v0 - m), e1 = expf(v1 - m);
    red[t] = e0 + e1; __syncthreads();
    for (int s = 128; s > 0; s >>= 1) {
        if (t < s) red[t] += red[t + s];
        __syncthreads();
    }
    float inv = 1.0f / red[0];
    p[t] = e0 * inv;
    p[t + 256] = e1 * inv;
}

// ---------------- ctx: per head z, O[512,64] = P[512,512] @ V[512,64] ----------
__global__ void k_ctx(const float* __restrict__ sc, const float* __restrict__ v,
                      float* __restrict__ ctx) {
    const int z = blockIdx.z;
    const float* P = sc  + (size_t)z * S * S;
    const float* V = v   + (size_t)z * HSZ;
    float*       O = ctx + (size_t)z * HSZ;
    const int bm = blockIdx.y * 64;

    __shared__ float Ps[16][64];
    __shared__ float Vs[16][64];

    const int tid = threadIdx.x;
    const int tx  = tid & 15;
    const int ty  = tid >> 4;

    float acc[4][4];
#pragma unroll
    for (int i = 0; i < 4; i++)
#pragma unroll
        for (int j = 0; j < 4; j++) acc[i][j] = 0.f;

    const int prow = tid >> 2, pcol = (tid & 3) * 4;
    const int vrow = tid >> 4, vcol = (tid & 15) * 4;

    for (int k0 = 0; k0 < S; k0 += 16) {
        float4 pv = *(const float4*)&P[(size_t)(bm + prow) * S + k0 + pcol];
        Ps[pcol + 0][prow] = pv.x; Ps[pcol + 1][prow] = pv.y;
        Ps[pcol + 2][prow] = pv.z; Ps[pcol + 3][prow] = pv.w;
        *(float4*)&Vs[vrow][vcol] = *(const float4*)&V[(size_t)(k0 + vrow) * 64 + vcol];
        __syncthreads();

#pragma unroll
        for (int kk = 0; kk < 16; kk++) {
            float a[4], b[4];
            *(float4*)&a[0] = *(const float4*)&Ps[kk][ty * 4];
            *(float4*)&b[0] = *(const float4*)&Vs[kk][tx * 4];
#pragma unroll
            for (int i = 0; i < 4; i++)
#pragma unroll
                for (int j = 0; j < 4; j++) acc[i][j] = fmaf(a[i], b[j], acc[i][j]);
        }
        __syncthreads();
    }

#pragma unroll
    for (int i = 0; i < 4; i++) {
        float4 o = { acc[i][0], acc[i][1], acc[i][2], acc[i][3] };
        *(float4*)&O[(size_t)(bm + ty * 4 + i) * 64 + tx * 4] = o;
    }
}

// ---------------- layernorm over rows of 768 ----------------
__global__ void k_ln(const float* __restrict__ in, float* __restrict__ out,
                     const float* __restrict__ g, const float* __restrict__ b) {
    __shared__ float r1[256];
    __shared__ float r2[256];
    const int row = blockIdx.x, t = threadIdx.x;
    const float* p = in + (size_t)row * E;

    float x0 = p[t], x1 = p[t + 256], x2 = p[t + 512];
    r1[t] = x0 + x1 + x2;
    r2[t] = x0 * x0 + x1 * x1 + x2 * x2;
    __syncthreads();
    for (int s = 128; s > 0; s >>= 1) {
        if (t < s) { r1[t] += r1[t + s]; r2[t] += r2[t + s]; }
        __syncthreads();
    }
    const float mean = r1[0] * (1.0f / E);
    const float var  = r2[0] * (1.0f / E) - mean * mean;
    const float inv  = rsqrtf(var + EPSL);

    float* o = out + (size_t)row * E;
    o[t      ] = (x0 - mean) * inv * g[t      ] + b[t      ];
    o[t + 256] = (x1 - mean) * inv * g[t + 256] + b[t + 256];
    o[t + 512] = (x2 - mean) * inv * g[t + 512] + b[t + 512];
}

// ---------------- classifier: out[8,10] = h[8, S*E] @ Wc + bc ----------------
__global__ void k_cls(const float* __restrict__ h, const float* __restrict__ Wc,
                      const float* __restrict__ bc, float* __restrict__ out) {
    __shared__ float red[256];
    const int bidx = blockIdx.x;            // b*10 + c
    const int bb = bidx / CC, c = bidx % CC;
    const float* hr = h + (size_t)bb * S * E;
    const int t = threadIdx.x;

    float s = 0.f;
    for (int i = t; i < S * E; i += 256)
        s = fmaf(hr[i], Wc[(size_t)i * CC + c], s);
    red[t] = s; __syncthreads();
    for (int k = 128; k > 0; k >>= 1) {
        if (t < k) red[t] += red[t + k];
        __syncthreads();
    }
    if (t == 0) out[bidx] = red[0] + bc[c];
}

// ---------------- launch ----------------
extern "C" void kernel_launch(void* const* d_in, const int* in_sizes, int n_in,
                              void* d_out, int out_size) {
    const int*   x    = (const int*)  d_in[0];
    const float* emb  = (const float*)d_in[1];
    const float* Wq   = (const float*)d_in[2];
    const float* bq   = (const float*)d_in[3];
    const float* Wk   = (const float*)d_in[4];
    const float* bk   = (const float*)d_in[5];
    const float* Wv   = (const float*)d_in[6];
    const float* bv   = (const float*)d_in[7];
    const float* Wo   = (const float*)d_in[8];
    const float* bo   = (const float*)d_in[9];
    const float* ln1g = (const float*)d_in[10];
    const float* ln1b = (const float*)d_in[11];
    const float* W1   = (const float*)d_in[12];
    const float* b1   = (const float*)d_in[13];
    const float* W2   = (const float*)d_in[14];
    const float* b2   = (const float*)d_in[15];
    const float* ln2g = (const float*)d_in[16];
    const float* ln2b = (const float*)d_in[17];
    const float* Wc   = (const float*)d_in[18];
    const float* bc   = (const float*)d_in[19];
    float* out = (float*)d_out;

    float *h, *q, *k, *v, *t, *ff, *sc;
    cudaGetSymbolAddress((void**)&h,  g_h);
    cudaGetSymbolAddress((void**)&q,  g_q);
    cudaGetSymbolAddress((void**)&k,  g_k);
    cudaGetSymbolAddress((void**)&v,  g_v);
    cudaGetSymbolAddress((void**)&t,  g_t);
    cudaGetSymbolAddress((void**)&ff, g_ff);
    cudaGetSymbolAddress((void**)&sc, g_sc);

    // embedding
    k_embed<<<M4, 192>>>(x, emb, h);

    const dim3 gEE(E / 128, M4 / 128);     // (6, 32)
    const dim3 gF1(FF / 128, M4 / 128);    // (24, 32)
    const dim3 gSc(8, 8, B * NH);          // scores tiles
    const dim3 gCx(1, 8, B * NH);          // ctx tiles

    for (int l = 0; l < L; l++) {
        const float* wq = Wq + (size_t)l * E * E;  const float* pbq = bq + (size_t)l * E;
        const float* wk = Wk + (size_t)l * E * E;  const float* pbk = bk + (size_t)l * E;
        const float* wv = Wv + (size_t)l * E * E;  const float* pbv = bv + (size_t)l * E;
        const float* wo = Wo + (size_t)l * E * E;  const float* pbo = bo + (size_t)l * E;
        const float* w1 = W1 + (size_t)l * E * FF; const float* pb1 = b1 + (size_t)l * FF;
        const float* w2 = W2 + (size_t)l * FF * E; const float* pb2 = b2 + (size_t)l * E;

        // QKV
        k_sgemm<<<gEE, 256>>>(h, wq, pbq, nullptr, q, M4, E, E, 0);
        k_sgemm<<<gEE, 256>>>(h, wk, pbk, nullptr, k, M4, E, E, 0);
        k_sgemm<<<gEE, 256>>>(h, wv, pbv, nullptr, v, M4, E, E, 0);

        // attention
        k_scores <<<gSc, 256>>>(q, k, sc);
        k_softmax<<<B * NH * S, 256>>>(sc);
        k_ctx    <<<gCx, 256>>>(sc, v, t);

        // output proj + residual, LN1  (q reused as pre-LN buffer)
        k_sgemm<<<gEE, 256>>>(t, wo, pbo, h, q, M4, E, E, 0);
        k_ln<<<M4, 256>>>(q, h, ln1g + (size_t)l * E, ln1b + (size_t)l * E);

        // FFN + residual, LN2
        k_sgemm<<<gF1, 256>>>(h, w1, pb1, nullptr, ff, M4, FF, E, 1);
        k_sgemm<<<gEE, 256>>>(ff, w2, pb2, h, q, M4, E, FF, 0);
        k_ln<<<M4, 256>>>(q, h, ln2g + (size_t)l * E, ln2b + (size_t)l * E);
    }

    // classifier
    k_cls<<<B * CC, 256>>>(h, Wc, bc, out);
}

// round 3
// speedup vs baseline: 2.5644x; 2.5644x over previous
#include <cuda_runtime.h>
#include <cuda_bf16.h>
#include <cstdint>
#include <math.h>

// ---------------- problem constants ----------------
#define B    8
#define S    512
#define E    768
#define NH   12
#define DH   64
#define FF   3072
#define L    6
#define CC   10
#define M4   (B*S)          // 4096 rows
#define HSZ  (S*DH)         // 32768 per-head elems
#define NHEAD (B*NH)        // 96
#define EPSL 1e-5f
#define SE   (S*E)          // 393216

// per-layer transposed-weight block (elems): Wq,Wk,Wv (contig), Wo, W1t, W2t
#define LW   (4*E*E + 2*E*FF)
#define OFF_Q 0
#define OFF_K (E*E)
#define OFF_V (2*E*E)
#define OFF_O (3*E*E)
#define OFF_1 (4*E*E)
#define OFF_2 (4*E*E + E*FF)

// ---------------- scratch (device globals) ----------------
__device__ float g_h [M4*E];
__device__ float g_t [M4*E];                    // pre-LN buffer; reused as cls partials
__device__ __nv_bfloat16 g_hh[M4*E], g_hl[M4*E];
__device__ __nv_bfloat16 g_qkv[3*M4*E];         // q,k,v contiguous
__device__ __nv_bfloat16 g_vt[M4*E];
__device__ __nv_bfloat16 g_ch[M4*E], g_cl[M4*E];
__device__ __nv_bfloat16 g_fh[M4*FF], g_fl[M4*FF];
__device__ __nv_bfloat16 g_sc[(size_t)NHEAD*S*S];
__device__ __nv_bfloat16 g_wh[(size_t)L*LW], g_wl[(size_t)L*LW];
__device__ float g_bqkv[L*3*E];

// ---------------- asm helpers ----------------
__device__ __forceinline__ uint32_t smem_u32(const void* p) {
    uint32_t a;
    asm("{ .reg .u64 t; cvta.to.shared.u64 t, %1; cvt.u32.u64 %0, t; }" : "=r"(a) : "l"(p));
    return a;
}
__device__ __forceinline__ void ldsm4(uint32_t* r, uint32_t a) {
    asm volatile("ldmatrix.sync.aligned.m8n8.x4.shared.b16 {%0,%1,%2,%3}, [%4];"
        : "=r"(r[0]), "=r"(r[1]), "=r"(r[2]), "=r"(r[3]) : "r"(a));
}
__device__ __forceinline__ void mma_bf16(float* c, const uint32_t* a, const uint32_t* b) {
    asm volatile("mma.sync.aligned.m16n8k16.row.col.f32.bf16.bf16.f32 "
        "{%0,%1,%2,%3}, {%4,%5,%6,%7}, {%8,%9}, {%0,%1,%2,%3};"
        : "+f"(c[0]), "+f"(c[1]), "+f"(c[2]), "+f"(c[3])
        : "r"(a[0]), "r"(a[1]), "r"(a[2]), "r"(a[3]), "r"(b[0]), "r"(b[1]));
}
#define CPA(dst, src) asm volatile("cp.async.cg.shared.global [%0], [%1], 16;" :: "r"(dst), "l"(src))
#define CPC() asm volatile("cp.async.commit_group;" ::: "memory")
#define CPW(n) asm volatile("cp.async.wait_group %0;" :: "n"(n) : "memory")

// ================= HMMA GEMM =================
// D[row,col] = scale*sum_k A[row,k]*B[col,k] (+bias)(relu)(+res)
// DUAL: acc += Ah*Bh + Ah*Bl + Al*Bh (bf16 hi/lo split, fp32-class accuracy)
// BM=128 fixed; BN in {128, 64}; BK=32; 256 threads; 2-stage cp.async pipeline.
template<int BN, bool DUAL>
__global__ void __launch_bounds__(256)
k_mma(const __nv_bfloat16* __restrict__ Ah, const __nv_bfloat16* __restrict__ Al,
      const __nv_bfloat16* __restrict__ Bh, const __nv_bfloat16* __restrict__ Bl,
      const float* __restrict__ bias, const float* __restrict__ res,
      float* __restrict__ Cf, __nv_bfloat16* __restrict__ Chi, __nv_bfloat16* __restrict__ Clo,
      int N, int K, size_t sAz, size_t sBz, size_t sCz, size_t bsz,
      float scale, int relu) {
    extern __shared__ char sm[];
    constexpr int WN  = (BN == 128) ? 4 : 2;   // warps along N
    constexpr int WM  = 8 / WN;                // 2 or 4
    constexpr int WTM = 128 / WM;              // 64 or 32
    constexpr int WTN = BN / WN;               // 32
    constexpr int MF  = WTM / 16;              // 4 or 2
    constexpr int NF  = WTN / 8;               // 4
    constexpr int ATILE = 128 * 80;            // 128 rows x (32+8) bf16
    constexpr int BTILE = BN * 80;
    constexpr int HALF  = ATILE + BTILE;       // hi section size
    constexpr int STAGE = HALF * (DUAL ? 2 : 1);

    const uint32_t smb = smem_u32(sm);
    const int tid = threadIdx.x, lane = tid & 31, wid = tid >> 5;
    const int wm = wid / WN, wn = wid % WN;
    const int bm = blockIdx.y * 128, bn = blockIdx.x * BN;
    const size_t zA = (size_t)blockIdx.z * sAz, zB = (size_t)blockIdx.z * sBz;
    const __nv_bfloat16* pA  = Ah + zA + (size_t)bm * K;
    const __nv_bfloat16* pB  = Bh + zB + (size_t)bn * K;
    const __nv_bfloat16* pAl = DUAL ? Al + zA + (size_t)bm * K : nullptr;
    const __nv_bfloat16* pBl = DUAL ? Bl + zB + (size_t)bn * K : nullptr;

    float acc[MF][NF][4];
#pragma unroll
    for (int i = 0; i < MF; i++)
#pragma unroll
        for (int j = 0; j < NF; j++)
#pragma unroll
            for (int q = 0; q < 4; q++) acc[i][j][q] = 0.f;

    // per-thread ldmatrix offsets
    const uint32_t a_off = (uint32_t)(lane & 15) * 80 + (uint32_t)(lane >> 4) * 16;
    const uint32_t b_off = (uint32_t)((lane & 7) + ((lane >> 1) & 8)) * 80
                         + (uint32_t)((lane >> 3) & 1) * 16;

    const int KT = K >> 5;

    // ---- stage loader ----
    auto load_stage = [&](int s, int kt) {
        const int k0 = kt << 5;
        const uint32_t base = smb + s * STAGE;
#pragma unroll 2
        for (int cid = tid; cid < 512; cid += 256) {
            const int row = cid >> 2, p = cid & 3;
            const uint32_t d = base + row * 80 + p * 16;
            const size_t go = (size_t)row * K + k0 + p * 8;
            CPA(d, pA + go);
            if (DUAL) CPA(d + HALF, pAl + go);
        }
        for (int cid = tid; cid < BN * 4; cid += 256) {
            const int row = cid >> 2, p = cid & 3;
            const uint32_t d = base + ATILE + row * 80 + p * 16;
            const size_t go = (size_t)row * K + k0 + p * 8;
            CPA(d, pB + go);
            if (DUAL) CPA(d + HALF, pBl + go);
        }
    };

    load_stage(0, 0); CPC();

    for (int kt = 0; kt < KT; ++kt) {
        if (kt + 1 < KT) { load_stage((kt + 1) & 1, kt + 1); CPC(); CPW(1); }
        else CPW(0);
        __syncthreads();

        const uint32_t aB = smb + (kt & 1) * STAGE + wm * WTM * 80 + a_off;
        const uint32_t bB = smb + (kt & 1) * STAGE + ATILE + wn * WTN * 80 + b_off;
#pragma unroll
        for (int ks = 0; ks < 2; ++ks) {
            uint32_t aR[MF][4], bR[NF / 2][4], bRl[NF / 2][4];
#pragma unroll
            for (int n2 = 0; n2 < NF / 2; n2++)
                ldsm4(bR[n2], bB + n2 * 16 * 80 + ks * 32);
            if (DUAL) {
#pragma unroll
                for (int n2 = 0; n2 < NF / 2; n2++)
                    ldsm4(bRl[n2], bB + HALF + n2 * 16 * 80 + ks * 32);
            }
#pragma unroll
            for (int mi = 0; mi < MF; mi++)
                ldsm4(aR[mi], aB + mi * 16 * 80 + ks * 32);

#pragma unroll
            for (int mi = 0; mi < MF; mi++)
#pragma unroll
                for (int n2 = 0; n2 < NF / 2; n2++) {
                    mma_bf16(acc[mi][n2 * 2],     aR[mi], &bR[n2][0]);
                    mma_bf16(acc[mi][n2 * 2 + 1], aR[mi], &bR[n2][2]);
                }
            if (DUAL) {
#pragma unroll
                for (int mi = 0; mi < MF; mi++)
#pragma unroll
                    for (int n2 = 0; n2 < NF / 2; n2++) {
                        mma_bf16(acc[mi][n2 * 2],     aR[mi], &bRl[n2][0]);
                        mma_bf16(acc[mi][n2 * 2 + 1], aR[mi], &bRl[n2][2]);
                    }
#pragma unroll
                for (int mi = 0; mi < MF; mi++)
                    ldsm4(aR[mi], aB + HALF + mi * 16 * 80 + ks * 32);
#pragma unroll
                for (int mi = 0; mi < MF; mi++)
#pragma unroll
                    for (int n2 = 0; n2 < NF / 2; n2++) {
                        mma_bf16(acc[mi][n2 * 2],     aR[mi], &bR[n2][0]);
                        mma_bf16(acc[mi][n2 * 2 + 1], aR[mi], &bR[n2][2]);
                    }
            }
        }
        __syncthreads();
    }

    // ---- epilogue ----
    const size_t cz = (size_t)blockIdx.z * sCz;
    const float* bz = bias ? bias + (size_t)blockIdx.z * bsz : nullptr;
    const int r0 = bm + wm * WTM + (lane >> 2);
    const int c0 = bn + wn * WTN + (lane & 3) * 2;

#pragma unroll
    for (int mi = 0; mi < MF; mi++) {
#pragma unroll
        for (int ni = 0; ni < NF; ni++) {
            const int col = c0 + ni * 8;
#pragma unroll
            for (int half = 0; half < 2; half++) {
                const int row = r0 + mi * 16 + half * 8;
                float v0 = acc[mi][ni][half * 2]     * scale;
                float v1 = acc[mi][ni][half * 2 + 1] * scale;
                if (bz) { v0 += bz[col]; v1 += bz[col + 1]; }
                if (relu) { v0 = fmaxf(v0, 0.f); v1 = fmaxf(v1, 0.f); }
                if (res) {
                    const float2 rv = *(const float2*)&res[(size_t)row * N + col];
                    v0 += rv.x; v1 += rv.y;
                }
                const size_t o = cz + (size_t)row * N + col;
                if (Cf) { float2 f = {v0, v1}; *(float2*)&Cf[o] = f; }
                if (Chi) {
                    const __nv_bfloat16 h0 = __float2bfloat16(v0);
                    const __nv_bfloat16 h1 = __float2bfloat16(v1);
                    __nv_bfloat162 hv; hv.x = h0; hv.y = h1;
                    *(__nv_bfloat162*)&Chi[o] = hv;
                    if (Clo) {
                        __nv_bfloat162 lv;
                        lv.x = __float2bfloat16(v0 - __bfloat162float(h0));
                        lv.y = __float2bfloat16(v1 - __bfloat162float(h1));
                        *(__nv_bfloat162*)&Clo[o] = lv;
                    }
                }
            }
        }
    }
}

// ---------------- weight transpose + bf16 hi/lo split: W[K,N] -> Wt[N,K] ------
__global__ void k_wt(const float* __restrict__ W, __nv_bfloat16* __restrict__ Th,
                     __nv_bfloat16* __restrict__ Tl, int K, int N) {
    __shared__ float t[32][33];
    const int k0 = blockIdx.y * 32, n0 = blockIdx.x * 32;
    const int tx = threadIdx.x & 31, ty = threadIdx.x >> 5;
#pragma unroll
    for (int i = 0; i < 4; i++)
        t[ty + i * 8][tx] = W[(size_t)(k0 + ty + i * 8) * N + n0 + tx];
    __syncthreads();
#pragma unroll
    for (int i = 0; i < 4; i++) {
        const float v = t[tx][ty + i * 8];
        const __nv_bfloat16 hi = __float2bfloat16(v);
        const size_t o = (size_t)(n0 + ty + i * 8) * K + k0 + tx;
        Th[o] = hi;
        Tl[o] = __float2bfloat16(v - __bfloat162float(hi));
    }
}

// ---------------- pack qkv biases contiguously ----------------
__global__ void k_pack3(const float* __restrict__ a, const float* __restrict__ b,
                        const float* __restrict__ c, float* __restrict__ o) {
    const int i = blockIdx.x * 256 + threadIdx.x;
    if (i < E) { o[i] = a[i]; o[E + i] = b[i]; o[2 * E + i] = c[i]; }
}

// ---------------- embedding gather + hi/lo ----------------
__global__ void k_embed(const int* __restrict__ x, const float* __restrict__ emb,
                        float* __restrict__ h, __nv_bfloat16* __restrict__ hh,
                        __nv_bfloat16* __restrict__ hl) {
    const int row = blockIdx.x;
    const int tok = x[row];
    for (int i = threadIdx.x; i < E; i += 256) {
        const float v = emb[(size_t)tok * E + i];
        const size_t o = (size_t)row * E + i;
        h[o] = v;
        const __nv_bfloat16 hi = __float2bfloat16(v);
        hh[o] = hi;
        hl[o] = __float2bfloat16(v - __bfloat162float(hi));
    }
}

// ---------------- V transpose (per head): [512,64] -> [64,512] bf16 -----------
__global__ void k_vt(const __nv_bfloat16* __restrict__ v, __nv_bfloat16* __restrict__ vt) {
    __shared__ __nv_bfloat16 t[64][65];
    const int z = blockIdx.y, s0 = blockIdx.x * 64;
    const int tid = threadIdx.x;
    for (int i = tid; i < 64 * 32; i += 256) {
        const int r = i >> 5, c2 = (i & 31) * 2;
        const __nv_bfloat162 u = *(const __nv_bfloat162*)(v + (size_t)z * HSZ + (size_t)(s0 + r) * 64 + c2);
        t[r][c2] = u.x; t[r][c2 + 1] = u.y;
    }
    __syncthreads();
    for (int i = tid; i < 64 * 32; i += 256) {
        const int d = i >> 5, s2 = (i & 31) * 2;
        __nv_bfloat162 p; p.x = t[s2][d]; p.y = t[s2 + 1][d];
        *(__nv_bfloat162*)(vt + (size_t)z * HSZ + (size_t)d * S + s0 + s2) = p;
    }
}

// ---------------- softmax over rows of 512, bf16 in/out ----------------
__global__ void k_softmax(__nv_bfloat16* __restrict__ sc) {
    __shared__ float red[256];
    __nv_bfloat16* p = sc + (size_t)blockIdx.x * S;
    const int t = threadIdx.x;
    const float v0 = __bfloat162float(p[t]), v1 = __bfloat162float(p[t + 256]);

    red[t] = fmaxf(v0, v1); __syncthreads();
    for (int s = 128; s > 0; s >>= 1) {
        if (t < s) red[t] = fmaxf(red[t], red[t + s]);
        __syncthreads();
    }
    const float m = red[0]; __syncthreads();

    const float e0 = expf(v0 - m), e1 = expf(v1 - m);
    red[t] = e0 + e1; __syncthreads();
    for (int s = 128; s > 0; s >>= 1) {
        if (t < s) red[t] += red[t + s];
        __syncthreads();
    }
    const float inv = 1.0f / red[0];
    p[t]       = __float2bfloat16(e0 * inv);
    p[t + 256] = __float2bfloat16(e1 * inv);
}

// ---------------- layernorm (fp32 in; fp32 + bf16 hi/lo out) ----------------
__global__ void k_ln(const float* __restrict__ in, float* __restrict__ out,
                     __nv_bfloat16* __restrict__ oh, __nv_bfloat16* __restrict__ ol,
                     const float* __restrict__ g, const float* __restrict__ b) {
    __shared__ float r1[256];
    __shared__ float r2[256];
    const int row = blockIdx.x, t = threadIdx.x;
    const float* p = in + (size_t)row * E;

    const float x0 = p[t], x1 = p[t + 256], x2 = p[t + 512];
    r1[t] = x0 + x1 + x2;
    r2[t] = x0 * x0 + x1 * x1 + x2 * x2;
    __syncthreads();
    for (int s = 128; s > 0; s >>= 1) {
        if (t < s) { r1[t] += r1[t + s]; r2[t] += r2[t + s]; }
        __syncthreads();
    }
    const float mean = r1[0] * (1.0f / E);
    const float var  = r2[0] * (1.0f / E) - mean * mean;
    const float inv  = rsqrtf(var + EPSL);

    const size_t base = (size_t)row * E;
#pragma unroll
    for (int k = 0; k < 3; k++) {
        const int idx = t + k * 256;
        const float xv = (k == 0) ? x0 : (k == 1) ? x1 : x2;
        const float v = (xv - mean) * inv * g[idx] + b[idx];
        out[base + idx] = v;
        const __nv_bfloat16 hi = __float2bfloat16(v);
        oh[base + idx] = hi;
        ol[base + idx] = __float2bfloat16(v - __bfloat162float(hi));
    }
}

// ---------------- classifier: partials then reduce ----------------
#define CLS_P 16
#define CLS_CHUNK (SE / CLS_P)   // 24576
__global__ void k_cls1(const float* __restrict__ h, const float* __restrict__ Wc,
                       float* __restrict__ part) {
    __shared__ float red[256];
    const int bb = blockIdx.x, p = blockIdx.y, t = threadIdx.x;
    const float* hr = h + (size_t)bb * SE;
    float a[CC];
#pragma unroll
    for (int c = 0; c < CC; c++) a[c] = 0.f;
    const int i0 = p * CLS_CHUNK;
    for (int i = i0 + t; i < i0 + CLS_CHUNK; i += 256) {
        const float hv = hr[i];
        const float* w = Wc + (size_t)i * CC;
#pragma unroll
        for (int c = 0; c < CC; c++) a[c] = fmaf(hv, w[c], a[c]);
    }
#pragma unroll
    for (int c = 0; c < CC; c++) {
        red[t] = a[c]; __syncthreads();
        for (int k = 128; k > 0; k >>= 1) {
            if (t < k) red[t] += red[t + k];
            __syncthreads();
        }
        if (t == 0) part[((size_t)bb * CLS_P + p) * CC + c] = red[0];
        __syncthreads();
    }
}
__global__ void k_cls2(const float* __restrict__ part, const float* __restrict__ bc,
                       float* __restrict__ out) {
    const int t = threadIdx.x;
    if (t < B * CC) {
        const int bb = t / CC, c = t % CC;
        float s = bc[c];
        for (int p = 0; p < CLS_P; p++) s += part[((size_t)bb * CLS_P + p) * CC + c];
        out[t] = s;
    }
}

// ---------------- host ----------------
extern "C" void kernel_launch(void* const* d_in, const int* in_sizes, int n_in,
                              void* d_out, int out_size) {
    const int*   x    = (const int*)  d_in[0];
    const float* emb  = (const float*)d_in[1];
    const float* Wq   = (const float*)d_in[2];
    const float* bq   = (const float*)d_in[3];
    const float* Wk   = (const float*)d_in[4];
    const float* bk   = (const float*)d_in[5];
    const float* Wv   = (const float*)d_in[6];
    const float* bv   = (const float*)d_in[7];
    const float* Wo   = (const float*)d_in[8];
    const float* bo   = (const float*)d_in[9];
    const float* ln1g = (const float*)d_in[10];
    const float* ln1b = (const float*)d_in[11];
    const float* W1   = (const float*)d_in[12];
    const float* b1   = (const float*)d_in[13];
    const float* W2   = (const float*)d_in[14];
    const float* b2   = (const float*)d_in[15];
    const float* ln2g = (const float*)d_in[16];
    const float* ln2b = (const float*)d_in[17];
    const float* Wc   = (const float*)d_in[18];
    const float* bc   = (const float*)d_in[19];
    float* out = (float*)d_out;

    float *h, *t, *bqkv;
    __nv_bfloat16 *hh, *hl, *qkv, *vt, *ch, *cl, *fh, *fl, *sc, *wh, *wl;
    cudaGetSymbolAddress((void**)&h,   g_h);
    cudaGetSymbolAddress((void**)&t,   g_t);
    cudaGetSymbolAddress((void**)&hh,  g_hh); cudaGetSymbolAddress((void**)&hl, g_hl);
    cudaGetSymbolAddress((void**)&qkv, g_qkv);
    cudaGetSymbolAddress((void**)&vt,  g_vt);
    cudaGetSymbolAddress((void**)&ch,  g_ch); cudaGetSymbolAddress((void**)&cl, g_cl);
    cudaGetSymbolAddress((void**)&fh,  g_fh); cudaGetSymbolAddress((void**)&fl, g_fl);
    cudaGetSymbolAddress((void**)&sc,  g_sc);
    cudaGetSymbolAddress((void**)&wh,  g_wh); cudaGetSymbolAddress((void**)&wl, g_wl);
    cudaGetSymbolAddress((void**)&bqkv, g_bqkv);

    constexpr int SMEM_D  = 2 * 2 * (128 * 80 + 128 * 80);   // DUAL BN=128: 81920
    constexpr int SMEM_S  = 2 * (128 * 80 + 128 * 80);       // NC1 BN=128: 40960
    constexpr int SMEM_C  = 2 * (128 * 80 + 64 * 80);        // NC1 BN=64:  30720
    cudaFuncSetAttribute(k_mma<128, true>,  cudaFuncAttributeMaxDynamicSharedMemorySize, SMEM_D);
    cudaFuncSetAttribute(k_mma<128, false>, cudaFuncAttributeMaxDynamicSharedMemorySize, SMEM_S);
    cudaFuncSetAttribute(k_mma<64, false>,  cudaFuncAttributeMaxDynamicSharedMemorySize, SMEM_C);

    __nv_bfloat16 *qh = qkv, *kh = qkv + (size_t)M4 * E, *vh = qkv + (size_t)2 * M4 * E;

    // ---- weight conversion (transpose + bf16 hi/lo split) + bias packing ----
    for (int l = 0; l < L; l++) {
        const size_t wb = (size_t)l * LW;
        k_wt<<<dim3(E / 32,  E / 32),  256>>>(Wq + (size_t)l * E * E,  wh + wb + OFF_Q, wl + wb + OFF_Q, E, E);
        k_wt<<<dim3(E / 32,  E / 32),  256>>>(Wk + (size_t)l * E * E,  wh + wb + OFF_K, wl + wb + OFF_K, E, E);
        k_wt<<<dim3(E / 32,  E / 32),  256>>>(Wv + (size_t)l * E * E,  wh + wb + OFF_V, wl + wb + OFF_V, E, E);
        k_wt<<<dim3(E / 32,  E / 32),  256>>>(Wo + (size_t)l * E * E,  wh + wb + OFF_O, wl + wb + OFF_O, E, E);
        k_wt<<<dim3(FF / 32, E / 32),  256>>>(W1 + (size_t)l * E * FF, wh + wb + OFF_1, wl + wb + OFF_1, E, FF);
        k_wt<<<dim3(E / 32,  FF / 32), 256>>>(W2 + (size_t)l * FF * E, wh + wb + OFF_2, wl + wb + OFF_2, FF, E);
        k_pack3<<<3, 256>>>(bq + (size_t)l * E, bk + (size_t)l * E, bv + (size_t)l * E,
                            bqkv + (size_t)l * 3 * E);
    }

    // ---- embedding ----
    k_embed<<<M4, 256>>>(x, emb, h, hh, hl);

    const dim3 gQKV(6, 32, 3);
    const dim3 gEE(6, 32);
    const dim3 gF1(24, 32);
    const dim3 gSc(4, 4, NHEAD);
    const dim3 gCx(1, 4, NHEAD);

    for (int l = 0; l < L; l++) {
        const size_t wb = (size_t)l * LW;

        // fused QKV (z over 3 weight sets; weights/biases/outputs contiguous)
        k_mma<128, true><<<gQKV, 256, SMEM_D>>>(hh, hl, wh + wb + OFF_Q, wl + wb + OFF_Q,
            bqkv + (size_t)l * 3 * E, nullptr, nullptr, qkv, nullptr,
            E, E, 0, (size_t)E * E, (size_t)M4 * E, E, 1.f, 0);
        k_vt<<<dim3(8, NHEAD), 256>>>(vh, vt);

        // scores = Q K^T / 8, softmax, ctx = P V
        k_mma<128, false><<<gSc, 256, SMEM_S>>>(qh, nullptr, kh, nullptr,
            nullptr, nullptr, nullptr, sc, nullptr,
            S, DH, HSZ, HSZ, (size_t)S * S, 0, 0.125f, 0);
        k_softmax<<<NHEAD * S, 256>>>(sc);
        k_mma<64, false><<<gCx, 256, SMEM_C>>>(sc, nullptr, vt, nullptr,
            nullptr, nullptr, nullptr, ch, cl,
            DH, S, (size_t)S * S, HSZ, HSZ, 0, 1.f, 0);

        // Wo + residual -> LN1
        k_mma<128, true><<<gEE, 256, SMEM_D>>>(ch, cl, wh + wb + OFF_O, wl + wb + OFF_O,
            bo + (size_t)l * E, h, t, nullptr, nullptr,
            E, E, 0, 0, 0, 0, 1.f, 0);
        k_ln<<<M4, 256>>>(t, h, hh, hl, ln1g + (size_t)l * E, ln1b + (size_t)l * E);

        // FFN
        k_mma<128, true><<<gF1, 256, SMEM_D>>>(hh, hl, wh + wb + OFF_1, wl + wb + OFF_1,
            b1 + (size_t)l * FF, nullptr, nullptr, fh, fl,
            FF, E, 0, 0, 0, 0, 1.f, 1);
        k_mma<128, true><<<gEE, 256, SMEM_D>>>(fh, fl, wh + wb + OFF_2, wl + wb + OFF_2,
            b2 + (size_t)l * E, h, t, nullptr, nullptr,
            E, FF, 0, 0, 0, 0, 1.f, 0);
        k_ln<<<M4, 256>>>(t, h, hh, hl, ln2g + (size_t)l * E, ln2b + (size_t)l * E);
    }

    // classifier (fp32 exact): partials into g_t, then reduce
    k_cls1<<<dim3(B, CLS_P), 256>>>(h, Wc, t);
    k_cls2<<<1, 128>>>(t, bc, out);
}

// round 4
// speedup vs baseline: 3.2843x; 1.2807x over previous
#include <cuda_runtime.h>
#include <cuda_bf16.h>
#include <cstdint>
#include <math.h>

// ---------------- problem constants ----------------
#define B    8
#define S    512
#define E    768
#define NH   12
#define DH   64
#define FF   3072
#define L    6
#define CC   10
#define M4   (B*S)          // 4096 rows
#define HSZ  (S*DH)         // 32768 per-head elems
#define NHEAD (B*NH)        // 96
#define EPSL 1e-5f
#define SE   (S*E)          // 393216

// per-layer weight block (elems), all in NATIVE [K,N] layout: Wq,Wk,Wv,Wo,W1,W2
#define LW   (4*E*E + 2*E*FF)
#define OFF_Q 0
#define OFF_K (E*E)
#define OFF_V (2*E*E)
#define OFF_O (3*E*E)
#define OFF_1 (4*E*E)
#define OFF_2 (4*E*E + E*FF)

// ---------------- scratch (device globals) ----------------
__device__ float g_h [M4*E];
__device__ float g_t [M4*E];                    // pre-LN buffer; reused as cls partials
__device__ __nv_bfloat16 g_hh[M4*E], g_hl[M4*E];
__device__ __nv_bfloat16 g_qkv[3*M4*E];         // q,k,v contiguous
__device__ __nv_bfloat16 g_ch[M4*E], g_cl[M4*E];
__device__ __nv_bfloat16 g_fh[M4*FF], g_fl[M4*FF];
__device__ __nv_bfloat16 g_sc[(size_t)NHEAD*S*S];
__device__ __nv_bfloat16 g_wh[(size_t)L*LW], g_wl[(size_t)L*LW];
__device__ float g_bqkv[L*3*E];

// ---------------- asm helpers ----------------
__device__ __forceinline__ uint32_t smem_u32(const void* p) {
    uint32_t a;
    asm("{ .reg .u64 t; cvta.to.shared.u64 t, %1; cvt.u32.u64 %0, t; }" : "=r"(a) : "l"(p));
    return a;
}
__device__ __forceinline__ void ldsm4(uint32_t* r, uint32_t a) {
    asm volatile("ldmatrix.sync.aligned.m8n8.x4.shared.b16 {%0,%1,%2,%3}, [%4];"
        : "=r"(r[0]), "=r"(r[1]), "=r"(r[2]), "=r"(r[3]) : "r"(a));
}
__device__ __forceinline__ void ldsm4t(uint32_t* r, uint32_t a) {
    asm volatile("ldmatrix.sync.aligned.m8n8.x4.trans.shared.b16 {%0,%1,%2,%3}, [%4];"
        : "=r"(r[0]), "=r"(r[1]), "=r"(r[2]), "=r"(r[3]) : "r"(a));
}
__device__ __forceinline__ void mma_bf16(float* c, const uint32_t* a, const uint32_t* b) {
    asm volatile("mma.sync.aligned.m16n8k16.row.col.f32.bf16.bf16.f32 "
        "{%0,%1,%2,%3}, {%4,%5,%6,%7}, {%8,%9}, {%0,%1,%2,%3};"
        : "+f"(c[0]), "+f"(c[1]), "+f"(c[2]), "+f"(c[3])
        : "r"(a[0]), "r"(a[1]), "r"(a[2]), "r"(a[3]), "r"(b[0]), "r"(b[1]));
}
#define CPA(dst, src) asm volatile("cp.async.cg.shared.global [%0], [%1], 16;" :: "r"(dst), "l"(src))
#define CPC() asm volatile("cp.async.commit_group;" ::: "memory")
#define CPW(n) asm volatile("cp.async.wait_group %0;" :: "n"(n) : "memory")

// ================= HMMA GEMM =================
// D[row,col] = scale*sum_k A[row,k]*B(col,k) (+bias)(relu)(+res)
// TB=false: B stored [N,K] row-major. TB=true: B stored [K,N] row-major (ldmatrix.trans).
// DUAL: acc += Ah*Bh + Ah*Bl + Al*Bh (bf16 hi/lo split).
// BM=128; BN in {128,64}; BK=32; 256 threads; 2-stage cp.async pipeline; 2 CTAs/SM.
template<int BN, bool DUAL, bool TB>
__global__ void __launch_bounds__(256, 2)
k_mma(const __nv_bfloat16* __restrict__ Ah, const __nv_bfloat16* __restrict__ Al,
      const __nv_bfloat16* __restrict__ Bh, const __nv_bfloat16* __restrict__ Bl,
      const float* __restrict__ bias, const float* __restrict__ res,
      float* __restrict__ Cf, __nv_bfloat16* __restrict__ Chi, __nv_bfloat16* __restrict__ Clo,
      int N, int K, size_t sAz, size_t sBz, size_t sCz, size_t bsz,
      float scale, int relu) {
    extern __shared__ char sm[];
    constexpr int WN  = (BN == 128) ? 4 : 2;
    constexpr int WM  = 8 / WN;
    constexpr int WTM = 128 / WM;
    constexpr int WTN = BN / WN;               // 32
    constexpr int MF  = WTM / 16;
    constexpr int NF  = WTN / 8;               // 4
    constexpr int ATILE  = 128 * 80;           // 128 rows x (32+8) bf16
    constexpr int BPITCH = TB ? (BN + 8) * 2 : 80;
    constexpr int BTILE  = TB ? 32 * BPITCH : BN * 80;
    constexpr int HALF   = ATILE + BTILE;
    constexpr int STAGE  = HALF * (DUAL ? 2 : 1);

    const uint32_t smb = smem_u32(sm);
    const int tid = threadIdx.x, lane = tid & 31, wid = tid >> 5;
    const int wm = wid / WN, wn = wid % WN;
    const int bm = blockIdx.y * 128, bn = blockIdx.x * BN;
    const size_t zA = (size_t)blockIdx.z * sAz, zB = (size_t)blockIdx.z * sBz;
    const __nv_bfloat16* pA  = Ah + zA + (size_t)bm * K;
    const __nv_bfloat16* pAl = DUAL ? Al + zA + (size_t)bm * K : nullptr;
    const __nv_bfloat16* pB  = TB ? Bh + zB : Bh + zB + (size_t)bn * K;
    const __nv_bfloat16* pBl = DUAL ? (TB ? Bl + zB : Bl + zB + (size_t)bn * K) : nullptr;

    float acc[MF][NF][4];
#pragma unroll
    for (int i = 0; i < MF; i++)
#pragma unroll
        for (int j = 0; j < NF; j++)
#pragma unroll
            for (int q = 0; q < 4; q++) acc[i][j][q] = 0.f;

    const uint32_t a_off = (uint32_t)(lane & 15) * 80 + (uint32_t)(lane >> 4) * 16;
    const uint32_t b_off = TB
        ? (uint32_t)(lane & 15) * BPITCH + (uint32_t)(lane >> 4) * 16
        : (uint32_t)((lane & 7) + ((lane >> 1) & 8)) * 80 + (uint32_t)((lane >> 3) & 1) * 16;

    const int KT = K >> 5;

    auto load_stage = [&](int s, int kt) {
        const int k0 = kt << 5;
        const uint32_t base = smb + s * STAGE;
#pragma unroll 2
        for (int cid = tid; cid < 512; cid += 256) {
            const int row = cid >> 2, p = cid & 3;
            const uint32_t d = base + row * 80 + p * 16;
            const size_t go = (size_t)row * K + k0 + p * 8;
            CPA(d, pA + go);
            if (DUAL) CPA(d + HALF, pAl + go);
        }
        if (TB) {
#pragma unroll 2
            for (int cid = tid; cid < 32 * (BN / 8); cid += 256) {
                const int row = cid / (BN / 8), c = cid % (BN / 8);
                const uint32_t d = base + ATILE + row * BPITCH + c * 16;
                const size_t go = (size_t)(k0 + row) * N + bn + c * 8;
                CPA(d, pB + go);
                if (DUAL) CPA(d + HALF, pBl + go);
            }
        } else {
#pragma unroll 2
            for (int cid = tid; cid < BN * 4; cid += 256) {
                const int row = cid >> 2, p = cid & 3;
                const uint32_t d = base + ATILE + row * 80 + p * 16;
                const size_t go = (size_t)row * K + k0 + p * 8;
                CPA(d, pB + go);
                if (DUAL) CPA(d + HALF, pBl + go);
            }
        }
    };

    load_stage(0, 0); CPC();

    for (int kt = 0; kt < KT; ++kt) {
        if (kt + 1 < KT) { load_stage((kt + 1) & 1, kt + 1); CPC(); CPW(1); }
        else CPW(0);
        __syncthreads();

        const uint32_t stageB = smb + (kt & 1) * STAGE;
        const uint32_t aB = stageB + wm * WTM * 80 + a_off;
        const uint32_t bB = TB ? stageB + ATILE + wn * WTN * 2 + b_off
                               : stageB + ATILE + wn * WTN * 80 + b_off;
#pragma unroll
        for (int ks = 0; ks < 2; ++ks) {
            uint32_t aR[MF][4], bR[NF / 2][4], bRl[NF / 2][4];
#pragma unroll
            for (int n2 = 0; n2 < NF / 2; n2++) {
                const uint32_t ad = TB ? bB + ks * 16 * BPITCH + n2 * 32
                                       : bB + n2 * 16 * 80 + ks * 32;
                if (TB) ldsm4t(bR[n2], ad); else ldsm4(bR[n2], ad);
            }
            if (DUAL) {
#pragma unroll
                for (int n2 = 0; n2 < NF / 2; n2++) {
                    const uint32_t ad = TB ? bB + HALF + ks * 16 * BPITCH + n2 * 32
                                           : bB + HALF + n2 * 16 * 80 + ks * 32;
                    if (TB) ldsm4t(bRl[n2], ad); else ldsm4(bRl[n2], ad);
                }
            }
#pragma unroll
            for (int mi = 0; mi < MF; mi++)
                ldsm4(aR[mi], aB + mi * 16 * 80 + ks * 32);

#pragma unroll
            for (int mi = 0; mi < MF; mi++)
#pragma unroll
                for (int n2 = 0; n2 < NF / 2; n2++) {
                    mma_bf16(acc[mi][n2 * 2],     aR[mi], &bR[n2][0]);
                    mma_bf16(acc[mi][n2 * 2 + 1], aR[mi], &bR[n2][2]);
                }
            if (DUAL) {
#pragma unroll
                for (int mi = 0; mi < MF; mi++)
#pragma unroll
                    for (int n2 = 0; n2 < NF / 2; n2++) {
                        mma_bf16(acc[mi][n2 * 2],     aR[mi], &bRl[n2][0]);
                        mma_bf16(acc[mi][n2 * 2 + 1], aR[mi], &bRl[n2][2]);
                    }
#pragma unroll
                for (int mi = 0; mi < MF; mi++)
                    ldsm4(aR[mi], aB + HALF + mi * 16 * 80 + ks * 32);
#pragma unroll
                for (int mi = 0; mi < MF; mi++)
#pragma unroll
                    for (int n2 = 0; n2 < NF / 2; n2++) {
                        mma_bf16(acc[mi][n2 * 2],     aR[mi], &bR[n2][0]);
                        mma_bf16(acc[mi][n2 * 2 + 1], aR[mi], &bR[n2][2]);
                    }
            }
        }
        __syncthreads();
    }

    // ---- epilogue ----
    const size_t cz = (size_t)blockIdx.z * sCz;
    const float* bz = bias ? bias + (size_t)blockIdx.z * bsz : nullptr;
    const int r0 = bm + wm * WTM + (lane >> 2);
    const int c0 = bn + wn * WTN + (lane & 3) * 2;

#pragma unroll
    for (int mi = 0; mi < MF; mi++) {
#pragma unroll
        for (int ni = 0; ni < NF; ni++) {
            const int col = c0 + ni * 8;
#pragma unroll
            for (int half = 0; half < 2; half++) {
                const int row = r0 + mi * 16 + half * 8;
                float v0 = acc[mi][ni][half * 2]     * scale;
                float v1 = acc[mi][ni][half * 2 + 1] * scale;
                if (bz) { v0 += bz[col]; v1 += bz[col + 1]; }
                if (relu) { v0 = fmaxf(v0, 0.f); v1 = fmaxf(v1, 0.f); }
                if (res) {
                    const float2 rv = *(const float2*)&res[(size_t)row * N + col];
                    v0 += rv.x; v1 += rv.y;
                }
                const size_t o = cz + (size_t)row * N + col;
                if (Cf) { float2 f = {v0, v1}; *(float2*)&Cf[o] = f; }
                if (Chi) {
                    const __nv_bfloat16 h0 = __float2bfloat16(v0);
                    const __nv_bfloat16 h1 = __float2bfloat16(v1);
                    __nv_bfloat162 hv; hv.x = h0; hv.y = h1;
                    *(__nv_bfloat162*)&Chi[o] = hv;
                    if (Clo) {
                        __nv_bfloat162 lv;
                        lv.x = __float2bfloat16(v0 - __bfloat162float(h0));
                        lv.y = __float2bfloat16(v1 - __bfloat162float(h1));
                        *(__nv_bfloat162*)&Clo[o] = lv;
                    }
                }
            }
        }
    }
}

// ---------------- elementwise weight hi/lo split (native layout) ----------------
__global__ void k_split(const float* __restrict__ W, __nv_bfloat16* __restrict__ Th,
                        __nv_bfloat16* __restrict__ Tl, size_t n, size_t lsrc, size_t ldst) {
    const size_t l = blockIdx.y;
    const size_t i = ((size_t)blockIdx.x * 256 + threadIdx.x) * 4;
    if (i >= n) return;
    const float4 v = *(const float4*)(W + l * lsrc + i);
    __nv_bfloat16 h0 = __float2bfloat16(v.x), h1 = __float2bfloat16(v.y);
    __nv_bfloat16 h2 = __float2bfloat16(v.z), h3 = __float2bfloat16(v.w);
    __nv_bfloat162 a0; a0.x = h0; a0.y = h1;
    __nv_bfloat162 a1; a1.x = h2; a1.y = h3;
    __nv_bfloat162 l0, l1;
    l0.x = __float2bfloat16(v.x - __bfloat162float(h0));
    l0.y = __float2bfloat16(v.y - __bfloat162float(h1));
    l1.x = __float2bfloat16(v.z - __bfloat162float(h2));
    l1.y = __float2bfloat16(v.w - __bfloat162float(h3));
    const size_t o = l * ldst + i;
    *(__nv_bfloat162*)(Th + o)     = a0;
    *(__nv_bfloat162*)(Th + o + 2) = a1;
    *(__nv_bfloat162*)(Tl + o)     = l0;
    *(__nv_bfloat162*)(Tl + o + 2) = l1;
}

// ---------------- pack qkv biases contiguously (per layer) ----------------
__global__ void k_pack3(const float* __restrict__ a, const float* __restrict__ b,
                        const float* __restrict__ c, float* __restrict__ o) {
    const int l = blockIdx.y;
    const int i = blockIdx.x * 256 + threadIdx.x;
    if (i < E) {
        float* ol = o + (size_t)l * 3 * E;
        ol[i] = a[(size_t)l * E + i];
        ol[E + i] = b[(size_t)l * E + i];
        ol[2 * E + i] = c[(size_t)l * E + i];
    }
}

// ---------------- embedding gather + hi/lo ----------------
__global__ void k_embed(const int* __restrict__ x, const float* __restrict__ emb,
                        float* __restrict__ h, __nv_bfloat16* __restrict__ hh,
                        __nv_bfloat16* __restrict__ hl) {
    const int row = blockIdx.x;
    const int tok = x[row];
    for (int i = threadIdx.x; i < E; i += 256) {
        const float v = emb[(size_t)tok * E + i];
        const size_t o = (size_t)row * E + i;
        h[o] = v;
        const __nv_bfloat16 hi = __float2bfloat16(v);
        hh[o] = hi;
        hl[o] = __float2bfloat16(v - __bfloat162float(hi));
    }
}

// ---------------- softmax: one warp per row of 512 ----------------
__global__ void k_softmax(__nv_bfloat16* __restrict__ sc) {
    const int row = blockIdx.x * 8 + (threadIdx.x >> 5);
    const int lane = threadIdx.x & 31;
    uint4* p = (uint4*)(sc + (size_t)row * S);   // 64 uint4 per row
    uint4 u[2];
    u[0] = p[lane * 2];
    u[1] = p[lane * 2 + 1];

    float f[16];
#pragma unroll
    for (int j = 0; j < 2; j++) {
        const uint32_t* w = (const uint32_t*)&u[j];
#pragma unroll
        for (int q = 0; q < 4; q++) {
            const __nv_bfloat162 h2 = *(const __nv_bfloat162*)&w[q];
            const float2 fv = __bfloat1622float2(h2);
            f[j * 8 + q * 2] = fv.x; f[j * 8 + q * 2 + 1] = fv.y;
        }
    }
    float m = f[0];
#pragma unroll
    for (int i = 1; i < 16; i++) m = fmaxf(m, f[i]);
#pragma unroll
    for (int off = 16; off; off >>= 1) m = fmaxf(m, __shfl_xor_sync(~0u, m, off));
    float s = 0.f;
#pragma unroll
    for (int i = 0; i < 16; i++) { f[i] = expf(f[i] - m); s += f[i]; }
#pragma unroll
    for (int off = 16; off; off >>= 1) s += __shfl_xor_sync(~0u, s, off);
    const float inv = 1.0f / s;
#pragma unroll
    for (int j = 0; j < 2; j++) {
        uint32_t* w = (uint32_t*)&u[j];
#pragma unroll
        for (int q = 0; q < 4; q++) {
            float2 fv; fv.x = f[j * 8 + q * 2] * inv; fv.y = f[j * 8 + q * 2 + 1] * inv;
            const __nv_bfloat162 h2 = __float22bfloat162_rn(fv);
            w[q] = *(const uint32_t*)&h2;
        }
    }
    p[lane * 2]     = u[0];
    p[lane * 2 + 1] = u[1];
}

// ---------------- layernorm (fp32 in; fp32 + bf16 hi/lo out) ----------------
__global__ void k_ln(const float* __restrict__ in, float* __restrict__ out,
                     __nv_bfloat16* __restrict__ oh, __nv_bfloat16* __restrict__ ol,
                     const float* __restrict__ g, const float* __restrict__ b) {
    __shared__ float s1[8], s2[8];
    const int row = blockIdx.x, t = threadIdx.x;
    const int lane = t & 31, w = t >> 5;
    const float* p = in + (size_t)row * E;

    const float x0 = p[t], x1 = p[t + 256], x2 = p[t + 512];
    float a = x0 + x1 + x2;
    float q = x0 * x0 + x1 * x1 + x2 * x2;
#pragma unroll
    for (int off = 16; off; off >>= 1) {
        a += __shfl_xor_sync(~0u, a, off);
        q += __shfl_xor_sync(~0u, q, off);
    }
    if (lane == 0) { s1[w] = a; s2[w] = q; }
    __syncthreads();
    float ta = 0.f, tq = 0.f;
#pragma unroll
    for (int i = 0; i < 8; i++) { ta += s1[i]; tq += s2[i]; }
    const float mean = ta * (1.0f / E);
    const float var  = tq * (1.0f / E) - mean * mean;
    const float inv  = rsqrtf(var + EPSL);

    const size_t base = (size_t)row * E;
#pragma unroll
    for (int k = 0; k < 3; k++) {
        const int idx = t + k * 256;
        const float xv = (k == 0) ? x0 : (k == 1) ? x1 : x2;
        const float v = (xv - mean) * inv * g[idx] + b[idx];
        out[base + idx] = v;
        const __nv_bfloat16 hi = __float2bfloat16(v);
        oh[base + idx] = hi;
        ol[base + idx] = __float2bfloat16(v - __bfloat162float(hi));
    }
}

// ---------------- classifier: partials then reduce ----------------
#define CLS_P 16
#define CLS_CHUNK (SE / CLS_P)
__global__ void k_cls1(const float* __restrict__ h, const float* __restrict__ Wc,
                       float* __restrict__ part) {
    __shared__ float red[256];
    const int bb = blockIdx.x, p = blockIdx.y, t = threadIdx.x;
    const float* hr = h + (size_t)bb * SE;
    float a[CC];
#pragma unroll
    for (int c = 0; c < CC; c++) a[c] = 0.f;
    const int i0 = p * CLS_CHUNK;
    for (int i = i0 + t; i < i0 + CLS_CHUNK; i += 256) {
        const float hv = hr[i];
        const float* w = Wc + (size_t)i * CC;
#pragma unroll
        for (int c = 0; c < CC; c++) a[c] = fmaf(hv, w[c], a[c]);
    }
#pragma unroll
    for (int c = 0; c < CC; c++) {
        red[t] = a[c]; __syncthreads();
        for (int k = 128; k > 0; k >>= 1) {
            if (t < k) red[t] += red[t + k];
            __syncthreads();
        }
        if (t == 0) part[((size_t)bb * CLS_P + p) * CC + c] = red[0];
        __syncthreads();
    }
}
__global__ void k_cls2(const float* __restrict__ part, const float* __restrict__ bc,
                       float* __restrict__ out) {
    const int t = threadIdx.x;
    if (t < B * CC) {
        const int bb = t / CC, c = t % CC;
        float s = bc[c];
        for (int p = 0; p < CLS_P; p++) s += part[((size_t)bb * CLS_P + p) * CC + c];
        out[t] = s;
    }
}

// ---------------- host ----------------
extern "C" void kernel_launch(void* const* d_in, const int* in_sizes, int n_in,
                              void* d_out, int out_size) {
    const int*   x    = (const int*)  d_in[0];
    const float* emb  = (const float*)d_in[1];
    const float* Wq   = (const float*)d_in[2];
    const float* bq   = (const float*)d_in[3];
    const float* Wk   = (const float*)d_in[4];
    const float* bk   = (const float*)d_in[5];
    const float* Wv   = (const float*)d_in[6];
    const float* bv   = (const float*)d_in[7];
    const float* Wo   = (const float*)d_in[8];
    const float* bo   = (const float*)d_in[9];
    const float* ln1g = (const float*)d_in[10];
    const float* ln1b = (const float*)d_in[11];
    const float* W1   = (const float*)d_in[12];
    const float* b1   = (const float*)d_in[13];
    const float* W2   = (const float*)d_in[14];
    const float* b2   = (const float*)d_in[15];
    const float* ln2g = (const float*)d_in[16];
    const float* ln2b = (const float*)d_in[17];
    const float* Wc   = (const float*)d_in[18];
    const float* bc   = (const float*)d_in[19];
    float* out = (float*)d_out;

    float *h, *t, *bqkv;
    __nv_bfloat16 *hh, *hl, *qkv, *ch, *cl, *fh, *fl, *sc, *wh, *wl;
    cudaGetSymbolAddress((void**)&h,   g_h);
    cudaGetSymbolAddress((void**)&t,   g_t);
    cudaGetSymbolAddress((void**)&hh,  g_hh); cudaGetSymbolAddress((void**)&hl, g_hl);
    cudaGetSymbolAddress((void**)&qkv, g_qkv);
    cudaGetSymbolAddress((void**)&ch,  g_ch); cudaGetSymbolAddress((void**)&cl, g_cl);
    cudaGetSymbolAddress((void**)&fh,  g_fh); cudaGetSymbolAddress((void**)&fl, g_fl);
    cudaGetSymbolAddress((void**)&sc,  g_sc);
    cudaGetSymbolAddress((void**)&wh,  g_wh); cudaGetSymbolAddress((void**)&wl, g_wl);
    cudaGetSymbolAddress((void**)&bqkv, g_bqkv);

    // smem sizes: A tile 128*80; B tile TB: 32*(BN+8)*2, non-TB: BN*80
    constexpr int SMEM_D = 2 * 2 * (128 * 80 + 32 * (128 + 8) * 2); // DUAL TB BN=128: 75776
    constexpr int SMEM_S = 2 * (128 * 80 + 128 * 80);               // scores: 40960
    constexpr int SMEM_C = 2 * (128 * 80 + 32 * (64 + 8) * 2);      // ctx TB BN=64: 29696
    cudaFuncSetAttribute(k_mma<128, true,  true>,  cudaFuncAttributeMaxDynamicSharedMemorySize, SMEM_D);
    cudaFuncSetAttribute(k_mma<128, false, false>, cudaFuncAttributeMaxDynamicSharedMemorySize, SMEM_S);
    cudaFuncSetAttribute(k_mma<64,  false, true>,  cudaFuncAttributeMaxDynamicSharedMemorySize, SMEM_C);

    __nv_bfloat16 *qh = qkv, *kh = qkv + (size_t)M4 * E, *vh = qkv + (size_t)2 * M4 * E;

    // ---- weight hi/lo split (native [K,N] layout, pure elementwise) ----
    k_split<<<dim3(E * E / 1024,  L), 256>>>(Wq, wh + OFF_Q, wl + OFF_Q, (size_t)E * E,  (size_t)E * E,  LW);
    k_split<<<dim3(E * E / 1024,  L), 256>>>(Wk, wh + OFF_K, wl + OFF_K, (size_t)E * E,  (size_t)E * E,  LW);
    k_split<<<dim3(E * E / 1024,  L), 256>>>(Wv, wh + OFF_V, wl + OFF_V, (size_t)E * E,  (size_t)E * E,  LW);
    k_split<<<dim3(E * E / 1024,  L), 256>>>(Wo, wh + OFF_O, wl + OFF_O, (size_t)E * E,  (size_t)E * E,  LW);
    k_split<<<dim3(E * FF / 1024, L), 256>>>(W1, wh + OFF_1, wl + OFF_1, (size_t)E * FF, (size_t)E * FF, LW);
    k_split<<<dim3(E * FF / 1024, L), 256>>>(W2, wh + OFF_2, wl + OFF_2, (size_t)E * FF, (size_t)E * FF, LW);
    k_pack3<<<dim3(3, L), 256>>>(bq, bk, bv, bqkv);

    // ---- embedding ----
    k_embed<<<M4, 256>>>(x, emb, h, hh, hl);

    const dim3 gQKV(6, 32, 3);
    const dim3 gEE(6, 32);
    const dim3 gF1(24, 32);
    const dim3 gSc(4, 4, NHEAD);
    const dim3 gCx(1, 4, NHEAD);

    for (int l = 0; l < L; l++) {
        const size_t wb = (size_t)l * LW;

        // fused QKV
        k_mma<128, true, true><<<gQKV, 256, SMEM_D>>>(hh, hl, wh + wb + OFF_Q, wl + wb + OFF_Q,
            bqkv + (size_t)l * 3 * E, nullptr, nullptr, qkv, nullptr,
            E, E, 0, (size_t)E * E, (size_t)M4 * E, E, 1.f, 0);

        // scores = Q K^T / 8, softmax, ctx = P V (V consumed directly, TB)
        k_mma<128, false, false><<<gSc, 256, SMEM_S>>>(qh, nullptr, kh, nullptr,
            nullptr, nullptr, nullptr, sc, nullptr,
            S, DH, HSZ, HSZ, (size_t)S * S, 0, 0.125f, 0);
        k_softmax<<<NHEAD * S / 8, 256>>>(sc);
        k_mma<64, false, true><<<gCx, 256, SMEM_C>>>(sc, nullptr, vh, nullptr,
            nullptr, nullptr, nullptr, ch, cl,
            DH, S, (size_t)S * S, HSZ, HSZ, 0, 1.f, 0);

        // Wo + residual -> LN1
        k_mma<128, true, true><<<gEE, 256, SMEM_D>>>(ch, cl, wh + wb + OFF_O, wl + wb + OFF_O,
            bo + (size_t)l * E, h, t, nullptr, nullptr,
            E, E, 0, 0, 0, 0, 1.f, 0);
        k_ln<<<M4, 256>>>(t, h, hh, hl, ln1g + (size_t)l * E, ln1b + (size_t)l * E);

        // FFN
        k_mma<128, true, true><<<gF1, 256, SMEM_D>>>(hh, hl, wh + wb + OFF_1, wl + wb + OFF_1,
            b1 + (size_t)l * FF, nullptr, nullptr, fh, fl,
            FF, E, 0, 0, 0, 0, 1.f, 1);
        k_mma<128, true, true><<<gEE, 256, SMEM_D>>>(fh, fl, wh + wb + OFF_2, wl + wb + OFF_2,
            b2 + (size_t)l * E, h, t, nullptr, nullptr,
            E, FF, 0, 0, 0, 0, 1.f, 0);
        k_ln<<<M4, 256>>>(t, h, hh, hl, ln2g + (size_t)l * E, ln2b + (size_t)l * E);
    }

    // classifier (fp32 exact)
    k_cls1<<<dim3(B, CLS_P), 256>>>(h, Wc, t);
    k_cls2<<<1, 128>>>(t, bc, out);
}

// round 6
// speedup vs baseline: 4.2983x; 1.3087x over previous
#include <cuda_runtime.h>
#include <cuda_fp16.h>
#include <cstdint>
#include <math.h>

// ---------------- problem constants ----------------
#define B    8
#define S    512
#define E    768
#define NH   12
#define DH   64
#define FF   3072
#define L    6
#define CC   10
#define M4   (B*S)          // 4096 rows
#define HSZ  (S*DH)         // 32768 per-head elems
#define NHEAD (B*NH)        // 96
#define EPSL 1e-5f
#define SE   (S*E)

// per-layer weight block (elems), native [K,N] layout: Wq,Wk,Wv,Wo,W1,W2
#define EE   (E*E)
#define EF   (E*FF)
#define LW   (4*EE + 2*EF)
#define OFF_Q 0
#define OFF_K EE
#define OFF_V (2*EE)
#define OFF_O (3*EE)
#define OFF_1 (4*EE)
#define OFF_2 (4*EE + EF)

// ---------------- scratch (device globals) ----------------
__device__ float g_h [M4*E];
__device__ float g_t [M4*E];                    // pre-LN buffer; cls partials; filler target
__device__ __half g_hh[M4*E];
__device__ __half g_qkv[3*M4*E];
__device__ __half g_ch[M4*E];
__device__ __half g_fh[M4*FF];
__device__ __half g_sc[(size_t)NHEAD*S*S];
__device__ __half g_wh[(size_t)L*LW], g_wl[(size_t)L*LW];
__device__ float g_bqkv[L*3*E];

// ---------------- asm helpers ----------------
__device__ __forceinline__ uint32_t smem_u32(const void* p) {
    uint32_t a;
    asm("{ .reg .u64 t; cvta.to.shared.u64 t, %1; cvt.u32.u64 %0, t; }" : "=r"(a) : "l"(p));
    return a;
}
__device__ __forceinline__ void ldsm4(uint32_t* r, uint32_t a) {
    asm volatile("ldmatrix.sync.aligned.m8n8.x4.shared.b16 {%0,%1,%2,%3}, [%4];"
        : "=r"(r[0]), "=r"(r[1]), "=r"(r[2]), "=r"(r[3]) : "r"(a));
}
__device__ __forceinline__ void ldsm4t(uint32_t* r, uint32_t a) {
    asm volatile("ldmatrix.sync.aligned.m8n8.x4.trans.shared.b16 {%0,%1,%2,%3}, [%4];"
        : "=r"(r[0]), "=r"(r[1]), "=r"(r[2]), "=r"(r[3]) : "r"(a));
}
__device__ __forceinline__ void mma_f16(float* c, const uint32_t* a, const uint32_t* b) {
    asm volatile("mma.sync.aligned.m16n8k16.row.col.f32.f16.f16.f32 "
        "{%0,%1,%2,%3}, {%4,%5,%6,%7}, {%8,%9}, {%0,%1,%2,%3};"
        : "+f"(c[0]), "+f"(c[1]), "+f"(c[2]), "+f"(c[3])
        : "r"(a[0]), "r"(a[1]), "r"(a[2]), "r"(a[3]), "r"(b[0]), "r"(b[1]));
}
#define CPA(dst, src) asm volatile("cp.async.cg.shared.global [%0], [%1], 16;" :: "r"(dst), "l"(src))
#define CPC() asm volatile("cp.async.commit_group;" ::: "memory")
#define CPW(n) asm volatile("cp.async.wait_group %0;" :: "n"(n) : "memory")

// ================= HMMA GEMM (fp16 in, fp32 accum) =================
// D[row,col] = scale*sum_k A[row,k]*B(col,k) (+bias)(relu)(+res)
// A: fp16 [M,K] single. B: DUAL -> hi+lo pair (weights), acc = A*Bh + A*Bl.
// TB=false: B stored [N,K]. TB=true: B stored [K,N] (ldmatrix.trans).
// BM=128; BN in {128,64}; BK=32; 256 threads; 3-stage cp.async; 2 CTAs/SM.
template<int BN, bool DUAL, bool TB>
__global__ void __launch_bounds__(256, 2)
k_mma(const __half* __restrict__ Ah,
      const __half* __restrict__ Bh, const __half* __restrict__ Bl,
      const float* __restrict__ bias, const float* __restrict__ res,
      float* __restrict__ Cf, __half* __restrict__ Chi,
      int N, int K, size_t sAz, size_t sBz, size_t sCz, size_t bsz,
      float scale, int relu) {
    extern __shared__ char sm[];
    constexpr int WN  = (BN == 128) ? 4 : 2;
    constexpr int WM  = 8 / WN;
    constexpr int WTM = 128 / WM;
    constexpr int WTN = BN / WN;               // 32
    constexpr int MF  = WTM / 16;
    constexpr int NF  = WTN / 8;               // 4
    constexpr int ATILE  = 128 * 80;
    constexpr int BPITCH = TB ? (BN + 8) * 2 : 80;
    constexpr int BTILE  = TB ? 32 * BPITCH : BN * 80;
    constexpr int STAGE  = ATILE + BTILE * (DUAL ? 2 : 1);

    const uint32_t smb = smem_u32(sm);
    const int tid = threadIdx.x, lane = tid & 31, wid = tid >> 5;
    const int wm = wid / WN, wn = wid % WN;
    const int bm = blockIdx.y * 128, bn = blockIdx.x * BN;
    const size_t zA = (size_t)blockIdx.z * sAz, zB = (size_t)blockIdx.z * sBz;
    const __half* pA  = Ah + zA + (size_t)bm * K;
    const __half* pB  = TB ? Bh + zB : Bh + zB + (size_t)bn * K;
    const __half* pBl = DUAL ? (TB ? Bl + zB : Bl + zB + (size_t)bn * K) : nullptr;

    float acc[MF][NF][4];
#pragma unroll
    for (int i = 0; i < MF; i++)
#pragma unroll
        for (int j = 0; j < NF; j++)
#pragma unroll
            for (int q = 0; q < 4; q++) acc[i][j][q] = 0.f;

    const uint32_t a_off = (uint32_t)(lane & 15) * 80 + (uint32_t)(lane >> 4) * 16;
    const uint32_t b_off = TB
        ? (uint32_t)(lane & 15) * BPITCH + (uint32_t)(lane >> 4) * 16
        : (uint32_t)((lane & 7) + ((lane >> 1) & 8)) * 80 + (uint32_t)((lane >> 3) & 1) * 16;

    const int KT = K >> 5;

    auto load_stage = [&](int s, int kt) {
        const int k0 = kt << 5;
        const uint32_t base = smb + s * STAGE;
#pragma unroll 2
        for (int cid = tid; cid < 512; cid += 256) {
            const int row = cid >> 2, p = cid & 3;
            CPA(base + row * 80 + p * 16, pA + (size_t)row * K + k0 + p * 8);
        }
        if (TB) {
#pragma unroll 2
            for (int cid = tid; cid < 32 * (BN / 8); cid += 256) {
                const int row = cid / (BN / 8), c = cid % (BN / 8);
                const uint32_t d = base + ATILE + row * BPITCH + c * 16;
                const size_t go = (size_t)(k0 + row) * N + bn + c * 8;
                CPA(d, pB + go);
                if (DUAL) CPA(d + BTILE, pBl + go);
            }
        } else {
#pragma unroll 2
            for (int cid = tid; cid < BN * 4; cid += 256) {
                const int row = cid >> 2, p = cid & 3;
                const uint32_t d = base + ATILE + row * 80 + p * 16;
                const size_t go = (size_t)row * K + k0 + p * 8;
                CPA(d, pB + go);
                if (DUAL) CPA(d + BTILE, pBl + go);
            }
        }
    };

    load_stage(0, 0); CPC();
    if (KT > 1) { load_stage(1, 1); CPC(); }

    int stg = 0;
    for (int kt = 0; kt < KT; ++kt) {
        if (kt + 2 < KT) { load_stage((stg + 2) % 3, kt + 2); CPC(); CPW(2); }
        else if (kt + 1 < KT) CPW(1);
        else CPW(0);
        __syncthreads();

        const uint32_t stageB = smb + stg * STAGE;
        const uint32_t aB = stageB + wm * WTM * 80 + a_off;
        const uint32_t bB = TB ? stageB + ATILE + wn * WTN * 2 + b_off
                               : stageB + ATILE + wn * WTN * 80 + b_off;
#pragma unroll
        for (int ks = 0; ks < 2; ++ks) {
            uint32_t aR[MF][4], bR[NF / 2][4], bRl[NF / 2][4];
#pragma unroll
            for (int n2 = 0; n2 < NF / 2; n2++) {
                const uint32_t ad = TB ? bB + ks * 16 * BPITCH + n2 * 32
                                       : bB + n2 * 16 * 80 + ks * 32;
                if (TB) ldsm4t(bR[n2], ad); else ldsm4(bR[n2], ad);
            }
            if (DUAL) {
#pragma unroll
                for (int n2 = 0; n2 < NF / 2; n2++) {
                    const uint32_t ad = TB ? bB + BTILE + ks * 16 * BPITCH + n2 * 32
                                           : bB + BTILE + n2 * 16 * 80 + ks * 32;
                    if (TB) ldsm4t(bRl[n2], ad); else ldsm4(bRl[n2], ad);
                }
            }
#pragma unroll
            for (int mi = 0; mi < MF; mi++)
                ldsm4(aR[mi], aB + mi * 16 * 80 + ks * 32);

#pragma unroll
            for (int mi = 0; mi < MF; mi++)
#pragma unroll
                for (int n2 = 0; n2 < NF / 2; n2++) {
                    mma_f16(acc[mi][n2 * 2],     aR[mi], &bR[n2][0]);
                    mma_f16(acc[mi][n2 * 2 + 1], aR[mi], &bR[n2][2]);
                }
            if (DUAL) {
#pragma unroll
                for (int mi = 0; mi < MF; mi++)
#pragma unroll
                    for (int n2 = 0; n2 < NF / 2; n2++) {
                        mma_f16(acc[mi][n2 * 2],     aR[mi], &bRl[n2][0]);
                        mma_f16(acc[mi][n2 * 2 + 1], aR[mi], &bRl[n2][2]);
                    }
            }
        }
        __syncthreads();
        stg = (stg + 1) % 3;
    }

    // ---- epilogue ----
    const size_t cz = (size_t)blockIdx.z * sCz;
    const float* bz = bias ? bias + (size_t)blockIdx.z * bsz : nullptr;
    const int r0 = bm + wm * WTM + (lane >> 2);
    const int c0 = bn + wn * WTN + (lane & 3) * 2;

#pragma unroll
    for (int mi = 0; mi < MF; mi++) {
#pragma unroll
        for (int ni = 0; ni < NF; ni++) {
            const int col = c0 + ni * 8;
#pragma unroll
            for (int half = 0; half < 2; half++) {
                const int row = r0 + mi * 16 + half * 8;
                float v0 = acc[mi][ni][half * 2]     * scale;
                float v1 = acc[mi][ni][half * 2 + 1] * scale;
                if (bz) { v0 += bz[col]; v1 += bz[col + 1]; }
                if (relu) { v0 = fmaxf(v0, 0.f); v1 = fmaxf(v1, 0.f); }
                if (res) {
                    const float2 rv = *(const float2*)&res[(size_t)row * N + col];
                    v0 += rv.x; v1 += rv.y;
                }
                const size_t o = cz + (size_t)row * N + col;
                if (Cf) { float2 f = {v0, v1}; *(float2*)&Cf[o] = f; }
                if (Chi) {
                    float2 fv; fv.x = v0; fv.y = v1;
                    *(__half2*)&Chi[o] = __float22half2_rn(fv);
                }
            }
        }
    }
}

// ---------------- fused weight hi/lo split (all 6 matrices, native layout) ----
__global__ void k_prep(const float* __restrict__ Wq, const float* __restrict__ Wk,
                       const float* __restrict__ Wv, const float* __restrict__ Wo,
                       const float* __restrict__ W1, const float* __restrict__ W2,
                       __half* __restrict__ wh, __half* __restrict__ wl) {
    const int l = blockIdx.y;
    const size_t i = ((size_t)blockIdx.x * 256 + threadIdx.x) * 8;
    if (i >= LW) return;
    const float* src;
    if (i < 4 * (size_t)EE) {
        const int ty = (int)(i / EE);
        const float* base = (ty == 0) ? Wq : (ty == 1) ? Wk : (ty == 2) ? Wv : Wo;
        src = base + (size_t)l * EE + (i - (size_t)ty * EE);
    } else if (i < (size_t)OFF_2) {
        src = W1 + (size_t)l * EF + (i - OFF_1);
    } else {
        src = W2 + (size_t)l * EF + (i - OFF_2);
    }
    const float4 v0 = *(const float4*)src;
    const float4 v1 = *(const float4*)(src + 4);
    float f[8] = {v0.x, v0.y, v0.z, v0.w, v1.x, v1.y, v1.z, v1.w};
    uint32_t hi[4], lo[4];
#pragma unroll
    for (int q = 0; q < 4; q++) {
        float2 p; p.x = f[q * 2]; p.y = f[q * 2 + 1];
        const __half2 h2 = __float22half2_rn(p);
        hi[q] = *(const uint32_t*)&h2;
        float2 r;
        r.x = p.x - __half2float(__low2half(h2));
        r.y = p.y - __half2float(__high2half(h2));
        const __half2 l2 = __float22half2_rn(r);
        lo[q] = *(const uint32_t*)&l2;
    }
    const size_t o = (size_t)l * LW + i;
    *(uint4*)(wh + o) = *(uint4*)hi;
    *(uint4*)(wl + o) = *(uint4*)lo;
}

// ---------------- pack qkv biases contiguously (all layers) ----------------
__global__ void k_pack3(const float* __restrict__ a, const float* __restrict__ b,
                        const float* __restrict__ c, float* __restrict__ o) {
    const int l = blockIdx.y;
    const int i = blockIdx.x * 256 + threadIdx.x;
    if (i < E) {
        float* ol = o + (size_t)l * 3 * E;
        ol[i] = a[(size_t)l * E + i];
        ol[E + i] = b[(size_t)l * E + i];
        ol[2 * E + i] = c[(size_t)l * E + i];
    }
}

// ---------------- embedding gather ----------------
__global__ void k_embed(const int* __restrict__ x, const float* __restrict__ emb,
                        float* __restrict__ h, __half* __restrict__ hh) {
    const int row = blockIdx.x;
    const int tok = x[row];
    for (int i = threadIdx.x; i < E; i += 256) {
        const float v = emb[(size_t)tok * E + i];
        const size_t o = (size_t)row * E + i;
        h[o] = v;
        hh[o] = __float2half(v);
    }
}

// ---------------- filler (profiling alignment; negligible cost) ----------------
__global__ void k_fill(float* p) { if (threadIdx.x == 0) p[0] = 0.f; }

// ---------------- softmax: one warp per row of 512 ----------------
__global__ void k_softmax(__half* __restrict__ sc) {
    const int row = blockIdx.x * 8 + (threadIdx.x >> 5);
    const int lane = threadIdx.x & 31;
    uint4* p = (uint4*)(sc + (size_t)row * S);
    uint4 u[2];
    u[0] = p[lane * 2];
    u[1] = p[lane * 2 + 1];

    float f[16];
#pragma unroll
    for (int j = 0; j < 2; j++) {
        const uint32_t* w = (const uint32_t*)&u[j];
#pragma unroll
        for (int q = 0; q < 4; q++) {
            const float2 fv = __half22float2(*(const __half2*)&w[q]);
            f[j * 8 + q * 2] = fv.x; f[j * 8 + q * 2 + 1] = fv.y;
        }
    }
    float m = f[0];
#pragma unroll
    for (int i = 1; i < 16; i++) m = fmaxf(m, f[i]);
#pragma unroll
    for (int off = 16; off; off >>= 1) m = fmaxf(m, __shfl_xor_sync(~0u, m, off));
    float s = 0.f;
#pragma unroll
    for (int i = 0; i < 16; i++) { f[i] = expf(f[i] - m); s += f[i]; }
#pragma unroll
    for (int off = 16; off; off >>= 1) s += __shfl_xor_sync(~0u, s, off);
    const float inv = 1.0f / s;
#pragma unroll
    for (int j = 0; j < 2; j++) {
        uint32_t* w = (uint32_t*)&u[j];
#pragma unroll
        for (int q = 0; q < 4; q++) {
            float2 fv; fv.x = f[j * 8 + q * 2] * inv; fv.y = f[j * 8 + q * 2 + 1] * inv;
            const __half2 h2 = __float22half2_rn(fv);
            w[q] = *(const uint32_t*)&h2;
        }
    }
    p[lane * 2]     = u[0];
    p[lane * 2 + 1] = u[1];
}

// ---------------- layernorm (fp32 in; fp32 + fp16 out) ----------------
__global__ void k_ln(const float* __restrict__ in, float* __restrict__ out,
                     __half* __restrict__ oh,
                     const float* __restrict__ g, const float* __restrict__ b) {
    __shared__ float s1[8], s2[8];
    const int row = blockIdx.x, t = threadIdx.x;
    const int lane = t & 31, w = t >> 5;
    const float* p = in + (size_t)row * E;

    const float x0 = p[t], x1 = p[t + 256], x2 = p[t + 512];
    float a = x0 + x1 + x2;
    float q = x0 * x0 + x1 * x1 + x2 * x2;
#pragma unroll
    for (int off = 16; off; off >>= 1) {
        a += __shfl_xor_sync(~0u, a, off);
        q += __shfl_xor_sync(~0u, q, off);
    }
    if (lane == 0) { s1[w] = a; s2[w] = q; }
    __syncthreads();
    float ta = 0.f, tq = 0.f;
#pragma unroll
    for (int i = 0; i < 8; i++) { ta += s1[i]; tq += s2[i]; }
    const float mean = ta * (1.0f / E);
    const float var  = tq * (1.0f / E) - mean * mean;
    const float inv  = rsqrtf(var + EPSL);

    const size_t base = (size_t)row * E;
#pragma unroll
    for (int k = 0; k < 3; k++) {
        const int idx = t + k * 256;
        const float xv = (k == 0) ? x0 : (k == 1) ? x1 : x2;
        const float v = (xv - mean) * inv * g[idx] + b[idx];
        out[base + idx] = v;
        oh[base + idx]  = __float2half(v);
    }
}

// ---------------- classifier: partials then reduce ----------------
#define CLS_P 16
#define CLS_CHUNK (SE / CLS_P)
__global__ void k_cls1(const float* __restrict__ h, const float* __restrict__ Wc,
                       float* __restrict__ part) {
    __shared__ float red[256];
    const int bb = blockIdx.x, p = blockIdx.y, t = threadIdx.x;
    const float* hr = h + (size_t)bb * SE;
    float a[CC];
#pragma unroll
    for (int c = 0; c < CC; c++) a[c] = 0.f;
    const int i0 = p * CLS_CHUNK;
    for (int i = i0 + t; i < i0 + CLS_CHUNK; i += 256) {
        const float hv = hr[i];
        const float* w = Wc + (size_t)i * CC;
#pragma unroll
        for (int c = 0; c < CC; c++) a[c] = fmaf(hv, w[c], a[c]);
    }
#pragma unroll
    for (int c = 0; c < CC; c++) {
        red[t] = a[c]; __syncthreads();
        for (int k = 128; k > 0; k >>= 1) {
            if (t < k) red[t] += red[t + k];
            __syncthreads();
        }
        if (t == 0) part[((size_t)bb * CLS_P + p) * CC + c] = red[0];
        __syncthreads();
    }
}
__global__ void k_cls2(const float* __restrict__ part, const float* __restrict__ bc,
                       float* __restrict__ out) {
    const int t = threadIdx.x;
    if (t < B * CC) {
        const int bb = t / CC, c = t % CC;
        float s = bc[c];
        for (int p = 0; p < CLS_P; p++) s += part[((size_t)bb * CLS_P + p) * CC + c];
        out[t] = s;
    }
}

// ---------------- host ----------------
extern "C" void kernel_launch(void* const* d_in, const int* in_sizes, int n_in,
                              void* d_out, int out_size) {
    const int*   x    = (const int*)  d_in[0];
    const float* emb  = (const float*)d_in[1];
    const float* Wq   = (const float*)d_in[2];
    const float* bq   = (const float*)d_in[3];
    const float* Wk   = (const float*)d_in[4];
    const float* bk   = (const float*)d_in[5];
    const float* Wv   = (const float*)d_in[6];
    const float* bv   = (const float*)d_in[7];
    const float* Wo   = (const float*)d_in[8];
    const float* bo   = (const float*)d_in[9];
    const float* ln1g = (const float*)d_in[10];
    const float* ln1b = (const float*)d_in[11];
    const float* W1   = (const float*)d_in[12];
    const float* b1   = (const float*)d_in[13];
    const float* W2   = (const float*)d_in[14];
    const float* b2   = (const float*)d_in[15];
    const float* ln2g = (const float*)d_in[16];
    const float* ln2b = (const float*)d_in[17];
    const float* Wc   = (const float*)d_in[18];
    const float* bc   = (const float*)d_in[19];
    float* out = (float*)d_out;

    float *h, *t, *bqkv;
    __half *hh, *qkv, *ch, *fh, *sc, *wh, *wl;
    cudaGetSymbolAddress((void**)&h,   g_h);
    cudaGetSymbolAddress((void**)&t,   g_t);
    cudaGetSymbolAddress((void**)&hh,  g_hh);
    cudaGetSymbolAddress((void**)&qkv, g_qkv);
    cudaGetSymbolAddress((void**)&ch,  g_ch);
    cudaGetSymbolAddress((void**)&fh,  g_fh);
    cudaGetSymbolAddress((void**)&sc,  g_sc);
    cudaGetSymbolAddress((void**)&wh,  g_wh); cudaGetSymbolAddress((void**)&wl, g_wl);
    cudaGetSymbolAddress((void**)&bqkv, g_bqkv);

    // smem: 3 stages; A tile 128*80; B tile TB: 32*(BN+8)*2 (x2 if DUAL), non-TB: BN*80
    constexpr int SMEM_D = 3 * (128 * 80 + 2 * 32 * (128 + 8) * 2); // 82944
    constexpr int SMEM_S = 3 * (128 * 80 + 128 * 80);               // 61440
    constexpr int SMEM_C = 3 * (128 * 80 + 32 * (64 + 8) * 2);      // 44544
    cudaFuncSetAttribute(k_mma<128, true,  true>,  cudaFuncAttributeMaxDynamicSharedMemorySize, SMEM_D);
    cudaFuncSetAttribute(k_mma<128, false, false>, cudaFuncAttributeMaxDynamicSharedMemorySize, SMEM_S);
    cudaFuncSetAttribute(k_mma<64,  false, true>,  cudaFuncAttributeMaxDynamicSharedMemorySize, SMEM_C);

    __half *qh = qkv, *kh = qkv + (size_t)M4 * E, *vh = qkv + (size_t)2 * M4 * E;

    // 1: fused weight split, 2: bias pack, 3: embed, 4-5: fillers (ncu -s 5 lands on QKV)
    k_prep<<<dim3(LW / 2048, L), 256>>>(Wq, Wk, Wv, Wo, W1, W2, wh, wl);
    k_pack3<<<dim3(3, L), 256>>>(bq, bk, bv, bqkv);
    k_embed<<<M4, 256>>>(x, emb, h, hh);
    k_fill<<<1, 32>>>(t);
    k_fill<<<1, 32>>>(t);

    const dim3 gQKV(6, 32, 3);
    const dim3 gEE(6, 32);
    const dim3 gF1(24, 32);
    const dim3 gSc(4, 4, NHEAD);
    const dim3 gCx(1, 4, NHEAD);

    for (int l = 0; l < L; l++) {
        const size_t wb = (size_t)l * LW;

        // fused QKV (weights dual)
        k_mma<128, true, true><<<gQKV, 256, SMEM_D>>>(hh, wh + wb + OFF_Q, wl + wb + OFF_Q,
            bqkv + (size_t)l * 3 * E, nullptr, nullptr, qkv,
            E, E, 0, (size_t)EE, (size_t)M4 * E, E, 1.f, 0);

        // scores = Q K^T / 8, softmax, ctx = P V
        k_mma<128, false, false><<<gSc, 256, SMEM_S>>>(qh, kh, nullptr,
            nullptr, nullptr, nullptr, sc,
            S, DH, HSZ, HSZ, (size_t)S * S, 0, 0.125f, 0);
        k_softmax<<<NHEAD * S / 8, 256>>>(sc);
        k_mma<64, false, true><<<gCx, 256, SMEM_C>>>(sc, vh, nullptr,
            nullptr, nullptr, nullptr, ch,
            DH, S, (size_t)S * S, HSZ, HSZ, 0, 1.f, 0);

        // Wo + residual -> LN1
        k_mma<128, true, true><<<gEE, 256, SMEM_D>>>(ch, wh + wb + OFF_O, wl + wb + OFF_O,
            bo + (size_t)l * E, h, t, nullptr,
            E, E, 0, 0, 0, 0, 1.f, 0);
        k_ln<<<M4, 256>>>(t, h, hh, ln1g + (size_t)l * E, ln1b + (size_t)l * E);

        // FFN
        k_mma<128, true, true><<<gF1, 256, SMEM_D>>>(hh, wh + wb + OFF_1, wl + wb + OFF_1,
            b1 + (size_t)l * FF, nullptr, nullptr, fh,
            FF, E, 0, 0, 0, 0, 1.f, 1);
        k_mma<128, true, true><<<gEE, 256, SMEM_D>>>(fh, wh + wb + OFF_2, wl + wb + OFF_2,
            b2 + (size_t)l * E, h, t, nullptr,
            E, FF, 0, 0, 0, 0, 1.f, 0);
        k_ln<<<M4, 256>>>(t, h, hh, ln2g + (size_t)l * E, ln2b + (size_t)l * E);
    }

    // classifier (fp32 exact)
    k_cls1<<<dim3(B, CLS_P), 256>>>(h, Wc, t);
    k_cls2<<<1, 128>>>(t, bc, out);
}

// round 7
// speedup vs baseline: 6.0655x; 1.4112x over previous
#include <cuda_runtime.h>
#include <cuda_fp16.h>
#include <cstdint>
#include <math.h>

// ---------------- problem constants ----------------
#define B    8
#define S    512
#define E    768
#define NH   12
#define DH   64
#define FF   3072
#define L    6
#define CC   10
#define M4   (B*S)          // 4096 rows
#define HSZ  (S*DH)         // 32768 per-head elems
#define NHEAD (B*NH)        // 96
#define EPSL 1e-5f
#define SE   (S*E)

// per-layer weight block (elems), native [K,N] layout: Wq,Wk,Wv,Wo,W1,W2
#define EE   (E*E)
#define EF   (E*FF)
#define LW   (4*EE + 2*EF)
#define OFF_Q 0
#define OFF_K EE
#define OFF_V (2*EE)
#define OFF_O (3*EE)
#define OFF_1 (4*EE)
#define OFF_2 (4*EE + EF)

// ---------------- scratch (device globals) ----------------
__device__ float g_h [M4*E];
__device__ float g_t [M4*E];                    // pre-LN buffer; cls partials
__device__ __half g_hh[M4*E];
__device__ __half g_qkv[3*M4*E];
__device__ __half g_ch[M4*E];
__device__ __half g_fh[M4*FF];
__device__ __half g_sc[(size_t)NHEAD*S*S];
__device__ __half g_wh[(size_t)L*LW];
__device__ float g_bqkv[L*3*E];

// ---------------- asm helpers ----------------
__device__ __forceinline__ uint32_t smem_u32(const void* p) {
    uint32_t a;
    asm("{ .reg .u64 t; cvta.to.shared.u64 t, %1; cvt.u32.u64 %0, t; }" : "=r"(a) : "l"(p));
    return a;
}
__device__ __forceinline__ void ldsm4(uint32_t* r, uint32_t a) {
    asm volatile("ldmatrix.sync.aligned.m8n8.x4.shared.b16 {%0,%1,%2,%3}, [%4];"
        : "=r"(r[0]), "=r"(r[1]), "=r"(r[2]), "=r"(r[3]) : "r"(a));
}
__device__ __forceinline__ void ldsm4t(uint32_t* r, uint32_t a) {
    asm volatile("ldmatrix.sync.aligned.m8n8.x4.trans.shared.b16 {%0,%1,%2,%3}, [%4];"
        : "=r"(r[0]), "=r"(r[1]), "=r"(r[2]), "=r"(r[3]) : "r"(a));
}
__device__ __forceinline__ void mma_f16(float* c, const uint32_t* a, const uint32_t* b) {
    asm volatile("mma.sync.aligned.m16n8k16.row.col.f32.f16.f16.f32 "
        "{%0,%1,%2,%3}, {%4,%5,%6,%7}, {%8,%9}, {%0,%1,%2,%3};"
        : "+f"(c[0]), "+f"(c[1]), "+f"(c[2]), "+f"(c[3])
        : "r"(a[0]), "r"(a[1]), "r"(a[2]), "r"(a[3]), "r"(b[0]), "r"(b[1]));
}
#define CPA(dst, src) asm volatile("cp.async.cg.shared.global [%0], [%1], 16;" :: "r"(dst), "l"(src))
#define CPC() asm volatile("cp.async.commit_group;" ::: "memory")
#define CPW(n) asm volatile("cp.async.wait_group %0;" :: "n"(n) : "memory")

// ================= HMMA GEMM (fp16 in, fp32 accum, single product) =================
// D[row,col] = scale*sum_k A[row,k]*B(col,k) (+bias)(relu)(+res)
// TB=false: B stored [N,K]. TB=true: B stored [K,N] (ldmatrix.trans).
// BM=128; BN in {128,64}; BK=32; 256 threads; 3-stage cp.async; 2 CTAs/SM.
template<int BN, bool TB>
__global__ void __launch_bounds__(256, 2)
k_mma(const __half* __restrict__ Ah, const __half* __restrict__ Bh,
      const float* __restrict__ bias, const float* __restrict__ res,
      float* __restrict__ Cf, __half* __restrict__ Chi,
      int N, int K, size_t sAz, size_t sBz, size_t sCz, size_t bsz,
      float scale, int relu) {
    extern __shared__ char sm[];
    constexpr int WN  = (BN == 128) ? 4 : 2;
    constexpr int WM  = 8 / WN;
    constexpr int WTM = 128 / WM;
    constexpr int WTN = BN / WN;               // 32
    constexpr int MF  = WTM / 16;
    constexpr int NF  = WTN / 8;               // 4
    constexpr int ATILE  = 128 * 80;
    constexpr int BPITCH = TB ? (BN + 8) * 2 : 80;
    constexpr int BTILE  = TB ? 32 * BPITCH : BN * 80;
    constexpr int STAGE  = ATILE + BTILE;

    const uint32_t smb = smem_u32(sm);
    const int tid = threadIdx.x, lane = tid & 31, wid = tid >> 5;
    const int wm = wid / WN, wn = wid % WN;
    const int bm = blockIdx.y * 128, bn = blockIdx.x * BN;
    const size_t zA = (size_t)blockIdx.z * sAz, zB = (size_t)blockIdx.z * sBz;
    const __half* pA = Ah + zA + (size_t)bm * K;
    const __half* pB = TB ? Bh + zB : Bh + zB + (size_t)bn * K;

    float acc[MF][NF][4];
#pragma unroll
    for (int i = 0; i < MF; i++)
#pragma unroll
        for (int j = 0; j < NF; j++)
#pragma unroll
            for (int q = 0; q < 4; q++) acc[i][j][q] = 0.f;

    const uint32_t a_off = (uint32_t)(lane & 15) * 80 + (uint32_t)(lane >> 4) * 16;
    const uint32_t b_off = TB
        ? (uint32_t)(lane & 15) * BPITCH + (uint32_t)(lane >> 4) * 16
        : (uint32_t)((lane & 7) + ((lane >> 1) & 8)) * 80 + (uint32_t)((lane >> 3) & 1) * 16;

    const int KT = K >> 5;

    auto load_stage = [&](int s, int kt) {
        const int k0 = kt << 5;
        const uint32_t base = smb + s * STAGE;
#pragma unroll 2
        for (int cid = tid; cid < 512; cid += 256) {
            const int row = cid >> 2, p = cid & 3;
            CPA(base + row * 80 + p * 16, pA + (size_t)row * K + k0 + p * 8);
        }
        if (TB) {
#pragma unroll 2
            for (int cid = tid; cid < 32 * (BN / 8); cid += 256) {
                const int row = cid / (BN / 8), c = cid % (BN / 8);
                CPA(base + ATILE + row * BPITCH + c * 16,
                    pB + (size_t)(k0 + row) * N + bn + c * 8);
            }
        } else {
#pragma unroll 2
            for (int cid = tid; cid < BN * 4; cid += 256) {
                const int row = cid >> 2, p = cid & 3;
                CPA(base + ATILE + row * 80 + p * 16, pB + (size_t)row * K + k0 + p * 8);
            }
        }
    };

    load_stage(0, 0); CPC();
    if (KT > 1) { load_stage(1, 1); CPC(); }

    int stg = 0;
    for (int kt = 0; kt < KT; ++kt) {
        if (kt + 2 < KT) { load_stage((stg + 2) % 3, kt + 2); CPC(); CPW(2); }
        else if (kt + 1 < KT) CPW(1);
        else CPW(0);
        __syncthreads();

        const uint32_t stageB = smb + stg * STAGE;
        const uint32_t aB = stageB + wm * WTM * 80 + a_off;
        const uint32_t bB = TB ? stageB + ATILE + wn * WTN * 2 + b_off
                               : stageB + ATILE + wn * WTN * 80 + b_off;
#pragma unroll
        for (int ks = 0; ks < 2; ++ks) {
            uint32_t aR[MF][4], bR[NF / 2][4];
#pragma unroll
            for (int n2 = 0; n2 < NF / 2; n2++) {
                const uint32_t ad = TB ? bB + ks * 16 * BPITCH + n2 * 32
                                       : bB + n2 * 16 * 80 + ks * 32;
                if (TB) ldsm4t(bR[n2], ad); else ldsm4(bR[n2], ad);
            }
#pragma unroll
            for (int mi = 0; mi < MF; mi++)
                ldsm4(aR[mi], aB + mi * 16 * 80 + ks * 32);

#pragma unroll
            for (int mi = 0; mi < MF; mi++)
#pragma unroll
                for (int n2 = 0; n2 < NF / 2; n2++) {
                    mma_f16(acc[mi][n2 * 2],     aR[mi], &bR[n2][0]);
                    mma_f16(acc[mi][n2 * 2 + 1], aR[mi], &bR[n2][2]);
                }
        }
        __syncthreads();
        stg = (stg + 1) % 3;
    }

    // ---- epilogue ----
    const size_t cz = (size_t)blockIdx.z * sCz;
    const float* bz = bias ? bias + (size_t)blockIdx.z * bsz : nullptr;
    const int r0 = bm + wm * WTM + (lane >> 2);
    const int c0 = bn + wn * WTN + (lane & 3) * 2;

#pragma unroll
    for (int mi = 0; mi < MF; mi++) {
#pragma unroll
        for (int ni = 0; ni < NF; ni++) {
            const int col = c0 + ni * 8;
#pragma unroll
            for (int half = 0; half < 2; half++) {
                const int row = r0 + mi * 16 + half * 8;
                float v0 = acc[mi][ni][half * 2]     * scale;
                float v1 = acc[mi][ni][half * 2 + 1] * scale;
                if (bz) { v0 += bz[col]; v1 += bz[col + 1]; }
                if (relu) { v0 = fmaxf(v0, 0.f); v1 = fmaxf(v1, 0.f); }
                if (res) {
                    const float2 rv = *(const float2*)&res[(size_t)row * N + col];
                    v0 += rv.x; v1 += rv.y;
                }
                const size_t o = cz + (size_t)row * N + col;
                if (Cf) { float2 f = {v0, v1}; *(float2*)&Cf[o] = f; }
                if (Chi) {
                    float2 fv; fv.x = v0; fv.y = v1;
                    *(__half2*)&Chi[o] = __float22half2_rn(fv);
                }
            }
        }
    }
}

// ---------------- fused weight fp16 convert (all 6 matrices, native layout) ----
__global__ void k_prep(const float* __restrict__ Wq, const float* __restrict__ Wk,
                       const float* __restrict__ Wv, const float* __restrict__ Wo,
                       const float* __restrict__ W1, const float* __restrict__ W2,
                       __half* __restrict__ wh) {
    const int l = blockIdx.y;
    const size_t i = ((size_t)blockIdx.x * 256 + threadIdx.x) * 8;
    if (i >= LW) return;
    const float* src;
    if (i < 4 * (size_t)EE) {
        const int ty = (int)(i / EE);
        const float* base = (ty == 0) ? Wq : (ty == 1) ? Wk : (ty == 2) ? Wv : Wo;
        src = base + (size_t)l * EE + (i - (size_t)ty * EE);
    } else if (i < (size_t)OFF_2) {
        src = W1 + (size_t)l * EF + (i - OFF_1);
    } else {
        src = W2 + (size_t)l * EF + (i - OFF_2);
    }
    const float4 v0 = *(const float4*)src;
    const float4 v1 = *(const float4*)(src + 4);
    float f[8] = {v0.x, v0.y, v0.z, v0.w, v1.x, v1.y, v1.z, v1.w};
    uint32_t hi[4];
#pragma unroll
    for (int q = 0; q < 4; q++) {
        float2 p; p.x = f[q * 2]; p.y = f[q * 2 + 1];
        const __half2 h2 = __float22half2_rn(p);
        hi[q] = *(const uint32_t*)&h2;
    }
    *(uint4*)(wh + (size_t)l * LW + i) = *(uint4*)hi;
}

// ---------------- pack qkv biases contiguously (all layers) ----------------
__global__ void k_pack3(const float* __restrict__ a, const float* __restrict__ b,
                        const float* __restrict__ c, float* __restrict__ o) {
    const int l = blockIdx.y;
    const int i = blockIdx.x * 256 + threadIdx.x;
    if (i < E) {
        float* ol = o + (size_t)l * 3 * E;
        ol[i] = a[(size_t)l * E + i];
        ol[E + i] = b[(size_t)l * E + i];
        ol[2 * E + i] = c[(size_t)l * E + i];
    }
}

// ---------------- embedding gather ----------------
__global__ void k_embed(const int* __restrict__ x, const float* __restrict__ emb,
                        float* __restrict__ h, __half* __restrict__ hh) {
    const int row = blockIdx.x;
    const int tok = x[row];
    for (int i = threadIdx.x; i < E; i += 256) {
        const float v = emb[(size_t)tok * E + i];
        const size_t o = (size_t)row * E + i;
        h[o] = v;
        hh[o] = __float2half(v);
    }
}

// ---------------- softmax: one warp per row of 512 ----------------
__global__ void k_softmax(__half* __restrict__ sc) {
    const int row = blockIdx.x * 8 + (threadIdx.x >> 5);
    const int lane = threadIdx.x & 31;
    uint4* p = (uint4*)(sc + (size_t)row * S);
    uint4 u[2];
    u[0] = p[lane * 2];
    u[1] = p[lane * 2 + 1];

    float f[16];
#pragma unroll
    for (int j = 0; j < 2; j++) {
        const uint32_t* w = (const uint32_t*)&u[j];
#pragma unroll
        for (int q = 0; q < 4; q++) {
            const float2 fv = __half22float2(*(const __half2*)&w[q]);
            f[j * 8 + q * 2] = fv.x; f[j * 8 + q * 2 + 1] = fv.y;
        }
    }
    float m = f[0];
#pragma unroll
    for (int i = 1; i < 16; i++) m = fmaxf(m, f[i]);
#pragma unroll
    for (int off = 16; off; off >>= 1) m = fmaxf(m, __shfl_xor_sync(~0u, m, off));
    float s = 0.f;
#pragma unroll
    for (int i = 0; i < 16; i++) { f[i] = expf(f[i] - m); s += f[i]; }
#pragma unroll
    for (int off = 16; off; off >>= 1) s += __shfl_xor_sync(~0u, s, off);
    const float inv = 1.0f / s;
#pragma unroll
    for (int j = 0; j < 2; j++) {
        uint32_t* w = (uint32_t*)&u[j];
#pragma unroll
        for (int q = 0; q < 4; q++) {
            float2 fv; fv.x = f[j * 8 + q * 2] * inv; fv.y = f[j * 8 + q * 2 + 1] * inv;
            const __half2 h2 = __float22half2_rn(fv);
            w[q] = *(const uint32_t*)&h2;
        }
    }
    p[lane * 2]     = u[0];
    p[lane * 2 + 1] = u[1];
}

// ---------------- layernorm (fp32 in; fp32 + fp16 out) ----------------
__global__ void k_ln(const float* __restrict__ in, float* __restrict__ out,
                     __half* __restrict__ oh,
                     const float* __restrict__ g, const float* __restrict__ b) {
    __shared__ float s1[8], s2[8];
    const int row = blockIdx.x, t = threadIdx.x;
    const int lane = t & 31, w = t >> 5;
    const float* p = in + (size_t)row * E;

    const float x0 = p[t], x1 = p[t + 256], x2 = p[t + 512];
    float a = x0 + x1 + x2;
    float q = x0 * x0 + x1 * x1 + x2 * x2;
#pragma unroll
    for (int off = 16; off; off >>= 1) {
        a += __shfl_xor_sync(~0u, a, off);
        q += __shfl_xor_sync(~0u, q, off);
    }
    if (lane == 0) { s1[w] = a; s2[w] = q; }
    __syncthreads();
    float ta = 0.f, tq = 0.f;
#pragma unroll
    for (int i = 0; i < 8; i++) { ta += s1[i]; tq += s2[i]; }
    const float mean = ta * (1.0f / E);
    const float var  = tq * (1.0f / E) - mean * mean;
    const float inv  = rsqrtf(var + EPSL);

    const size_t base = (size_t)row * E;
#pragma unroll
    for (int k = 0; k < 3; k++) {
        const int idx = t + k * 256;
        const float xv = (k == 0) ? x0 : (k == 1) ? x1 : x2;
        const float v = (xv - mean) * inv * g[idx] + b[idx];
        out[base + idx] = v;
        oh[base + idx]  = __float2half(v);
    }
}

// ---------------- classifier: partials then reduce ----------------
#define CLS_P 16
#define CLS_CHUNK (SE / CLS_P)
__global__ void k_cls1(const float* __restrict__ h, const float* __restrict__ Wc,
                       float* __restrict__ part) {
    __shared__ float red[256];
    const int bb = blockIdx.x, p = blockIdx.y, t = threadIdx.x;
    const float* hr = h + (size_t)bb * SE;
    float a[CC];
#pragma unroll
    for (int c = 0; c < CC; c++) a[c] = 0.f;
    const int i0 = p * CLS_CHUNK;
    for (int i = i0 + t; i < i0 + CLS_CHUNK; i += 256) {
        const float hv = hr[i];
        const float* w = Wc + (size_t)i * CC;
#pragma unroll
        for (int c = 0; c < CC; c++) a[c] = fmaf(hv, w[c], a[c]);
    }
#pragma unroll
    for (int c = 0; c < CC; c++) {
        red[t] = a[c]; __syncthreads();
        for (int k = 128; k > 0; k >>= 1) {
            if (t < k) red[t] += red[t + k];
            __syncthreads();
        }
        if (t == 0) part[((size_t)bb * CLS_P + p) * CC + c] = red[0];
        __syncthreads();
    }
}
__global__ void k_cls2(const float* __restrict__ part, const float* __restrict__ bc,
                       float* __restrict__ out) {
    const int t = threadIdx.x;
    if (t < B * CC) {
        const int bb = t / CC, c = t % CC;
        float s = bc[c];
        for (int p = 0; p < CLS_P; p++) s += part[((size_t)bb * CLS_P + p) * CC + c];
        out[t] = s;
    }
}

// ---------------- host ----------------
extern "C" void kernel_launch(void* const* d_in, const int* in_sizes, int n_in,
                              void* d_out, int out_size) {
    const int*   x    = (const int*)  d_in[0];
    const float* emb  = (const float*)d_in[1];
    const float* Wq   = (const float*)d_in[2];
    const float* bq   = (const float*)d_in[3];
    const float* Wk   = (const float*)d_in[4];
    const float* bk   = (const float*)d_in[5];
    const float* Wv   = (const float*)d_in[6];
    const float* bv   = (const float*)d_in[7];
    const float* Wo   = (const float*)d_in[8];
    const float* bo   = (const float*)d_in[9];
    const float* ln1g = (const float*)d_in[10];
    const float* ln1b = (const float*)d_in[11];
    const float* W1   = (const float*)d_in[12];
    const float* b1   = (const float*)d_in[13];
    const float* W2   = (const float*)d_in[14];
    const float* b2   = (const float*)d_in[15];
    const float* ln2g = (const float*)d_in[16];
    const float* ln2b = (const float*)d_in[17];
    const float* Wc   = (const float*)d_in[18];
    const float* bc   = (const float*)d_in[19];
    float* out = (float*)d_out;

    float *h, *t, *bqkv;
    __half *hh, *qkv, *ch, *fh, *sc, *wh;
    cudaGetSymbolAddress((void**)&h,   g_h);
    cudaGetSymbolAddress((void**)&t,   g_t);
    cudaGetSymbolAddress((void**)&hh,  g_hh);
    cudaGetSymbolAddress((void**)&qkv, g_qkv);
    cudaGetSymbolAddress((void**)&ch,  g_ch);
    cudaGetSymbolAddress((void**)&fh,  g_fh);
    cudaGetSymbolAddress((void**)&sc,  g_sc);
    cudaGetSymbolAddress((void**)&wh,  g_wh);
    cudaGetSymbolAddress((void**)&bqkv, g_bqkv);

    // smem: 3 stages; A tile 128*80; B tile TB: 32*(BN+8)*2, non-TB: BN*80
    constexpr int SMEM_D = 3 * (128 * 80 + 32 * (128 + 8) * 2); // 56832 (TB BN=128)
    constexpr int SMEM_S = 3 * (128 * 80 + 128 * 80);           // 61440 (non-TB BN=128)
    constexpr int SMEM_C = 3 * (128 * 80 + 32 * (64 + 8) * 2);  // 44544 (TB BN=64)
    cudaFuncSetAttribute(k_mma<128, true>,  cudaFuncAttributeMaxDynamicSharedMemorySize, SMEM_D);
    cudaFuncSetAttribute(k_mma<128, false>, cudaFuncAttributeMaxDynamicSharedMemorySize, SMEM_S);
    cudaFuncSetAttribute(k_mma<64,  true>,  cudaFuncAttributeMaxDynamicSharedMemorySize, SMEM_C);

    __half *qh = qkv, *kh = qkv + (size_t)M4 * E, *vh = qkv + (size_t)2 * M4 * E;

    // launches 1-3: prep, pack3, embed. Launch 4 = QKV GEMM (ncu capture target).
    k_prep<<<dim3(LW / 2048, L), 256>>>(Wq, Wk, Wv, Wo, W1, W2, wh);
    k_pack3<<<dim3(3, L), 256>>>(bq, bk, bv, bqkv);
    k_embed<<<M4, 256>>>(x, emb, h, hh);

    const dim3 gQKV(6, 32, 3);
    const dim3 gEE(6, 32);
    const dim3 gF1(24, 32);
    const dim3 gSc(4, 4, NHEAD);
    const dim3 gCx(1, 4, NHEAD);

    for (int l = 0; l < L; l++) {
        const size_t wb = (size_t)l * LW;

        // fused QKV
        k_mma<128, true><<<gQKV, 256, SMEM_D>>>(hh, wh + wb + OFF_Q,
            bqkv + (size_t)l * 3 * E, nullptr, nullptr, qkv,
            E, E, 0, (size_t)EE, (size_t)M4 * E, E, 1.f, 0);

        // scores = Q K^T / 8, softmax, ctx = P V
        k_mma<128, false><<<gSc, 256, SMEM_S>>>(qh, kh,
            nullptr, nullptr, nullptr, sc,
            S, DH, HSZ, HSZ, (size_t)S * S, 0, 0.125f, 0);
        k_softmax<<<NHEAD * S / 8, 256>>>(sc);
        k_mma<64, true><<<gCx, 256, SMEM_C>>>(sc, vh,
            nullptr, nullptr, nullptr, ch,
            DH, S, (size_t)S * S, HSZ, HSZ, 0, 1.f, 0);

        // Wo + residual -> LN1
        k_mma<128, true><<<gEE, 256, SMEM_D>>>(ch, wh + wb + OFF_O,
            bo + (size_t)l * E, h, t, nullptr,
            E, E, 0, 0, 0, 0, 1.f, 0);
        k_ln<<<M4, 256>>>(t, h, hh, ln1g + (size_t)l * E, ln1b + (size_t)l * E);

        // FFN
        k_mma<128, true><<<gF1, 256, SMEM_D>>>(hh, wh + wb + OFF_1,
            b1 + (size_t)l * FF, nullptr, nullptr, fh,
            FF, E, 0, 0, 0, 0, 1.f, 1);
        k_mma<128, true><<<gEE, 256, SMEM_D>>>(fh, wh + wb + OFF_2,
            b2 + (size_t)l * E, h, t, nullptr,
            E, FF, 0, 0, 0, 0, 1.f, 0);
        k_ln<<<M4, 256>>>(t, h, hh, ln2g + (size_t)l * E, ln2b + (size_t)l * E);
    }

    // classifier (fp32 exact)
    k_cls1<<<dim3(B, CLS_P), 256>>>(h, Wc, t);
    k_cls2<<<1, 128>>>(t, bc, out);
}

// round 8
// speedup vs baseline: 6.1096x; 1.0073x over previous
#include <cuda_runtime.h>
#include <cuda_fp16.h>
#include <cstdint>
#include <math.h>

// ---------------- problem constants ----------------
#define B    8
#define S    512
#define E    768
#define NH   12
#define DH   64
#define FF   3072
#define L    6
#define CC   10
#define M4   (B*S)          // 4096 rows
#define HSZ  (S*DH)         // 32768 per-head elems
#define NHEAD (B*NH)        // 96
#define EPSL 1e-5f
#define SE   (S*E)

// per-layer weight block (elems), native [K,N] layout: Wq,Wk,Wv,Wo,W1,W2
#define EE   (E*E)
#define EF   (E*FF)
#define LW   (4*EE + 2*EF)
#define OFF_Q 0
#define OFF_K EE
#define OFF_V (2*EE)
#define OFF_O (3*EE)
#define OFF_1 (4*EE)
#define OFF_2 (4*EE + EF)

// ---------------- scratch (device globals) ----------------
__device__ float g_h [M4*E];
__device__ float g_t [M4*E];                    // pre-LN buffer; cls partials
__device__ __half g_hh[M4*E];
__device__ __half g_qkv[3*M4*E];
__device__ __half g_ch[M4*E];
__device__ __half g_fh[M4*FF];
__device__ __half g_sc[(size_t)NHEAD*S*S];
__device__ __half g_wh[(size_t)L*LW];
__device__ float g_bqkv[L*3*E];

// ---------------- asm helpers ----------------
__device__ __forceinline__ uint32_t smem_u32(const void* p) {
    uint32_t a;
    asm("{ .reg .u64 t; cvta.to.shared.u64 t, %1; cvt.u32.u64 %0, t; }" : "=r"(a) : "l"(p));
    return a;
}
__device__ __forceinline__ void ldsm4(uint32_t* r, uint32_t a) {
    asm volatile("ldmatrix.sync.aligned.m8n8.x4.shared.b16 {%0,%1,%2,%3}, [%4];"
        : "=r"(r[0]), "=r"(r[1]), "=r"(r[2]), "=r"(r[3]) : "r"(a));
}
__device__ __forceinline__ void ldsm4t(uint32_t* r, uint32_t a) {
    asm volatile("ldmatrix.sync.aligned.m8n8.x4.trans.shared.b16 {%0,%1,%2,%3}, [%4];"
        : "=r"(r[0]), "=r"(r[1]), "=r"(r[2]), "=r"(r[3]) : "r"(a));
}
__device__ __forceinline__ void mma_f16(float* c, const uint32_t* a, const uint32_t* b) {
    asm volatile("mma.sync.aligned.m16n8k16.row.col.f32.f16.f16.f32 "
        "{%0,%1,%2,%3}, {%4,%5,%6,%7}, {%8,%9}, {%0,%1,%2,%3};"
        : "+f"(c[0]), "+f"(c[1]), "+f"(c[2]), "+f"(c[3])
        : "r"(a[0]), "r"(a[1]), "r"(a[2]), "r"(a[3]), "r"(b[0]), "r"(b[1]));
}
#define CPA(dst, src) asm volatile("cp.async.cg.shared.global [%0], [%1], 16;" :: "r"(dst), "l"(src))
#define CPC() asm volatile("cp.async.commit_group;" ::: "memory")
#define CPW(n) asm volatile("cp.async.wait_group %0;" :: "n"(n) : "memory")

// ================= HMMA GEMM (fp16 in, fp32 accum, single product) =================
// D[row,col] = scale*sum_k A[row,k]*B(col,k) (+bias)(relu)(+res)
// TB=false: B stored [N,K]. TB=true: B stored [K,N] (ldmatrix.trans).
// BM=128; BN in {128,64}; BK=32; 256 threads; 3-stage cp.async; 2 CTAs/SM.
// Warp layout: 4 warps along M (WTM=32) x 2 warps along N (WTN=BN/2).
template<int BN, bool TB>
__global__ void __launch_bounds__(256, 2)
k_mma(const __half* __restrict__ Ah, const __half* __restrict__ Bh,
      const float* __restrict__ bias, const float* __restrict__ res,
      float* __restrict__ Cf, __half* __restrict__ Chi,
      int N, int K, size_t sAz, size_t sBz, size_t sCz, size_t bsz,
      float scale, int relu) {
    extern __shared__ char sm[];
    constexpr int WN  = 2;
    constexpr int WM  = 4;
    constexpr int WTM = 32;
    constexpr int WTN = BN / WN;               // 64 or 32
    constexpr int MF  = WTM / 16;              // 2
    constexpr int NF  = WTN / 8;               // 8 or 4
    constexpr int ATILE  = 128 * 80;
    constexpr int BPITCH = TB ? (BN + 8) * 2 : 80;
    constexpr int BTILE  = TB ? 32 * BPITCH : BN * 80;
    constexpr int STAGE  = ATILE + BTILE;

    const uint32_t smb = smem_u32(sm);
    const int tid = threadIdx.x, lane = tid & 31, wid = tid >> 5;
    const int wm = wid / WN, wn = wid % WN;
    const int bm = blockIdx.y * 128, bn = blockIdx.x * BN;
    const size_t zA = (size_t)blockIdx.z * sAz, zB = (size_t)blockIdx.z * sBz;
    const __half* pA = Ah + zA + (size_t)bm * K;
    const __half* pB = TB ? Bh + zB : Bh + zB + (size_t)bn * K;

    float acc[MF][NF][4];
#pragma unroll
    for (int i = 0; i < MF; i++)
#pragma unroll
        for (int j = 0; j < NF; j++)
#pragma unroll
            for (int q = 0; q < 4; q++) acc[i][j][q] = 0.f;

    const uint32_t a_off = (uint32_t)(lane & 15) * 80 + (uint32_t)(lane >> 4) * 16;
    const uint32_t b_off = TB
        ? (uint32_t)(lane & 15) * BPITCH + (uint32_t)(lane >> 4) * 16
        : (uint32_t)((lane & 7) + ((lane >> 1) & 8)) * 80 + (uint32_t)((lane >> 3) & 1) * 16;

    const int KT = K >> 5;

    auto load_stage = [&](int s, int kt) {
        const int k0 = kt << 5;
        const uint32_t base = smb + s * STAGE;
#pragma unroll 2
        for (int cid = tid; cid < 512; cid += 256) {
            const int row = cid >> 2, p = cid & 3;
            CPA(base + row * 80 + p * 16, pA + (size_t)row * K + k0 + p * 8);
        }
        if (TB) {
#pragma unroll 2
            for (int cid = tid; cid < 32 * (BN / 8); cid += 256) {
                const int row = cid / (BN / 8), c = cid % (BN / 8);
                CPA(base + ATILE + row * BPITCH + c * 16,
                    pB + (size_t)(k0 + row) * N + bn + c * 8);
            }
        } else {
#pragma unroll 2
            for (int cid = tid; cid < BN * 4; cid += 256) {
                const int row = cid >> 2, p = cid & 3;
                CPA(base + ATILE + row * 80 + p * 16, pB + (size_t)row * K + k0 + p * 8);
            }
        }
    };

    load_stage(0, 0); CPC();
    if (KT > 1) { load_stage(1, 1); CPC(); }

    int stg = 0;
    for (int kt = 0; kt < KT; ++kt) {
        if (kt + 2 < KT) { load_stage((stg + 2) % 3, kt + 2); CPC(); CPW(2); }
        else if (kt + 1 < KT) CPW(1);
        else CPW(0);
        __syncthreads();

        const uint32_t stageB = smb + stg * STAGE;
        const uint32_t aB = stageB + wm * WTM * 80 + a_off;
        const uint32_t bB = TB ? stageB + ATILE + wn * WTN * 2 + b_off
                               : stageB + ATILE + wn * WTN * 80 + b_off;
#pragma unroll
        for (int ks = 0; ks < 2; ++ks) {
            uint32_t aR[MF][4], bR[NF / 2][4];
#pragma unroll
            for (int n2 = 0; n2 < NF / 2; n2++) {
                const uint32_t ad = TB ? bB + ks * 16 * BPITCH + n2 * 32
                                       : bB + n2 * 16 * 80 + ks * 32;
                if (TB) ldsm4t(bR[n2], ad); else ldsm4(bR[n2], ad);
            }
#pragma unroll
            for (int mi = 0; mi < MF; mi++)
                ldsm4(aR[mi], aB + mi * 16 * 80 + ks * 32);

#pragma unroll
            for (int mi = 0; mi < MF; mi++)
#pragma unroll
                for (int n2 = 0; n2 < NF / 2; n2++) {
                    mma_f16(acc[mi][n2 * 2],     aR[mi], &bR[n2][0]);
                    mma_f16(acc[mi][n2 * 2 + 1], aR[mi], &bR[n2][2]);
                }
        }
        __syncthreads();
        stg = (stg + 1) % 3;
    }

    // ---- epilogue ----
    const size_t cz = (size_t)blockIdx.z * sCz;
    const float* bz = bias ? bias + (size_t)blockIdx.z * bsz : nullptr;
    const int r0 = bm + wm * WTM + (lane >> 2);
    const int c0 = bn + wn * WTN + (lane & 3) * 2;

#pragma unroll
    for (int mi = 0; mi < MF; mi++) {
#pragma unroll
        for (int ni = 0; ni < NF; ni++) {
            const int col = c0 + ni * 8;
#pragma unroll
            for (int half = 0; half < 2; half++) {
                const int row = r0 + mi * 16 + half * 8;
                float v0 = acc[mi][ni][half * 2]     * scale;
                float v1 = acc[mi][ni][half * 2 + 1] * scale;
                if (bz) { v0 += bz[col]; v1 += bz[col + 1]; }
                if (relu) { v0 = fmaxf(v0, 0.f); v1 = fmaxf(v1, 0.f); }
                if (res) {
                    const float2 rv = *(const float2*)&res[(size_t)row * N + col];
                    v0 += rv.x; v1 += rv.y;
                }
                const size_t o = cz + (size_t)row * N + col;
                if (Cf) { float2 f = {v0, v1}; *(float2*)&Cf[o] = f; }
                if (Chi) {
                    float2 fv; fv.x = v0; fv.y = v1;
                    *(__half2*)&Chi[o] = __float22half2_rn(fv);
                }
            }
        }
    }
}

// ---------------- fused weight fp16 convert (all 6 matrices, native layout) ----
__global__ void k_prep(const float* __restrict__ Wq, const float* __restrict__ Wk,
                       const float* __restrict__ Wv, const float* __restrict__ Wo,
                       const float* __restrict__ W1, const float* __restrict__ W2,
                       __half* __restrict__ wh) {
    const int l = blockIdx.y;
    const size_t i = ((size_t)blockIdx.x * 256 + threadIdx.x) * 8;
    if (i >= LW) return;
    const float* src;
    if (i < 4 * (size_t)EE) {
        const int ty = (int)(i / EE);
        const float* base = (ty == 0) ? Wq : (ty == 1) ? Wk : (ty == 2) ? Wv : Wo;
        src = base + (size_t)l * EE + (i - (size_t)ty * EE);
    } else if (i < (size_t)OFF_2) {
        src = W1 + (size_t)l * EF + (i - OFF_1);
    } else {
        src = W2 + (size_t)l * EF + (i - OFF_2);
    }
    const float4 v0 = *(const float4*)src;
    const float4 v1 = *(const float4*)(src + 4);
    float f[8] = {v0.x, v0.y, v0.z, v0.w, v1.x, v1.y, v1.z, v1.w};
    uint32_t hi[4];
#pragma unroll
    for (int q = 0; q < 4; q++) {
        float2 p; p.x = f[q * 2]; p.y = f[q * 2 + 1];
        const __half2 h2 = __float22half2_rn(p);
        hi[q] = *(const uint32_t*)&h2;
    }
    *(uint4*)(wh + (size_t)l * LW + i) = *(uint4*)hi;
}

// ---------------- pack qkv biases contiguously (all layers) ----------------
__global__ void k_pack3(const float* __restrict__ a, const float* __restrict__ b,
                        const float* __restrict__ c, float* __restrict__ o) {
    const int l = blockIdx.y;
    const int i = blockIdx.x * 256 + threadIdx.x;
    if (i < E) {
        float* ol = o + (size_t)l * 3 * E;
        ol[i] = a[(size_t)l * E + i];
        ol[E + i] = b[(size_t)l * E + i];
        ol[2 * E + i] = c[(size_t)l * E + i];
    }
}

// ---------------- embedding gather ----------------
__global__ void k_embed(const int* __restrict__ x, const float* __restrict__ emb,
                        float* __restrict__ h, __half* __restrict__ hh) {
    const int row = blockIdx.x;
    const int tok = x[row];
    for (int i = threadIdx.x; i < E; i += 256) {
        const float v = emb[(size_t)tok * E + i];
        const size_t o = (size_t)row * E + i;
        h[o] = v;
        hh[o] = __float2half(v);
    }
}

// ---------------- softmax: one warp per row of 512 ----------------
__global__ void k_softmax(__half* __restrict__ sc) {
    const int row = blockIdx.x * 8 + (threadIdx.x >> 5);
    const int lane = threadIdx.x & 31;
    uint4* p = (uint4*)(sc + (size_t)row * S);
    uint4 u[2];
    u[0] = p[lane * 2];
    u[1] = p[lane * 2 + 1];

    float f[16];
#pragma unroll
    for (int j = 0; j < 2; j++) {
        const uint32_t* w = (const uint32_t*)&u[j];
#pragma unroll
        for (int q = 0; q < 4; q++) {
            const float2 fv = __half22float2(*(const __half2*)&w[q]);
            f[j * 8 + q * 2] = fv.x; f[j * 8 + q * 2 + 1] = fv.y;
        }
    }
    float m = f[0];
#pragma unroll
    for (int i = 1; i < 16; i++) m = fmaxf(m, f[i]);
#pragma unroll
    for (int off = 16; off; off >>= 1) m = fmaxf(m, __shfl_xor_sync(~0u, m, off));
    float s = 0.f;
#pragma unroll
    for (int i = 0; i < 16; i++) { f[i] = expf(f[i] - m); s += f[i]; }
#pragma unroll
    for (int off = 16; off; off >>= 1) s += __shfl_xor_sync(~0u, s, off);
    const float inv = 1.0f / s;
#pragma unroll
    for (int j = 0; j < 2; j++) {
        uint32_t* w = (uint32_t*)&u[j];
#pragma unroll
        for (int q = 0; q < 4; q++) {
            float2 fv; fv.x = f[j * 8 + q * 2] * inv; fv.y = f[j * 8 + q * 2 + 1] * inv;
            const __half2 h2 = __float22half2_rn(fv);
            w[q] = *(const uint32_t*)&h2;
        }
    }
    p[lane * 2]     = u[0];
    p[lane * 2 + 1] = u[1];
}

// ---------------- layernorm (fp32 in; fp32 + fp16 out) ----------------
__global__ void k_ln(const float* __restrict__ in, float* __restrict__ out,
                     __half* __restrict__ oh,
                     const float* __restrict__ g, const float* __restrict__ b) {
    __shared__ float s1[8], s2[8];
    const int row = blockIdx.x, t = threadIdx.x;
    const int lane = t & 31, w = t >> 5;
    const float* p = in + (size_t)row * E;

    const float x0 = p[t], x1 = p[t + 256], x2 = p[t + 512];
    float a = x0 + x1 + x2;
    float q = x0 * x0 + x1 * x1 + x2 * x2;
#pragma unroll
    for (int off = 16; off; off >>= 1) {
        a += __shfl_xor_sync(~0u, a, off);
        q += __shfl_xor_sync(~0u, q, off);
    }
    if (lane == 0) { s1[w] = a; s2[w] = q; }
    __syncthreads();
    float ta = 0.f, tq = 0.f;
#pragma unroll
    for (int i = 0; i < 8; i++) { ta += s1[i]; tq += s2[i]; }
    const float mean = ta * (1.0f / E);
    const float var  = tq * (1.0f / E) - mean * mean;
    const float inv  = rsqrtf(var + EPSL);

    const size_t base = (size_t)row * E;
#pragma unroll
    for (int k = 0; k < 3; k++) {
        const int idx = t + k * 256;
        const float xv = (k == 0) ? x0 : (k == 1) ? x1 : x2;
        const float v = (xv - mean) * inv * g[idx] + b[idx];
        out[base + idx] = v;
        oh[base + idx]  = __float2half(v);
    }
}

// ---------------- classifier: partials then reduce ----------------
#define CLS_P 16
#define CLS_CHUNK (SE / CLS_P)
__global__ void k_cls1(const float* __restrict__ h, const float* __restrict__ Wc,
                       float* __restrict__ part) {
    __shared__ float red[256];
    const int bb = blockIdx.x, p = blockIdx.y, t = threadIdx.x;
    const float* hr = h + (size_t)bb * SE;
    float a[CC];
#pragma unroll
    for (int c = 0; c < CC; c++) a[c] = 0.f;
    const int i0 = p * CLS_CHUNK;
    for (int i = i0 + t; i < i0 + CLS_CHUNK; i += 256) {
        const float hv = hr[i];
        const float* w = Wc + (size_t)i * CC;
#pragma unroll
        for (int c = 0; c < CC; c++) a[c] = fmaf(hv, w[c], a[c]);
    }
#pragma unroll
    for (int c = 0; c < CC; c++) {
        red[t] = a[c]; __syncthreads();
        for (int k = 128; k > 0; k >>= 1) {
            if (t < k) red[t] += red[t + k];
            __syncthreads();
        }
        if (t == 0) part[((size_t)bb * CLS_P + p) * CC + c] = red[0];
        __syncthreads();
    }
}
__global__ void k_cls2(const float* __restrict__ part, const float* __restrict__ bc,
                       float* __restrict__ out) {
    const int t = threadIdx.x;
    if (t < B * CC) {
        const int bb = t / CC, c = t % CC;
        float s = bc[c];
        for (int p = 0; p < CLS_P; p++) s += part[((size_t)bb * CLS_P + p) * CC + c];
        out[t] = s;
    }
}

// ---------------- host ----------------
extern "C" void kernel_launch(void* const* d_in, const int* in_sizes, int n_in,
                              void* d_out, int out_size) {
    const int*   x    = (const int*)  d_in[0];
    const float* emb  = (const float*)d_in[1];
    const float* Wq   = (const float*)d_in[2];
    const float* bq   = (const float*)d_in[3];
    const float* Wk   = (const float*)d_in[4];
    const float* bk   = (const float*)d_in[5];
    const float* Wv   = (const float*)d_in[6];
    const float* bv   = (const float*)d_in[7];
    const float* Wo   = (const float*)d_in[8];
    const float* bo   = (const float*)d_in[9];
    const float* ln1g = (const float*)d_in[10];
    const float* ln1b = (const float*)d_in[11];
    const float* W1   = (const float*)d_in[12];
    const float* b1   = (const float*)d_in[13];
    const float* W2   = (const float*)d_in[14];
    const float* b2   = (const float*)d_in[15];
    const float* ln2g = (const float*)d_in[16];
    const float* ln2b = (const float*)d_in[17];
    const float* Wc   = (const float*)d_in[18];
    const float* bc   = (const float*)d_in[19];
    float* out = (float*)d_out;

    float *h, *t, *bqkv;
    __half *hh, *qkv, *ch, *fh, *sc, *wh;
    cudaGetSymbolAddress((void**)&h,   g_h);
    cudaGetSymbolAddress((void**)&t,   g_t);
    cudaGetSymbolAddress((void**)&hh,  g_hh);
    cudaGetSymbolAddress((void**)&qkv, g_qkv);
    cudaGetSymbolAddress((void**)&ch,  g_ch);
    cudaGetSymbolAddress((void**)&fh,  g_fh);
    cudaGetSymbolAddress((void**)&sc,  g_sc);
    cudaGetSymbolAddress((void**)&wh,  g_wh);
    cudaGetSymbolAddress((void**)&bqkv, g_bqkv);

    // smem: 3 stages; A tile 128*80; B tile TB: 32*(BN+8)*2, non-TB: BN*80
    constexpr int SMEM_D = 3 * (128 * 80 + 32 * (128 + 8) * 2); // 56832 (TB BN=128)
    constexpr int SMEM_S = 3 * (128 * 80 + 128 * 80);           // 61440 (non-TB BN=128)
    constexpr int SMEM_C = 3 * (128 * 80 + 32 * (64 + 8) * 2);  // 44544 (TB BN=64)
    cudaFuncSetAttribute(k_mma<128, true>,  cudaFuncAttributeMaxDynamicSharedMemorySize, SMEM_D);
    cudaFuncSetAttribute(k_mma<128, false>, cudaFuncAttributeMaxDynamicSharedMemorySize, SMEM_S);
    cudaFuncSetAttribute(k_mma<64,  true>,  cudaFuncAttributeMaxDynamicSharedMemorySize, SMEM_C);

    __half *qh = qkv, *kh = qkv + (size_t)M4 * E, *vh = qkv + (size_t)2 * M4 * E;

    // launches 1-3: prep, pack3, embed. Launch 4 = QKV GEMM (ncu capture target).
    k_prep<<<dim3(LW / 2048, L), 256>>>(Wq, Wk, Wv, Wo, W1, W2, wh);
    k_pack3<<<dim3(3, L), 256>>>(bq, bk, bv, bqkv);
    k_embed<<<M4, 256>>>(x, emb, h, hh);

    const dim3 gQKV(6, 32, 3);
    const dim3 gEE(6, 32);
    const dim3 gF1(24, 32);
    const dim3 gSc(4, 4, NHEAD);
    const dim3 gCx(1, 4, NHEAD);

    for (int l = 0; l < L; l++) {
        const size_t wb = (size_t)l * LW;

        // fused QKV
        k_mma<128, true><<<gQKV, 256, SMEM_D>>>(hh, wh + wb + OFF_Q,
            bqkv + (size_t)l * 3 * E, nullptr, nullptr, qkv,
            E, E, 0, (size_t)EE, (size_t)M4 * E, E, 1.f, 0);

        // scores = Q K^T / 8, softmax, ctx = P V
        k_mma<128, false><<<gSc, 256, SMEM_S>>>(qh, kh,
            nullptr, nullptr, nullptr, sc,
            S, DH, HSZ, HSZ, (size_t)S * S, 0, 0.125f, 0);
        k_softmax<<<NHEAD * S / 8, 256>>>(sc);
        k_mma<64, true><<<gCx, 256, SMEM_C>>>(sc, vh,
            nullptr, nullptr, nullptr, ch,
            DH, S, (size_t)S * S, HSZ, HSZ, 0, 1.f, 0);

        // Wo + residual -> LN1
        k_mma<128, true><<<gEE, 256, SMEM_D>>>(ch, wh + wb + OFF_O,
            bo + (size_t)l * E, h, t, nullptr,
            E, E, 0, 0, 0, 0, 1.f, 0);
        k_ln<<<M4, 256>>>(t, h, hh, ln1g + (size_t)l * E, ln1b + (size_t)l * E);

        // FFN
        k_mma<128, true><<<gF1, 256, SMEM_D>>>(hh, wh + wb + OFF_1,
            b1 + (size_t)l * FF, nullptr, nullptr, fh,
            FF, E, 0, 0, 0, 0, 1.f, 1);
        k_mma<128, true><<<gEE, 256, SMEM_D>>>(fh, wh + wb + OFF_2,
            b2 + (size_t)l * E, h, t, nullptr,
            E, FF, 0, 0, 0, 0, 1.f, 0);
        k_ln<<<M4, 256>>>(t, h, hh, ln2g + (size_t)l * E, ln2b + (size_t)l * E);
    }

    // classifier (fp32 exact)
    k_cls1<<<dim3(B, CLS_P), 256>>>(h, Wc, t);
    k_cls2<<<1, 128>>>(t, bc, out);
}

// round 9
// speedup vs baseline: 6.6404x; 1.0869x over previous
#include <cuda_runtime.h>
#include <cuda_fp16.h>
#include <cstdint>
#include <math.h>

// ---------------- problem constants ----------------
#define B    8
#define S    512
#define E    768
#define NH   12
#define DH   64
#define FF   3072
#define L    6
#define CC   10
#define M4   (B*S)          // 4096 rows
#define HSZ  (S*DH)         // 32768 per-head elems
#define NHEAD (B*NH)        // 96
#define EPSL 1e-5f
#define SE   (S*E)

// per-layer weight block (elems), native [K,N] layout: Wq,Wk,Wv,Wo,W1,W2
#define EE   (E*E)
#define EF   (E*FF)
#define LW   (4*EE + 2*EF)
#define OFF_Q 0
#define OFF_K EE
#define OFF_V (2*EE)
#define OFF_O (3*EE)
#define OFF_1 (4*EE)
#define OFF_2 (4*EE + EF)

// ---------------- scratch (device globals) ----------------
__device__ float g_h [M4*E];
__device__ float g_t [M4*E];                    // pre-LN buffer; cls partials
__device__ __half g_hh[M4*E];
__device__ __half g_qkv[3*M4*E];
__device__ __half g_ch[M4*E];
__device__ __half g_fh[M4*FF];
__device__ __half g_sc[(size_t)NHEAD*S*S];
__device__ __half g_wh[(size_t)L*LW];
__device__ float g_bqkv[L*3*E];

// ---------------- asm helpers ----------------
__device__ __forceinline__ uint32_t smem_u32(const void* p) {
    uint32_t a;
    asm("{ .reg .u64 t; cvta.to.shared.u64 t, %1; cvt.u32.u64 %0, t; }" : "=r"(a) : "l"(p));
    return a;
}
__device__ __forceinline__ void ldsm4(uint32_t* r, uint32_t a) {
    asm volatile("ldmatrix.sync.aligned.m8n8.x4.shared.b16 {%0,%1,%2,%3}, [%4];"
        : "=r"(r[0]), "=r"(r[1]), "=r"(r[2]), "=r"(r[3]) : "r"(a));
}
__device__ __forceinline__ void ldsm4t(uint32_t* r, uint32_t a) {
    asm volatile("ldmatrix.sync.aligned.m8n8.x4.trans.shared.b16 {%0,%1,%2,%3}, [%4];"
        : "=r"(r[0]), "=r"(r[1]), "=r"(r[2]), "=r"(r[3]) : "r"(a));
}
__device__ __forceinline__ void mma_f16(float* c, const uint32_t* a, const uint32_t* b) {
    asm volatile("mma.sync.aligned.m16n8k16.row.col.f32.f16.f16.f32 "
        "{%0,%1,%2,%3}, {%4,%5,%6,%7}, {%8,%9}, {%0,%1,%2,%3};"
        : "+f"(c[0]), "+f"(c[1]), "+f"(c[2]), "+f"(c[3])
        : "r"(a[0]), "r"(a[1]), "r"(a[2]), "r"(a[3]), "r"(b[0]), "r"(b[1]));
}
#define CPA(dst, src) asm volatile("cp.async.cg.shared.global [%0], [%1], 16;" :: "r"(dst), "l"(src))
#define CPC() asm volatile("cp.async.commit_group;" ::: "memory")
#define CPW(n) asm volatile("cp.async.wait_group %0;" :: "n"(n) : "memory")

// ================= HMMA GEMM (fp16 in, fp32 accum) =================
// D[row,col] = scale*sum_k A[row,k]*B(col,k) (+bias)(relu)(+res)
// TB=false: B stored [N,K]. TB=true: B stored [K,N] (ldmatrix.trans).
// BM in {128,64}; BK=32; 256 threads; 4-stage cp.async ring (prefetch dist 2),
// ONE __syncthreads per kt. BM=128 -> 2 CTAs/SM; BM=64 -> 3 CTAs/SM.
// Warp layout: WM = BM/32 warps on M (WTM=32), WN = 8/WM on N.
template<int BM, int BN, bool TB>
__global__ void __launch_bounds__(256, (BM == 128) ? 2 : 3)
k_mma(const __half* __restrict__ Ah, const __half* __restrict__ Bh,
      const float* __restrict__ bias, const float* __restrict__ res,
      float* __restrict__ Cf, __half* __restrict__ Chi,
      int N, int K, size_t sAz, size_t sBz, size_t sCz, size_t bsz,
      float scale, int relu) {
    extern __shared__ char sm[];
    constexpr int WM  = BM / 32;               // 4 or 2
    constexpr int WN  = 8 / WM;                // 2 or 4
    constexpr int WTN = BN / WN;               // 64 / 32 / 16
    constexpr int MF  = 2;                     // WTM = 32
    constexpr int NF  = WTN / 8;               // 8 / 4 / 2
    constexpr int ATILE  = BM * 80;
    constexpr int BPITCH = TB ? (BN + 8) * 2 : 80;
    constexpr int BTILE  = TB ? 32 * BPITCH : BN * 80;
    constexpr int STAGE  = ATILE + BTILE;

    const uint32_t smb = smem_u32(sm);
    const int tid = threadIdx.x, lane = tid & 31, wid = tid >> 5;
    const int wm = wid / WN, wn = wid % WN;
    const int bm = blockIdx.y * BM, bn = blockIdx.x * BN;
    const size_t zA = (size_t)blockIdx.z * sAz, zB = (size_t)blockIdx.z * sBz;
    const __half* pA = Ah + zA + (size_t)bm * K;
    const __half* pB = TB ? Bh + zB : Bh + zB + (size_t)bn * K;

    float acc[MF][NF][4];
#pragma unroll
    for (int i = 0; i < MF; i++)
#pragma unroll
        for (int j = 0; j < NF; j++)
#pragma unroll
            for (int q = 0; q < 4; q++) acc[i][j][q] = 0.f;

    const uint32_t a_off = (uint32_t)(lane & 15) * 80 + (uint32_t)(lane >> 4) * 16;
    const uint32_t b_off = TB
        ? (uint32_t)(lane & 15) * BPITCH + (uint32_t)(lane >> 4) * 16
        : (uint32_t)((lane & 7) + ((lane >> 1) & 8)) * 80 + (uint32_t)((lane >> 3) & 1) * 16;

    const int KT = K >> 5;

    auto load_stage = [&](int s, int kt) {
        const int k0 = kt << 5;
        const uint32_t base = smb + s * STAGE;
#pragma unroll 2
        for (int cid = tid; cid < BM * 4; cid += 256) {
            const int row = cid >> 2, p = cid & 3;
            CPA(base + row * 80 + p * 16, pA + (size_t)row * K + k0 + p * 8);
        }
        if (TB) {
#pragma unroll 2
            for (int cid = tid; cid < 32 * (BN / 8); cid += 256) {
                const int row = cid / (BN / 8), c = cid % (BN / 8);
                CPA(base + ATILE + row * BPITCH + c * 16,
                    pB + (size_t)(k0 + row) * N + bn + c * 8);
            }
        } else {
#pragma unroll 2
            for (int cid = tid; cid < BN * 4; cid += 256) {
                const int row = cid >> 2, p = cid & 3;
                CPA(base + ATILE + row * 80 + p * 16, pB + (size_t)row * K + k0 + p * 8);
            }
        }
    };

    load_stage(0, 0); CPC();
    if (KT > 1) { load_stage(1, 1); CPC(); }

    for (int kt = 0; kt < KT; ++kt) {
        const int stg = kt & 3;
        if (kt + 2 < KT) { load_stage((kt + 2) & 3, kt + 2); CPC(); CPW(2); }
        else if (kt + 1 < KT) CPW(1);
        else CPW(0);
        __syncthreads();

        const uint32_t stageB = smb + stg * STAGE;
        const uint32_t aB = stageB + wm * 32 * 80 + a_off;
        const uint32_t bB = TB ? stageB + ATILE + wn * WTN * 2 + b_off
                               : stageB + ATILE + wn * WTN * 80 + b_off;
#pragma unroll
        for (int ks = 0; ks < 2; ++ks) {
            uint32_t aR[MF][4], bR[(NF + 1) / 2][4];
#pragma unroll
            for (int n2 = 0; n2 < NF / 2; n2++) {
                const uint32_t ad = TB ? bB + ks * 16 * BPITCH + n2 * 32
                                       : bB + n2 * 16 * 80 + ks * 32;
                if (TB) ldsm4t(bR[n2], ad); else ldsm4(bR[n2], ad);
            }
#pragma unroll
            for (int mi = 0; mi < MF; mi++)
                ldsm4(aR[mi], aB + mi * 16 * 80 + ks * 32);

#pragma unroll
            for (int mi = 0; mi < MF; mi++)
#pragma unroll
                for (int n2 = 0; n2 < NF / 2; n2++) {
                    mma_f16(acc[mi][n2 * 2],     aR[mi], &bR[n2][0]);
                    mma_f16(acc[mi][n2 * 2 + 1], aR[mi], &bR[n2][2]);
                }
        }
        // single barrier per kt: next iteration's loads target (kt+3)&3, which is
        // not read until kt+3; stage (kt+2)&3 written above was last read at kt-2,
        // and every warp has crossed the kt-1 barrier since then.
    }

    // ---- epilogue ----
    const size_t cz = (size_t)blockIdx.z * sCz;
    const float* bz = bias ? bias + (size_t)blockIdx.z * bsz : nullptr;
    const int r0 = bm + wm * 32 + (lane >> 2);
    const int c0 = bn + wn * WTN + (lane & 3) * 2;

#pragma unroll
    for (int mi = 0; mi < MF; mi++) {
#pragma unroll
        for (int ni = 0; ni < NF; ni++) {
            const int col = c0 + ni * 8;
#pragma unroll
            for (int half = 0; half < 2; half++) {
                const int row = r0 + mi * 16 + half * 8;
                float v0 = acc[mi][ni][half * 2]     * scale;
                float v1 = acc[mi][ni][half * 2 + 1] * scale;
                if (bz) { v0 += bz[col]; v1 += bz[col + 1]; }
                if (relu) { v0 = fmaxf(v0, 0.f); v1 = fmaxf(v1, 0.f); }
                if (res) {
                    const float2 rv = *(const float2*)&res[(size_t)row * N + col];
                    v0 += rv.x; v1 += rv.y;
                }
                const size_t o = cz + (size_t)row * N + col;
                if (Cf) { float2 f = {v0, v1}; *(float2*)&Cf[o] = f; }
                if (Chi) {
                    float2 fv; fv.x = v0; fv.y = v1;
                    *(__half2*)&Chi[o] = __float22half2_rn(fv);
                }
            }
        }
    }
}

// ---------------- fused weight fp16 convert (all 6 matrices, native layout) ----
__global__ void k_prep(const float* __restrict__ Wq, const float* __restrict__ Wk,
                       const float* __restrict__ Wv, const float* __restrict__ Wo,
                       const float* __restrict__ W1, const float* __restrict__ W2,
                       __half* __restrict__ wh) {
    const int l = blockIdx.y;
    const size_t i = ((size_t)blockIdx.x * 256 + threadIdx.x) * 8;
    if (i >= LW) return;
    const float* src;
    if (i < 4 * (size_t)EE) {
        const int ty = (int)(i / EE);
        const float* base = (ty == 0) ? Wq : (ty == 1) ? Wk : (ty == 2) ? Wv : Wo;
        src = base + (size_t)l * EE + (i - (size_t)ty * EE);
    } else if (i < (size_t)OFF_2) {
        src = W1 + (size_t)l * EF + (i - OFF_1);
    } else {
        src = W2 + (size_t)l * EF + (i - OFF_2);
    }
    const float4 v0 = *(const float4*)src;
    const float4 v1 = *(const float4*)(src + 4);
    float f[8] = {v0.x, v0.y, v0.z, v0.w, v1.x, v1.y, v1.z, v1.w};
    uint32_t hi[4];
#pragma unroll
    for (int q = 0; q < 4; q++) {
        float2 p; p.x = f[q * 2]; p.y = f[q * 2 + 1];
        const __half2 h2 = __float22half2_rn(p);
        hi[q] = *(const uint32_t*)&h2;
    }
    *(uint4*)(wh + (size_t)l * LW + i) = *(uint4*)hi;
}

// ---------------- pack qkv biases contiguously (all layers) ----------------
__global__ void k_pack3(const float* __restrict__ a, const float* __restrict__ b,
                        const float* __restrict__ c, float* __restrict__ o) {
    const int l = blockIdx.y;
    const int i = blockIdx.x * 256 + threadIdx.x;
    if (i < E) {
        float* ol = o + (size_t)l * 3 * E;
        ol[i] = a[(size_t)l * E + i];
        ol[E + i] = b[(size_t)l * E + i];
        ol[2 * E + i] = c[(size_t)l * E + i];
    }
}

// ---------------- embedding gather ----------------
__global__ void k_embed(const int* __restrict__ x, const float* __restrict__ emb,
                        float* __restrict__ h, __half* __restrict__ hh) {
    const int row = blockIdx.x;
    const int tok = x[row];
    for (int i = threadIdx.x; i < E; i += 256) {
        const float v = emb[(size_t)tok * E + i];
        const size_t o = (size_t)row * E + i;
        h[o] = v;
        hh[o] = __float2half(v);
    }
}

// ---------------- softmax: one warp per row of 512 ----------------
__global__ void k_softmax(__half* __restrict__ sc) {
    const int row = blockIdx.x * 8 + (threadIdx.x >> 5);
    const int lane = threadIdx.x & 31;
    uint4* p = (uint4*)(sc + (size_t)row * S);
    uint4 u[2];
    u[0] = p[lane * 2];
    u[1] = p[lane * 2 + 1];

    float f[16];
#pragma unroll
    for (int j = 0; j < 2; j++) {
        const uint32_t* w = (const uint32_t*)&u[j];
#pragma unroll
        for (int q = 0; q < 4; q++) {
            const float2 fv = __half22float2(*(const __half2*)&w[q]);
            f[j * 8 + q * 2] = fv.x; f[j * 8 + q * 2 + 1] = fv.y;
        }
    }
    float m = f[0];
#pragma unroll
    for (int i = 1; i < 16; i++) m = fmaxf(m, f[i]);
#pragma unroll
    for (int off = 16; off; off >>= 1) m = fmaxf(m, __shfl_xor_sync(~0u, m, off));
    float s = 0.f;
#pragma unroll
    for (int i = 0; i < 16; i++) { f[i] = expf(f[i] - m); s += f[i]; }
#pragma unroll
    for (int off = 16; off; off >>= 1) s += __shfl_xor_sync(~0u, s, off);
    const float inv = 1.0f / s;
#pragma unroll
    for (int j = 0; j < 2; j++) {
        uint32_t* w = (uint32_t*)&u[j];
#pragma unroll
        for (int q = 0; q < 4; q++) {
            float2 fv; fv.x = f[j * 8 + q * 2] * inv; fv.y = f[j * 8 + q * 2 + 1] * inv;
            const __half2 h2 = __float22half2_rn(fv);
            w[q] = *(const uint32_t*)&h2;
        }
    }
    p[lane * 2]     = u[0];
    p[lane * 2 + 1] = u[1];
}

// ---------------- layernorm (fp32 in; fp32 + fp16 out) ----------------
__global__ void k_ln(const float* __restrict__ in, float* __restrict__ out,
                     __half* __restrict__ oh,
                     const float* __restrict__ g, const float* __restrict__ b) {
    __shared__ float s1[8], s2[8];
    const int row = blockIdx.x, t = threadIdx.x;
    const int lane = t & 31, w = t >> 5;
    const float* p = in + (size_t)row * E;

    const float x0 = p[t], x1 = p[t + 256], x2 = p[t + 512];
    float a = x0 + x1 + x2;
    float q = x0 * x0 + x1 * x1 + x2 * x2;
#pragma unroll
    for (int off = 16; off; off >>= 1) {
        a += __shfl_xor_sync(~0u, a, off);
        q += __shfl_xor_sync(~0u, q, off);
    }
    if (lane == 0) { s1[w] = a; s2[w] = q; }
    __syncthreads();
    float ta = 0.f, tq = 0.f;
#pragma unroll
    for (int i = 0; i < 8; i++) { ta += s1[i]; tq += s2[i]; }
    const float mean = ta * (1.0f / E);
    const float var  = tq * (1.0f / E) - mean * mean;
    const float inv  = rsqrtf(var + EPSL);

    const size_t base = (size_t)row * E;
#pragma unroll
    for (int k = 0; k < 3; k++) {
        const int idx = t + k * 256;
        const float xv = (k == 0) ? x0 : (k == 1) ? x1 : x2;
        const float v = (xv - mean) * inv * g[idx] + b[idx];
        out[base + idx] = v;
        oh[base + idx]  = __float2half(v);
    }
}

// ---------------- classifier: partials then reduce ----------------
#define CLS_P 16
#define CLS_CHUNK (SE / CLS_P)
__global__ void k_cls1(const float* __restrict__ h, const float* __restrict__ Wc,
                       float* __restrict__ part) {
    __shared__ float red[256];
    const int bb = blockIdx.x, p = blockIdx.y, t = threadIdx.x;
    const float* hr = h + (size_t)bb * SE;
    float a[CC];
#pragma unroll
    for (int c = 0; c < CC; c++) a[c] = 0.f;
    const int i0 = p * CLS_CHUNK;
    for (int i = i0 + t; i < i0 + CLS_CHUNK; i += 256) {
        const float hv = hr[i];
        const float* w = Wc + (size_t)i * CC;
#pragma unroll
        for (int c = 0; c < CC; c++) a[c] = fmaf(hv, w[c], a[c]);
    }
#pragma unroll
    for (int c = 0; c < CC; c++) {
        red[t] = a[c]; __syncthreads();
        for (int k = 128; k > 0; k >>= 1) {
            if (t < k) red[t] += red[t + k];
            __syncthreads();
        }
        if (t == 0) part[((size_t)bb * CLS_P + p) * CC + c] = red[0];
        __syncthreads();
    }
}
__global__ void k_cls2(const float* __restrict__ part, const float* __restrict__ bc,
                       float* __restrict__ out) {
    const int t = threadIdx.x;
    if (t < B * CC) {
        const int bb = t / CC, c = t % CC;
        float s = bc[c];
        for (int p = 0; p < CLS_P; p++) s += part[((size_t)bb * CLS_P + p) * CC + c];
        out[t] = s;
    }
}

// ---------------- host ----------------
extern "C" void kernel_launch(void* const* d_in, const int* in_sizes, int n_in,
                              void* d_out, int out_size) {
    const int*   x    = (const int*)  d_in[0];
    const float* emb  = (const float*)d_in[1];
    const float* Wq   = (const float*)d_in[2];
    const float* bq   = (const float*)d_in[3];
    const float* Wk   = (const float*)d_in[4];
    const float* bk   = (const float*)d_in[5];
    const float* Wv   = (const float*)d_in[6];
    const float* bv   = (const float*)d_in[7];
    const float* Wo   = (const float*)d_in[8];
    const float* bo   = (const float*)d_in[9];
    const float* ln1g = (const float*)d_in[10];
    const float* ln1b = (const float*)d_in[11];
    const float* W1   = (const float*)d_in[12];
    const float* b1   = (const float*)d_in[13];
    const float* W2   = (const float*)d_in[14];
    const float* b2   = (const float*)d_in[15];
    const float* ln2g = (const float*)d_in[16];
    const float* ln2b = (const float*)d_in[17];
    const float* Wc   = (const float*)d_in[18];
    const float* bc   = (const float*)d_in[19];
    float* out = (float*)d_out;

    float *h, *t, *bqkv;
    __half *hh, *qkv, *ch, *fh, *sc, *wh;
    cudaGetSymbolAddress((void**)&h,   g_h);
    cudaGetSymbolAddress((void**)&t,   g_t);
    cudaGetSymbolAddress((void**)&hh,  g_hh);
    cudaGetSymbolAddress((void**)&qkv, g_qkv);
    cudaGetSymbolAddress((void**)&ch,  g_ch);
    cudaGetSymbolAddress((void**)&fh,  g_fh);
    cudaGetSymbolAddress((void**)&sc,  g_sc);
    cudaGetSymbolAddress((void**)&wh,  g_wh);
    cudaGetSymbolAddress((void**)&bqkv, g_bqkv);

    // smem: 4 stages
    constexpr int SMEM_QKV = 4 * (128 * 80 + 32 * (128 + 8) * 2); // 75776
    constexpr int SMEM_SC  = 4 * (128 * 80 + 128 * 80);           // 81920
    constexpr int SMEM_W   = 4 * (64 * 80 + 32 * (128 + 8) * 2);  // 55296
    constexpr int SMEM_CX  = 4 * (64 * 80 + 32 * (64 + 8) * 2);   // 38912
    cudaFuncSetAttribute(k_mma<128, 128, true>,  cudaFuncAttributeMaxDynamicSharedMemorySize, SMEM_QKV);
    cudaFuncSetAttribute(k_mma<128, 128, false>, cudaFuncAttributeMaxDynamicSharedMemorySize, SMEM_SC);
    cudaFuncSetAttribute(k_mma<64, 128, true>,   cudaFuncAttributeMaxDynamicSharedMemorySize, SMEM_W);
    cudaFuncSetAttribute(k_mma<64, 64, true>,    cudaFuncAttributeMaxDynamicSharedMemorySize, SMEM_CX);

    __half *qh = qkv, *kh = qkv + (size_t)M4 * E, *vh = qkv + (size_t)2 * M4 * E;

    // launches 1-3: prep, pack3, embed. Launch 4 = QKV GEMM (ncu capture target).
    k_prep<<<dim3(LW / 2048, L), 256>>>(Wq, Wk, Wv, Wo, W1, W2, wh);
    k_pack3<<<dim3(3, L), 256>>>(bq, bk, bv, bqkv);
    k_embed<<<M4, 256>>>(x, emb, h, hh);

    const dim3 gQKV(6, 32, 3);     // BM=128
    const dim3 gEE64(6, 64);       // BM=64: Wo, FF2
    const dim3 gF164(24, 64);      // BM=64: FF1
    const dim3 gSc(4, 4, NHEAD);   // BM=128, non-TB
    const dim3 gCx(1, 8, NHEAD);   // BM=64, BN=64

    for (int l = 0; l < L; l++) {
        const size_t wb = (size_t)l * LW;

        // fused QKV
        k_mma<128, 128, true><<<gQKV, 256, SMEM_QKV>>>(hh, wh + wb + OFF_Q,
            bqkv + (size_t)l * 3 * E, nullptr, nullptr, qkv,
            E, E, 0, (size_t)EE, (size_t)M4 * E, E, 1.f, 0);

        // scores = Q K^T / 8, softmax, ctx = P V
        k_mma<128, 128, false><<<gSc, 256, SMEM_SC>>>(qh, kh,
            nullptr, nullptr, nullptr, sc,
            S, DH, HSZ, HSZ, (size_t)S * S, 0, 0.125f, 0);
        k_softmax<<<NHEAD * S / 8, 256>>>(sc);
        k_mma<64, 64, true><<<gCx, 256, SMEM_CX>>>(sc, vh,
            nullptr, nullptr, nullptr, ch,
            DH, S, (size_t)S * S, HSZ, HSZ, 0, 1.f, 0);

        // Wo + residual -> LN1
        k_mma<64, 128, true><<<gEE64, 256, SMEM_W>>>(ch, wh + wb + OFF_O,
            bo + (size_t)l * E, h, t, nullptr,
            E, E, 0, 0, 0, 0, 1.f, 0);
        k_ln<<<M4, 256>>>(t, h, hh, ln1g + (size_t)l * E, ln1b + (size_t)l * E);

        // FFN
        k_mma<64, 128, true><<<gF164, 256, SMEM_W>>>(hh, wh + wb + OFF_1,
            b1 + (size_t)l * FF, nullptr, nullptr, fh,
            FF, E, 0, 0, 0, 0, 1.f, 1);
        k_mma<64, 128, true><<<gEE64, 256, SMEM_W>>>(fh, wh + wb + OFF_2,
            b2 + (size_t)l * E, h, t, nullptr,
            E, FF, 0, 0, 0, 0, 1.f, 0);
        k_ln<<<M4, 256>>>(t, h, hh, ln2g + (size_t)l * E, ln2b + (size_t)l * E);
    }

    // classifier (fp32 exact)
    k_cls1<<<dim3(B, CLS_P), 256>>>(h, Wc, t);
    k_cls2<<<1, 128>>>(t, bc, out);
}

// round 10
// speedup vs baseline: 7.4112x; 1.1161x over previous
#include <cuda_runtime.h>
#include <cuda_fp16.h>
#include <cstdint>
#include <math.h>

// ---------------- problem constants ----------------
#define B    8
#define S    512
#define E    768
#define NH   12
#define DH   64
#define FF   3072
#define L    6
#define CC   10
#define M4   (B*S)          // 4096 rows
#define HSZ  (S*DH)         // 32768 per-head elems
#define NHEAD (B*NH)        // 96
#define EPSL 1e-5f
#define SE   (S*E)

// per-layer weight block (elems), native [K,N] layout: Wq,Wk,Wv,Wo,W1,W2
#define EE   (E*E)
#define EF   (E*FF)
#define LW   (4*EE + 2*EF)
#define OFF_Q 0
#define OFF_K EE
#define OFF_V (2*EE)
#define OFF_O (3*EE)
#define OFF_1 (4*EE)
#define OFF_2 (4*EE + EF)

// ---------------- scratch (device globals) ----------------
__device__ float g_h [M4*E];
__device__ float g_t [M4*E];                    // pre-LN buffer; cls partials
__device__ __half g_hh[M4*E];
__device__ __half g_qkv[3*M4*E];
__device__ __half g_ch[M4*E];
__device__ __half g_fh[M4*FF];
__device__ __half g_wh[(size_t)L*LW];
__device__ float g_bqkv[L*3*E];

// ---------------- asm helpers ----------------
__device__ __forceinline__ uint32_t smem_u32(const void* p) {
    uint32_t a;
    asm("{ .reg .u64 t; cvta.to.shared.u64 t, %1; cvt.u32.u64 %0, t; }" : "=r"(a) : "l"(p));
    return a;
}
__device__ __forceinline__ void ldsm4(uint32_t* r, uint32_t a) {
    asm volatile("ldmatrix.sync.aligned.m8n8.x4.shared.b16 {%0,%1,%2,%3}, [%4];"
        : "=r"(r[0]), "=r"(r[1]), "=r"(r[2]), "=r"(r[3]) : "r"(a));
}
__device__ __forceinline__ void ldsm4t(uint32_t* r, uint32_t a) {
    asm volatile("ldmatrix.sync.aligned.m8n8.x4.trans.shared.b16 {%0,%1,%2,%3}, [%4];"
        : "=r"(r[0]), "=r"(r[1]), "=r"(r[2]), "=r"(r[3]) : "r"(a));
}
__device__ __forceinline__ void mma_f16(float* c, const uint32_t* a, const uint32_t* b) {
    asm volatile("mma.sync.aligned.m16n8k16.row.col.f32.f16.f16.f32 "
        "{%0,%1,%2,%3}, {%4,%5,%6,%7}, {%8,%9}, {%0,%1,%2,%3};"
        : "+f"(c[0]), "+f"(c[1]), "+f"(c[2]), "+f"(c[3])
        : "r"(a[0]), "r"(a[1]), "r"(a[2]), "r"(a[3]), "r"(b[0]), "r"(b[1]));
}
__device__ __forceinline__ float ex2(float x) {
    float r;
    asm("ex2.approx.f32 %0, %1;" : "=f"(r) : "f"(x));
    return r;
}
#define CPA(dst, src) asm volatile("cp.async.cg.shared.global [%0], [%1], 16;" :: "r"(dst), "l"(src))
#define CPC() asm volatile("cp.async.commit_group;" ::: "memory")
#define CPW(n) asm volatile("cp.async.wait_group %0;" :: "n"(n) : "memory")

// ================= HMMA GEMM (fp16 in, fp32 accum) =================
// D[row,col] = scale*sum_k A[row,k]*B(col,k) (+bias)(relu)(+res); B stored [K,N] (trans).
// BM in {128,64}; BK=32; 256 threads; 4-stage cp.async ring, one barrier per kt.
template<int BM, int BN>
__global__ void __launch_bounds__(256, (BM == 128) ? 2 : 3)
k_mma(const __half* __restrict__ Ah, const __half* __restrict__ Bh,
      const float* __restrict__ bias, const float* __restrict__ res,
      float* __restrict__ Cf, __half* __restrict__ Chi,
      int N, int K, size_t sAz, size_t sBz, size_t sCz, size_t bsz,
      float scale, int relu) {
    extern __shared__ char sm[];
    constexpr int WM  = BM / 32;
    constexpr int WN  = 8 / WM;
    constexpr int WTN = BN / WN;
    constexpr int MF  = 2;
    constexpr int NF  = WTN / 8;
    constexpr int ATILE  = BM * 80;
    constexpr int BPITCH = (BN + 8) * 2;
    constexpr int BTILE  = 32 * BPITCH;
    constexpr int STAGE  = ATILE + BTILE;

    const uint32_t smb = smem_u32(sm);
    const int tid = threadIdx.x, lane = tid & 31, wid = tid >> 5;
    const int wm = wid / WN, wn = wid % WN;
    const int bm = blockIdx.y * BM, bn = blockIdx.x * BN;
    const size_t zA = (size_t)blockIdx.z * sAz, zB = (size_t)blockIdx.z * sBz;
    const __half* pA = Ah + zA + (size_t)bm * K;
    const __half* pB = Bh + zB;

    float acc[MF][NF][4];
#pragma unroll
    for (int i = 0; i < MF; i++)
#pragma unroll
        for (int j = 0; j < NF; j++)
#pragma unroll
            for (int q = 0; q < 4; q++) acc[i][j][q] = 0.f;

    const uint32_t a_off = (uint32_t)(lane & 15) * 80 + (uint32_t)(lane >> 4) * 16;
    const uint32_t b_off = (uint32_t)(lane & 15) * BPITCH + (uint32_t)(lane >> 4) * 16;

    const int KT = K >> 5;

    auto load_stage = [&](int s, int kt) {
        const int k0 = kt << 5;
        const uint32_t base = smb + s * STAGE;
#pragma unroll 2
        for (int cid = tid; cid < BM * 4; cid += 256) {
            const int row = cid >> 2, p = cid & 3;
            CPA(base + row * 80 + p * 16, pA + (size_t)row * K + k0 + p * 8);
        }
#pragma unroll 2
        for (int cid = tid; cid < 32 * (BN / 8); cid += 256) {
            const int row = cid / (BN / 8), c = cid % (BN / 8);
            CPA(base + ATILE + row * BPITCH + c * 16,
                pB + (size_t)(k0 + row) * N + bn + c * 8);
        }
    };

    load_stage(0, 0); CPC();
    if (KT > 1) { load_stage(1, 1); CPC(); }

    for (int kt = 0; kt < KT; ++kt) {
        const int stg = kt & 3;
        if (kt + 2 < KT) { load_stage((kt + 2) & 3, kt + 2); CPC(); CPW(2); }
        else if (kt + 1 < KT) CPW(1);
        else CPW(0);
        __syncthreads();

        const uint32_t stageB = smb + stg * STAGE;
        const uint32_t aB = stageB + wm * 32 * 80 + a_off;
        const uint32_t bB = stageB + ATILE + wn * WTN * 2 + b_off;
#pragma unroll
        for (int ks = 0; ks < 2; ++ks) {
            uint32_t aR[MF][4], bR[(NF + 1) / 2][4];
#pragma unroll
            for (int n2 = 0; n2 < NF / 2; n2++)
                ldsm4t(bR[n2], bB + ks * 16 * BPITCH + n2 * 32);
#pragma unroll
            for (int mi = 0; mi < MF; mi++)
                ldsm4(aR[mi], aB + mi * 16 * 80 + ks * 32);

#pragma unroll
            for (int mi = 0; mi < MF; mi++)
#pragma unroll
                for (int n2 = 0; n2 < NF / 2; n2++) {
                    mma_f16(acc[mi][n2 * 2],     aR[mi], &bR[n2][0]);
                    mma_f16(acc[mi][n2 * 2 + 1], aR[mi], &bR[n2][2]);
                }
        }
    }

    // ---- epilogue ----
    const size_t cz = (size_t)blockIdx.z * sCz;
    const float* bz = bias ? bias + (size_t)blockIdx.z * bsz : nullptr;
    const int r0 = bm + wm * 32 + (lane >> 2);
    const int c0 = bn + wn * WTN + (lane & 3) * 2;

#pragma unroll
    for (int mi = 0; mi < MF; mi++) {
#pragma unroll
        for (int ni = 0; ni < NF; ni++) {
            const int col = c0 + ni * 8;
#pragma unroll
            for (int half = 0; half < 2; half++) {
                const int row = r0 + mi * 16 + half * 8;
                float v0 = acc[mi][ni][half * 2]     * scale;
                float v1 = acc[mi][ni][half * 2 + 1] * scale;
                if (bz) { v0 += bz[col]; v1 += bz[col + 1]; }
                if (relu) { v0 = fmaxf(v0, 0.f); v1 = fmaxf(v1, 0.f); }
                if (res) {
                    const float2 rv = *(const float2*)&res[(size_t)row * N + col];
                    v0 += rv.x; v1 += rv.y;
                }
                const size_t o = cz + (size_t)row * N + col;
                if (Cf) { float2 f = {v0, v1}; *(float2*)&Cf[o] = f; }
                if (Chi) {
                    float2 fv; fv.x = v0; fv.y = v1;
                    *(__half2*)&Chi[o] = __float22half2_rn(fv);
                }
            }
        }
    }
}

// ================= fused attention (FlashAttention-2 style) =================
// grid (4, 96): blockIdx.x = 128-row Q block, blockIdx.y = head. 8 warps, 16 Q rows/warp.
// S = Q K^T * 1/8 (fp32 acc), online softmax (exp2 domain), O += P V, out = O/l (fp16).
#define APITCH 144           // (64+8)*2 bytes per row
#define QBYTES (128*APITCH)  // 18432
#define TBYTES (64*APITCH)   // 9216
#define AT_SMEM (QBYTES + 4*TBYTES)  // Q + 2xK + 2xV = 55296
#define C_EXP2 0.18033688011112042f  // 0.125 * log2(e)

__global__ void __launch_bounds__(256, 2)
k_attn(const __half* __restrict__ q, const __half* __restrict__ k,
       const __half* __restrict__ v, __half* __restrict__ och) {
    extern __shared__ char sm[];
    const uint32_t smb = smem_u32(sm);
    const uint32_t KOFF = QBYTES, VOFF = QBYTES + 2 * TBYTES;
    const int tid = threadIdx.x, lane = tid & 31, w = tid >> 5;
    const int z = blockIdx.y, qb = blockIdx.x;
    const __half* pQ = q + (size_t)z * HSZ + (size_t)qb * 128 * DH;
    const __half* pK = k + (size_t)z * HSZ;
    const __half* pV = v + (size_t)z * HSZ;

    const uint32_t a_off  = (uint32_t)(lane & 15) * APITCH + (uint32_t)(lane >> 4) * 16;
    const uint32_t bs_off = (uint32_t)((lane & 7) + ((lane >> 1) & 8)) * APITCH
                          + (uint32_t)((lane >> 3) & 1) * 16;   // K (non-trans B)
    const uint32_t bt_off = a_off;                              // V (trans B)

    // loaders
    auto loadQ = [&]() {
#pragma unroll
        for (int cid = tid; cid < 1024; cid += 256) {
            const int row = cid >> 3, p = cid & 7;
            CPA(smb + row * APITCH + p * 16, pQ + (size_t)row * DH + p * 8);
        }
    };
    auto loadKV = [&](int t) {
        const uint32_t kb = smb + KOFF + (t & 1) * TBYTES;
        const uint32_t vb = smb + VOFF + (t & 1) * TBYTES;
        const __half* sk = pK + (size_t)t * 64 * DH;
        const __half* sv = pV + (size_t)t * 64 * DH;
#pragma unroll
        for (int cid = tid; cid < 512; cid += 256) {
            const int row = cid >> 3, p = cid & 7;
            CPA(kb + row * APITCH + p * 16, sk + (size_t)row * DH + p * 8);
            CPA(vb + row * APITCH + p * 16, sv + (size_t)row * DH + p * 8);
        }
    };

    loadQ(); loadKV(0); CPC();

    uint32_t qf[4][4];
    float oacc[8][4];
#pragma unroll
    for (int j = 0; j < 8; j++)
#pragma unroll
        for (int qq = 0; qq < 4; qq++) oacc[j][qq] = 0.f;
    float m0 = -1e30f, m1 = -1e30f, l0 = 0.f, l1 = 0.f;

    for (int t = 0; t < 8; ++t) {
        if (t + 1 < 8) { loadKV(t + 1); CPC(); CPW(1); }
        else CPW(0);
        __syncthreads();

        if (t == 0) {
            const uint32_t qbase = smb + w * 16 * APITCH + a_off;
#pragma unroll
            for (int kc = 0; kc < 4; kc++) ldsm4(qf[kc], qbase + kc * 32);
        }

        // ---- S = Q K^T ----
        const uint32_t kbase = smb + KOFF + (t & 1) * TBYTES;
        float sacc[8][4];
#pragma unroll
        for (int j = 0; j < 8; j++)
#pragma unroll
            for (int qq = 0; qq < 4; qq++) sacc[j][qq] = 0.f;
#pragma unroll
        for (int kc = 0; kc < 4; kc++) {
#pragma unroll
            for (int n2 = 0; n2 < 4; n2++) {
                uint32_t kb[4];
                ldsm4(kb, kbase + n2 * 16 * APITCH + kc * 32 + bs_off);
                mma_f16(sacc[n2 * 2],     qf[kc], &kb[0]);
                mma_f16(sacc[n2 * 2 + 1], qf[kc], &kb[2]);
            }
        }

        // ---- online softmax (exp2 domain) ----
        float mt0 = -1e30f, mt1 = -1e30f;
#pragma unroll
        for (int j = 0; j < 8; j++) {
#pragma unroll
            for (int qq = 0; qq < 4; qq++) sacc[j][qq] *= C_EXP2;
            mt0 = fmaxf(mt0, fmaxf(sacc[j][0], sacc[j][1]));
            mt1 = fmaxf(mt1, fmaxf(sacc[j][2], sacc[j][3]));
        }
#pragma unroll
        for (int off = 1; off <= 2; off <<= 1) {
            mt0 = fmaxf(mt0, __shfl_xor_sync(~0u, mt0, off));
            mt1 = fmaxf(mt1, __shfl_xor_sync(~0u, mt1, off));
        }
        const float mn0 = fmaxf(m0, mt0), mn1 = fmaxf(m1, mt1);
        const float al0 = ex2(m0 - mn0), al1 = ex2(m1 - mn1);
        m0 = mn0; m1 = mn1;

        float rs0 = 0.f, rs1 = 0.f;
#pragma unroll
        for (int j = 0; j < 8; j++) {
            sacc[j][0] = ex2(sacc[j][0] - m0);
            sacc[j][1] = ex2(sacc[j][1] - m0);
            sacc[j][2] = ex2(sacc[j][2] - m1);
            sacc[j][3] = ex2(sacc[j][3] - m1);
            rs0 += sacc[j][0] + sacc[j][1];
            rs1 += sacc[j][2] + sacc[j][3];
        }
#pragma unroll
        for (int off = 1; off <= 2; off <<= 1) {
            rs0 += __shfl_xor_sync(~0u, rs0, off);
            rs1 += __shfl_xor_sync(~0u, rs1, off);
        }
        l0 = l0 * al0 + rs0;
        l1 = l1 * al1 + rs1;
#pragma unroll
        for (int j = 0; j < 8; j++) {
            oacc[j][0] *= al0; oacc[j][1] *= al0;
            oacc[j][2] *= al1; oacc[j][3] *= al1;
        }

        // ---- O += P V ----
        const uint32_t vbase = smb + VOFF + (t & 1) * TBYTES;
#pragma unroll
        for (int kc = 0; kc < 4; kc++) {
            uint32_t pa[4];
            __half2 h;
            h = __floats2half2_rn(sacc[2 * kc][0],     sacc[2 * kc][1]);     pa[0] = *(uint32_t*)&h;
            h = __floats2half2_rn(sacc[2 * kc][2],     sacc[2 * kc][3]);     pa[1] = *(uint32_t*)&h;
            h = __floats2half2_rn(sacc[2 * kc + 1][0], sacc[2 * kc + 1][1]); pa[2] = *(uint32_t*)&h;
            h = __floats2half2_rn(sacc[2 * kc + 1][2], sacc[2 * kc + 1][3]); pa[3] = *(uint32_t*)&h;
#pragma unroll
            for (int n2 = 0; n2 < 4; n2++) {
                uint32_t vb[4];
                ldsm4t(vb, vbase + kc * 16 * APITCH + n2 * 32 + bt_off);
                mma_f16(oacc[n2 * 2],     pa, &vb[0]);
                mma_f16(oacc[n2 * 2 + 1], pa, &vb[2]);
            }
        }
        __syncthreads();
    }

    // ---- normalize + write fp16 ----
    const float inv0 = 1.f / l0, inv1 = 1.f / l1;
    const int r0 = qb * 128 + w * 16 + (lane >> 2);
    __half* po = och + (size_t)z * HSZ;
#pragma unroll
    for (int j = 0; j < 8; j++) {
        const int col = j * 8 + (lane & 3) * 2;
        *(__half2*)(po + (size_t)r0 * DH + col) =
            __floats2half2_rn(oacc[j][0] * inv0, oacc[j][1] * inv0);
        *(__half2*)(po + (size_t)(r0 + 8) * DH + col) =
            __floats2half2_rn(oacc[j][2] * inv1, oacc[j][3] * inv1);
    }
}

// ---------------- fused weight fp16 convert (all 6 matrices, native layout) ----
__global__ void k_prep(const float* __restrict__ Wq, const float* __restrict__ Wk,
                       const float* __restrict__ Wv, const float* __restrict__ Wo,
                       const float* __restrict__ W1, const float* __restrict__ W2,
                       __half* __restrict__ wh) {
    const int l = blockIdx.y;
    const size_t i = ((size_t)blockIdx.x * 256 + threadIdx.x) * 8;
    if (i >= LW) return;
    const float* src;
    if (i < 4 * (size_t)EE) {
        const int ty = (int)(i / EE);
        const float* base = (ty == 0) ? Wq : (ty == 1) ? Wk : (ty == 2) ? Wv : Wo;
        src = base + (size_t)l * EE + (i - (size_t)ty * EE);
    } else if (i < (size_t)OFF_2) {
        src = W1 + (size_t)l * EF + (i - OFF_1);
    } else {
        src = W2 + (size_t)l * EF + (i - OFF_2);
    }
    const float4 v0 = *(const float4*)src;
    const float4 v1 = *(const float4*)(src + 4);
    float f[8] = {v0.x, v0.y, v0.z, v0.w, v1.x, v1.y, v1.z, v1.w};
    uint32_t hi[4];
#pragma unroll
    for (int q = 0; q < 4; q++) {
        const __half2 h2 = __floats2half2_rn(f[q * 2], f[q * 2 + 1]);
        hi[q] = *(const uint32_t*)&h2;
    }
    *(uint4*)(wh + (size_t)l * LW + i) = *(uint4*)hi;
}

// ---------------- pack qkv biases contiguously (all layers) ----------------
__global__ void k_pack3(const float* __restrict__ a, const float* __restrict__ b,
                        const float* __restrict__ c, float* __restrict__ o) {
    const int l = blockIdx.y;
    const int i = blockIdx.x * 256 + threadIdx.x;
    if (i < E) {
        float* ol = o + (size_t)l * 3 * E;
        ol[i] = a[(size_t)l * E + i];
        ol[E + i] = b[(size_t)l * E + i];
        ol[2 * E + i] = c[(size_t)l * E + i];
    }
}

// ---------------- embedding gather ----------------
__global__ void k_embed(const int* __restrict__ x, const float* __restrict__ emb,
                        float* __restrict__ h, __half* __restrict__ hh) {
    const int row = blockIdx.x;
    const int tok = x[row];
    for (int i = threadIdx.x; i < E; i += 256) {
        const float v = emb[(size_t)tok * E + i];
        const size_t o = (size_t)row * E + i;
        h[o] = v;
        hh[o] = __float2half(v);
    }
}

// ---------------- layernorm (fp32 in; fp32 + fp16 out) ----------------
__global__ void k_ln(const float* __restrict__ in, float* __restrict__ out,
                     __half* __restrict__ oh,
                     const float* __restrict__ g, const float* __restrict__ b) {
    __shared__ float s1[8], s2[8];
    const int row = blockIdx.x, t = threadIdx.x;
    const int lane = t & 31, w = t >> 5;
    const float* p = in + (size_t)row * E;

    const float x0 = p[t], x1 = p[t + 256], x2 = p[t + 512];
    float a = x0 + x1 + x2;
    float q = x0 * x0 + x1 * x1 + x2 * x2;
#pragma unroll
    for (int off = 16; off; off >>= 1) {
        a += __shfl_xor_sync(~0u, a, off);
        q += __shfl_xor_sync(~0u, q, off);
    }
    if (lane == 0) { s1[w] = a; s2[w] = q; }
    __syncthreads();
    float ta = 0.f, tq = 0.f;
#pragma unroll
    for (int i = 0; i < 8; i++) { ta += s1[i]; tq += s2[i]; }
    const float mean = ta * (1.0f / E);
    const float var  = tq * (1.0f / E) - mean * mean;
    const float inv  = rsqrtf(var + EPSL);

    const size_t base = (size_t)row * E;
#pragma unroll
    for (int k = 0; k < 3; k++) {
        const int idx = t + k * 256;
        const float xv = (k == 0) ? x0 : (k == 1) ? x1 : x2;
        const float v = (xv - mean) * inv * g[idx] + b[idx];
        out[base + idx] = v;
        oh[base + idx]  = __float2half(v);
    }
}

// ---------------- classifier: partials then reduce ----------------
#define CLS_P 16
#define CLS_CHUNK (SE / CLS_P)
__global__ void k_cls1(const float* __restrict__ h, const float* __restrict__ Wc,
                       float* __restrict__ part) {
    __shared__ float red[256];
    const int bb = blockIdx.x, p = blockIdx.y, t = threadIdx.x;
    const float* hr = h + (size_t)bb * SE;
    float a[CC];
#pragma unroll
    for (int c = 0; c < CC; c++) a[c] = 0.f;
    const int i0 = p * CLS_CHUNK;
    for (int i = i0 + t; i < i0 + CLS_CHUNK; i += 256) {
        const float hv = hr[i];
        const float* w = Wc + (size_t)i * CC;
#pragma unroll
        for (int c = 0; c < CC; c++) a[c] = fmaf(hv, w[c], a[c]);
    }
#pragma unroll
    for (int c = 0; c < CC; c++) {
        red[t] = a[c]; __syncthreads();
        for (int k = 128; k > 0; k >>= 1) {
            if (t < k) red[t] += red[t + k];
            __syncthreads();
        }
        if (t == 0) part[((size_t)bb * CLS_P + p) * CC + c] = red[0];
        __syncthreads();
    }
}
__global__ void k_cls2(const float* __restrict__ part, const float* __restrict__ bc,
                       float* __restrict__ out) {
    const int t = threadIdx.x;
    if (t < B * CC) {
        const int bb = t / CC, c = t % CC;
        float s = bc[c];
        for (int p = 0; p < CLS_P; p++) s += part[((size_t)bb * CLS_P + p) * CC + c];
        out[t] = s;
    }
}

// ---------------- host ----------------
extern "C" void kernel_launch(void* const* d_in, const int* in_sizes, int n_in,
                              void* d_out, int out_size) {
    const int*   x    = (const int*)  d_in[0];
    const float* emb  = (const float*)d_in[1];
    const float* Wq   = (const float*)d_in[2];
    const float* bq   = (const float*)d_in[3];
    const float* Wk   = (const float*)d_in[4];
    const float* bk   = (const float*)d_in[5];
    const float* Wv   = (const float*)d_in[6];
    const float* bv   = (const float*)d_in[7];
    const float* Wo   = (const float*)d_in[8];
    const float* bo   = (const float*)d_in[9];
    const float* ln1g = (const float*)d_in[10];
    const float* ln1b = (const float*)d_in[11];
    const float* W1   = (const float*)d_in[12];
    const float* b1   = (const float*)d_in[13];
    const float* W2   = (const float*)d_in[14];
    const float* b2   = (const float*)d_in[15];
    const float* ln2g = (const float*)d_in[16];
    const float* ln2b = (const float*)d_in[17];
    const float* Wc   = (const float*)d_in[18];
    const float* bc   = (const float*)d_in[19];
    float* out = (float*)d_out;

    float *h, *t, *bqkv;
    __half *hh, *qkv, *ch, *fh, *wh;
    cudaGetSymbolAddress((void**)&h,   g_h);
    cudaGetSymbolAddress((void**)&t,   g_t);
    cudaGetSymbolAddress((void**)&hh,  g_hh);
    cudaGetSymbolAddress((void**)&qkv, g_qkv);
    cudaGetSymbolAddress((void**)&ch,  g_ch);
    cudaGetSymbolAddress((void**)&fh,  g_fh);
    cudaGetSymbolAddress((void**)&wh,  g_wh);
    cudaGetSymbolAddress((void**)&bqkv, g_bqkv);

    constexpr int SMEM_QKV = 4 * (128 * 80 + 32 * (128 + 8) * 2); // 75776
    constexpr int SMEM_W   = 4 * (64 * 80 + 32 * (128 + 8) * 2);  // 55296
    cudaFuncSetAttribute(k_mma<128, 128>, cudaFuncAttributeMaxDynamicSharedMemorySize, SMEM_QKV);
    cudaFuncSetAttribute(k_mma<64, 128>,  cudaFuncAttributeMaxDynamicSharedMemorySize, SMEM_W);
    cudaFuncSetAttribute(k_attn,          cudaFuncAttributeMaxDynamicSharedMemorySize, AT_SMEM);

    __half *qh = qkv, *kh = qkv + (size_t)M4 * E, *vh = qkv + (size_t)2 * M4 * E;

    k_prep<<<dim3(LW / 2048, L), 256>>>(Wq, Wk, Wv, Wo, W1, W2, wh);
    k_pack3<<<dim3(3, L), 256>>>(bq, bk, bv, bqkv);
    k_embed<<<M4, 256>>>(x, emb, h, hh);

    const dim3 gQKV(6, 32, 3);     // BM=128
    const dim3 gEE64(6, 64);       // BM=64: Wo, FF2
    const dim3 gF164(24, 64);      // BM=64: FF1
    const dim3 gAt(4, NHEAD);      // fused attention

    for (int l = 0; l < L; l++) {
        const size_t wb = (size_t)l * LW;

        // fused QKV
        k_mma<128, 128><<<gQKV, 256, SMEM_QKV>>>(hh, wh + wb + OFF_Q,
            bqkv + (size_t)l * 3 * E, nullptr, nullptr, qkv,
            E, E, 0, (size_t)EE, (size_t)M4 * E, E, 1.f, 0);

        // fused attention: softmax(QK^T/8)V -> ch (fp16)
        k_attn<<<gAt, 256, AT_SMEM>>>(qh, kh, vh, ch);

        // Wo + residual -> LN1
        k_mma<64, 128><<<gEE64, 256, SMEM_W>>>(ch, wh + wb + OFF_O,
            bo + (size_t)l * E, h, t, nullptr,
            E, E, 0, 0, 0, 0, 1.f, 0);
        k_ln<<<M4, 256>>>(t, h, hh, ln1g + (size_t)l * E, ln1b + (size_t)l * E);

        // FFN
        k_mma<64, 128><<<gF164, 256, SMEM_W>>>(hh, wh + wb + OFF_1,
            b1 + (size_t)l * FF, nullptr, nullptr, fh,
            FF, E, 0, 0, 0, 0, 1.f, 1);
        k_mma<64, 128><<<gEE64, 256, SMEM_W>>>(fh, wh + wb + OFF_2,
            b2 + (size_t)l * E, h, t, nullptr,
            E, FF, 0, 0, 0, 0, 1.f, 0);
        k_ln<<<M4, 256>>>(t, h, hh, ln2g + (size_t)l * E, ln2b + (size_t)l * E);
    }

    // classifier (fp32 exact)
    k_cls1<<<dim3(B, CLS_P), 256>>>(h, Wc, t);
    k_cls2<<<1, 128>>>(t, bc, out);
}

// round 11
// speedup vs baseline: 7.4536x; 1.0057x over previous
#include <cuda_runtime.h>
#include <cuda_fp16.h>
#include <cstdint>
#include <math.h>

// ---------------- problem constants ----------------
#define B    8
#define S    512
#define E    768
#define NH   12
#define DH   64
#define FF   3072
#define L    6
#define CC   10
#define M4   (B*S)          // 4096 rows
#define HSZ  (S*DH)         // 32768 per-head elems
#define NHEAD (B*NH)        // 96
#define EPSL 1e-5f
#define SE   (S*E)

// per-layer weight block (elems), native [K,N] layout: Wq,Wk,Wv,Wo,W1,W2
#define EE   (E*E)
#define EF   (E*FF)
#define LW   (4*EE + 2*EF)
#define OFF_Q 0
#define OFF_K EE
#define OFF_V (2*EE)
#define OFF_O (3*EE)
#define OFF_1 (4*EE)
#define OFF_2 (4*EE + EF)

// ---------------- scratch (device globals) ----------------
__device__ float g_h [M4*E];
__device__ float g_t [M4*E];                    // pre-LN buffer; cls partials
__device__ __half g_hh[M4*E];
__device__ __half g_qkv[3*M4*E];
__device__ __half g_ch[M4*E];
__device__ __half g_fh[M4*FF];
__device__ __half g_wh[(size_t)L*LW];
__device__ float g_bqkv[L*3*E];

// ---------------- asm helpers ----------------
__device__ __forceinline__ uint32_t smem_u32(const void* p) {
    uint32_t a;
    asm("{ .reg .u64 t; cvta.to.shared.u64 t, %1; cvt.u32.u64 %0, t; }" : "=r"(a) : "l"(p));
    return a;
}
__device__ __forceinline__ void ldsm4(uint32_t* r, uint32_t a) {
    asm volatile("ldmatrix.sync.aligned.m8n8.x4.shared.b16 {%0,%1,%2,%3}, [%4];"
        : "=r"(r[0]), "=r"(r[1]), "=r"(r[2]), "=r"(r[3]) : "r"(a));
}
__device__ __forceinline__ void ldsm4t(uint32_t* r, uint32_t a) {
    asm volatile("ldmatrix.sync.aligned.m8n8.x4.trans.shared.b16 {%0,%1,%2,%3}, [%4];"
        : "=r"(r[0]), "=r"(r[1]), "=r"(r[2]), "=r"(r[3]) : "r"(a));
}
__device__ __forceinline__ void mma_f16(float* c, const uint32_t* a, const uint32_t* b) {
    asm volatile("mma.sync.aligned.m16n8k16.row.col.f32.f16.f16.f32 "
        "{%0,%1,%2,%3}, {%4,%5,%6,%7}, {%8,%9}, {%0,%1,%2,%3};"
        : "+f"(c[0]), "+f"(c[1]), "+f"(c[2]), "+f"(c[3])
        : "r"(a[0]), "r"(a[1]), "r"(a[2]), "r"(a[3]), "r"(b[0]), "r"(b[1]));
}
__device__ __forceinline__ float ex2(float x) {
    float r;
    asm("ex2.approx.f32 %0, %1;" : "=f"(r) : "f"(x));
    return r;
}
#define CPA(dst, src) asm volatile("cp.async.cg.shared.global [%0], [%1], 16;" :: "r"(dst), "l"(src))
#define CPC() asm volatile("cp.async.commit_group;" ::: "memory")
#define CPW(n) asm volatile("cp.async.wait_group %0;" :: "n"(n) : "memory")

// ================= HMMA GEMM (fp16 in, fp32 accum) =================
// D[row,col] = scale*sum_k A[row,k]*B(col,k) (+bias)(relu)(+res); B stored [K,N] (trans).
// BM in {128,64}; BK=32; 256 threads; 4-stage cp.async ring, one barrier per kt.
template<int BM, int BN>
__global__ void __launch_bounds__(256, (BM == 128) ? 2 : 3)
k_mma(const __half* __restrict__ Ah, const __half* __restrict__ Bh,
      const float* __restrict__ bias, const float* __restrict__ res,
      float* __restrict__ Cf, __half* __restrict__ Chi,
      int N, int K, size_t sAz, size_t sBz, size_t sCz, size_t bsz,
      float scale, int relu) {
    extern __shared__ char sm[];
    constexpr int WM  = BM / 32;
    constexpr int WN  = 8 / WM;
    constexpr int WTN = BN / WN;
    constexpr int MF  = 2;
    constexpr int NF  = WTN / 8;
    constexpr int ATILE  = BM * 80;
    constexpr int BPITCH = (BN + 8) * 2;
    constexpr int BTILE  = 32 * BPITCH;
    constexpr int STAGE  = ATILE + BTILE;

    const uint32_t smb = smem_u32(sm);
    const int tid = threadIdx.x, lane = tid & 31, wid = tid >> 5;
    const int wm = wid / WN, wn = wid % WN;
    const int bm = blockIdx.y * BM, bn = blockIdx.x * BN;
    const size_t zA = (size_t)blockIdx.z * sAz, zB = (size_t)blockIdx.z * sBz;
    const __half* pA = Ah + zA + (size_t)bm * K;
    const __half* pB = Bh + zB;

    float acc[MF][NF][4];
#pragma unroll
    for (int i = 0; i < MF; i++)
#pragma unroll
        for (int j = 0; j < NF; j++)
#pragma unroll
            for (int q = 0; q < 4; q++) acc[i][j][q] = 0.f;

    const uint32_t a_off = (uint32_t)(lane & 15) * 80 + (uint32_t)(lane >> 4) * 16;
    const uint32_t b_off = (uint32_t)(lane & 15) * BPITCH + (uint32_t)(lane >> 4) * 16;

    const int KT = K >> 5;

    auto load_stage = [&](int s, int kt) {
        const int k0 = kt << 5;
        const uint32_t base = smb + s * STAGE;
#pragma unroll 2
        for (int cid = tid; cid < BM * 4; cid += 256) {
            const int row = cid >> 2, p = cid & 3;
            CPA(base + row * 80 + p * 16, pA + (size_t)row * K + k0 + p * 8);
        }
#pragma unroll 2
        for (int cid = tid; cid < 32 * (BN / 8); cid += 256) {
            const int row = cid / (BN / 8), c = cid % (BN / 8);
            CPA(base + ATILE + row * BPITCH + c * 16,
                pB + (size_t)(k0 + row) * N + bn + c * 8);
        }
    };

    load_stage(0, 0); CPC();
    if (KT > 1) { load_stage(1, 1); CPC(); }

    for (int kt = 0; kt < KT; ++kt) {
        const int stg = kt & 3;
        if (kt + 2 < KT) { load_stage((kt + 2) & 3, kt + 2); CPC(); CPW(2); }
        else if (kt + 1 < KT) CPW(1);
        else CPW(0);
        __syncthreads();

        const uint32_t stageB = smb + stg * STAGE;
        const uint32_t aB = stageB + wm * 32 * 80 + a_off;
        const uint32_t bB = stageB + ATILE + wn * WTN * 2 + b_off;
#pragma unroll
        for (int ks = 0; ks < 2; ++ks) {
            uint32_t aR[MF][4], bR[(NF + 1) / 2][4];
#pragma unroll
            for (int n2 = 0; n2 < NF / 2; n2++)
                ldsm4t(bR[n2], bB + ks * 16 * BPITCH + n2 * 32);
#pragma unroll
            for (int mi = 0; mi < MF; mi++)
                ldsm4(aR[mi], aB + mi * 16 * 80 + ks * 32);

#pragma unroll
            for (int mi = 0; mi < MF; mi++)
#pragma unroll
                for (int n2 = 0; n2 < NF / 2; n2++) {
                    mma_f16(acc[mi][n2 * 2],     aR[mi], &bR[n2][0]);
                    mma_f16(acc[mi][n2 * 2 + 1], aR[mi], &bR[n2][2]);
                }
        }
    }

    // ---- epilogue ----
    const size_t cz = (size_t)blockIdx.z * sCz;
    const float* bz = bias ? bias + (size_t)blockIdx.z * bsz : nullptr;
    const int r0 = bm + wm * 32 + (lane >> 2);
    const int c0 = bn + wn * WTN + (lane & 3) * 2;

#pragma unroll
    for (int mi = 0; mi < MF; mi++) {
#pragma unroll
        for (int ni = 0; ni < NF; ni++) {
            const int col = c0 + ni * 8;
#pragma unroll
            for (int half = 0; half < 2; half++) {
                const int row = r0 + mi * 16 + half * 8;
                float v0 = acc[mi][ni][half * 2]     * scale;
                float v1 = acc[mi][ni][half * 2 + 1] * scale;
                if (bz) { v0 += bz[col]; v1 += bz[col + 1]; }
                if (relu) { v0 = fmaxf(v0, 0.f); v1 = fmaxf(v1, 0.f); }
                if (res) {
                    const float2 rv = *(const float2*)&res[(size_t)row * N + col];
                    v0 += rv.x; v1 += rv.y;
                }
                const size_t o = cz + (size_t)row * N + col;
                if (Cf) { float2 f = {v0, v1}; *(float2*)&Cf[o] = f; }
                if (Chi) {
                    float2 fv; fv.x = v0; fv.y = v1;
                    *(__half2*)&Chi[o] = __float22half2_rn(fv);
                }
            }
        }
    }
}

// ================= fused attention (FlashAttention-2 style) =================
#define APITCH 144           // (64+8)*2 bytes per row
#define QBYTES (128*APITCH)  // 18432
#define TBYTES (64*APITCH)   // 9216
#define AT_SMEM (QBYTES + 4*TBYTES)  // 55296
#define C_EXP2 0.18033688011112042f  // 0.125 * log2(e)

__global__ void __launch_bounds__(256, 2)
k_attn(const __half* __restrict__ q, const __half* __restrict__ k,
       const __half* __restrict__ v, __half* __restrict__ och) {
    extern __shared__ char sm[];
    const uint32_t smb = smem_u32(sm);
    const uint32_t KOFF = QBYTES, VOFF = QBYTES + 2 * TBYTES;
    const int tid = threadIdx.x, lane = tid & 31, w = tid >> 5;
    const int z = blockIdx.y, qb = blockIdx.x;
    const __half* pQ = q + (size_t)z * HSZ + (size_t)qb * 128 * DH;
    const __half* pK = k + (size_t)z * HSZ;
    const __half* pV = v + (size_t)z * HSZ;

    const uint32_t a_off  = (uint32_t)(lane & 15) * APITCH + (uint32_t)(lane >> 4) * 16;
    const uint32_t bs_off = (uint32_t)((lane & 7) + ((lane >> 1) & 8)) * APITCH
                          + (uint32_t)((lane >> 3) & 1) * 16;
    const uint32_t bt_off = a_off;

    auto loadQ = [&]() {
#pragma unroll
        for (int cid = tid; cid < 1024; cid += 256) {
            const int row = cid >> 3, p = cid & 7;
            CPA(smb + row * APITCH + p * 16, pQ + (size_t)row * DH + p * 8);
        }
    };
    auto loadKV = [&](int t) {
        const uint32_t kb = smb + KOFF + (t & 1) * TBYTES;
        const uint32_t vb = smb + VOFF + (t & 1) * TBYTES;
        const __half* sk = pK + (size_t)t * 64 * DH;
        const __half* sv = pV + (size_t)t * 64 * DH;
#pragma unroll
        for (int cid = tid; cid < 512; cid += 256) {
            const int row = cid >> 3, p = cid & 7;
            CPA(kb + row * APITCH + p * 16, sk + (size_t)row * DH + p * 8);
            CPA(vb + row * APITCH + p * 16, sv + (size_t)row * DH + p * 8);
        }
    };

    loadQ(); loadKV(0); CPC();

    uint32_t qf[4][4];
    float oacc[8][4];
#pragma unroll
    for (int j = 0; j < 8; j++)
#pragma unroll
        for (int qq = 0; qq < 4; qq++) oacc[j][qq] = 0.f;
    float m0 = -1e30f, m1 = -1e30f, l0 = 0.f, l1 = 0.f;

    for (int t = 0; t < 8; ++t) {
        if (t + 1 < 8) { loadKV(t + 1); CPC(); CPW(1); }
        else CPW(0);
        __syncthreads();

        if (t == 0) {
            const uint32_t qbase = smb + w * 16 * APITCH + a_off;
#pragma unroll
            for (int kc = 0; kc < 4; kc++) ldsm4(qf[kc], qbase + kc * 32);
        }

        const uint32_t kbase = smb + KOFF + (t & 1) * TBYTES;
        float sacc[8][4];
#pragma unroll
        for (int j = 0; j < 8; j++)
#pragma unroll
            for (int qq = 0; qq < 4; qq++) sacc[j][qq] = 0.f;
#pragma unroll
        for (int kc = 0; kc < 4; kc++) {
#pragma unroll
            for (int n2 = 0; n2 < 4; n2++) {
                uint32_t kb[4];
                ldsm4(kb, kbase + n2 * 16 * APITCH + kc * 32 + bs_off);
                mma_f16(sacc[n2 * 2],     qf[kc], &kb[0]);
                mma_f16(sacc[n2 * 2 + 1], qf[kc], &kb[2]);
            }
        }

        float mt0 = -1e30f, mt1 = -1e30f;
#pragma unroll
        for (int j = 0; j < 8; j++) {
#pragma unroll
            for (int qq = 0; qq < 4; qq++) sacc[j][qq] *= C_EXP2;
            mt0 = fmaxf(mt0, fmaxf(sacc[j][0], sacc[j][1]));
            mt1 = fmaxf(mt1, fmaxf(sacc[j][2], sacc[j][3]));
        }
#pragma unroll
        for (int off = 1; off <= 2; off <<= 1) {
            mt0 = fmaxf(mt0, __shfl_xor_sync(~0u, mt0, off));
            mt1 = fmaxf(mt1, __shfl_xor_sync(~0u, mt1, off));
        }
        const float mn0 = fmaxf(m0, mt0), mn1 = fmaxf(m1, mt1);
        const float al0 = ex2(m0 - mn0), al1 = ex2(m1 - mn1);
        m0 = mn0; m1 = mn1;

        float rs0 = 0.f, rs1 = 0.f;
#pragma unroll
        for (int j = 0; j < 8; j++) {
            sacc[j][0] = ex2(sacc[j][0] - m0);
            sacc[j][1] = ex2(sacc[j][1] - m0);
            sacc[j][2] = ex2(sacc[j][2] - m1);
            sacc[j][3] = ex2(sacc[j][3] - m1);
            rs0 += sacc[j][0] + sacc[j][1];
            rs1 += sacc[j][2] + sacc[j][3];
        }
#pragma unroll
        for (int off = 1; off <= 2; off <<= 1) {
            rs0 += __shfl_xor_sync(~0u, rs0, off);
            rs1 += __shfl_xor_sync(~0u, rs1, off);
        }
        l0 = l0 * al0 + rs0;
        l1 = l1 * al1 + rs1;
#pragma unroll
        for (int j = 0; j < 8; j++) {
            oacc[j][0] *= al0; oacc[j][1] *= al0;
            oacc[j][2] *= al1; oacc[j][3] *= al1;
        }

        const uint32_t vbase = smb + VOFF + (t & 1) * TBYTES;
#pragma unroll
        for (int kc = 0; kc < 4; kc++) {
            uint32_t pa[4];
            __half2 h;
            h = __floats2half2_rn(sacc[2 * kc][0],     sacc[2 * kc][1]);     pa[0] = *(uint32_t*)&h;
            h = __floats2half2_rn(sacc[2 * kc][2],     sacc[2 * kc][3]);     pa[1] = *(uint32_t*)&h;
            h = __floats2half2_rn(sacc[2 * kc + 1][0], sacc[2 * kc + 1][1]); pa[2] = *(uint32_t*)&h;
            h = __floats2half2_rn(sacc[2 * kc + 1][2], sacc[2 * kc + 1][3]); pa[3] = *(uint32_t*)&h;
#pragma unroll
            for (int n2 = 0; n2 < 4; n2++) {
                uint32_t vb[4];
                ldsm4t(vb, vbase + kc * 16 * APITCH + n2 * 32 + bt_off);
                mma_f16(oacc[n2 * 2],     pa, &vb[0]);
                mma_f16(oacc[n2 * 2 + 1], pa, &vb[2]);
            }
        }
        __syncthreads();
    }

    const float inv0 = 1.f / l0, inv1 = 1.f / l1;
    const int r0 = qb * 128 + w * 16 + (lane >> 2);
    __half* po = och + (size_t)z * HSZ;
#pragma unroll
    for (int j = 0; j < 8; j++) {
        const int col = j * 8 + (lane & 3) * 2;
        *(__half2*)(po + (size_t)r0 * DH + col) =
            __floats2half2_rn(oacc[j][0] * inv0, oacc[j][1] * inv0);
        *(__half2*)(po + (size_t)(r0 + 8) * DH + col) =
            __floats2half2_rn(oacc[j][2] * inv1, oacc[j][3] * inv1);
    }
}

// ---------------- fused weight fp16 convert (16 elems/thread) ----------------
__global__ void k_prep(const float* __restrict__ Wq, const float* __restrict__ Wk,
                       const float* __restrict__ Wv, const float* __restrict__ Wo,
                       const float* __restrict__ W1, const float* __restrict__ W2,
                       __half* __restrict__ wh) {
    const int l = blockIdx.y;
    const size_t i = ((size_t)blockIdx.x * 256 + threadIdx.x) * 16;
    if (i >= LW) return;
    const float* src;
    if (i < 4 * (size_t)EE) {
        const int ty = (int)(i / EE);
        const float* base = (ty == 0) ? Wq : (ty == 1) ? Wk : (ty == 2) ? Wv : Wo;
        src = base + (size_t)l * EE + (i - (size_t)ty * EE);
    } else if (i < (size_t)OFF_2) {
        src = W1 + (size_t)l * EF + (i - OFF_1);
    } else {
        src = W2 + (size_t)l * EF + (i - OFF_2);
    }
    uint32_t hi[8];
#pragma unroll
    for (int g4 = 0; g4 < 4; g4++) {
        const float4 v = *(const float4*)(src + g4 * 4);
        const __half2 h0 = __floats2half2_rn(v.x, v.y);
        const __half2 h1 = __floats2half2_rn(v.z, v.w);
        hi[g4 * 2]     = *(const uint32_t*)&h0;
        hi[g4 * 2 + 1] = *(const uint32_t*)&h1;
    }
    __half* dst = wh + (size_t)l * LW + i;
    *(uint4*)dst       = *(uint4*)hi;
    *(uint4*)(dst + 8) = *(uint4*)(hi + 4);
}

// ---------------- pack qkv biases contiguously (all layers) ----------------
__global__ void k_pack3(const float* __restrict__ a, const float* __restrict__ b,
                        const float* __restrict__ c, float* __restrict__ o) {
    const int l = blockIdx.y;
    const int i = blockIdx.x * 256 + threadIdx.x;
    if (i < E) {
        float* ol = o + (size_t)l * 3 * E;
        ol[i] = a[(size_t)l * E + i];
        ol[E + i] = b[(size_t)l * E + i];
        ol[2 * E + i] = c[(size_t)l * E + i];
    }
}

// ---------------- embedding gather ----------------
__global__ void k_embed(const int* __restrict__ x, const float* __restrict__ emb,
                        float* __restrict__ h, __half* __restrict__ hh) {
    const int row = blockIdx.x;
    const int tok = x[row];
    for (int i = threadIdx.x; i < E; i += 256) {
        const float v = emb[(size_t)tok * E + i];
        const size_t o = (size_t)row * E + i;
        h[o] = v;
        hh[o] = __float2half(v);
    }
}

// ---------------- layernorm: one warp per row, shfl-only ----------------
__global__ void k_ln(const float* __restrict__ in, float* __restrict__ out,
                     __half* __restrict__ oh,
                     const float* __restrict__ g, const float* __restrict__ b) {
    const int w = threadIdx.x >> 5, lane = threadIdx.x & 31;
    const int row = blockIdx.x * 8 + w;
    const float* p = in + (size_t)row * E;

    float4 x[6];
    float s = 0.f, q = 0.f;
#pragma unroll
    for (int i = 0; i < 6; i++) {
        x[i] = *(const float4*)(p + 4 * (lane + 32 * i));
        s += x[i].x + x[i].y + x[i].z + x[i].w;
        q += x[i].x * x[i].x + x[i].y * x[i].y + x[i].z * x[i].z + x[i].w * x[i].w;
    }
#pragma unroll
    for (int off = 16; off; off >>= 1) {
        s += __shfl_xor_sync(~0u, s, off);
        q += __shfl_xor_sync(~0u, q, off);
    }
    const float mean = s * (1.0f / E);
    const float var  = q * (1.0f / E) - mean * mean;
    const float inv  = rsqrtf(var + EPSL);

    float* po = out + (size_t)row * E;
    __half* ph = oh + (size_t)row * E;
#pragma unroll
    for (int i = 0; i < 6; i++) {
        const int c4 = 4 * (lane + 32 * i);
        const float4 gv = *(const float4*)(g + c4);
        const float4 bv = *(const float4*)(b + c4);
        float4 v;
        v.x = (x[i].x - mean) * inv * gv.x + bv.x;
        v.y = (x[i].y - mean) * inv * gv.y + bv.y;
        v.z = (x[i].z - mean) * inv * gv.z + bv.z;
        v.w = (x[i].w - mean) * inv * gv.w + bv.w;
        *(float4*)(po + c4) = v;
        uint32_t hp[2];
        const __half2 h0 = __floats2half2_rn(v.x, v.y);
        const __half2 h1 = __floats2half2_rn(v.z, v.w);
        hp[0] = *(const uint32_t*)&h0;
        hp[1] = *(const uint32_t*)&h1;
        *(uint2*)(ph + c4) = *(uint2*)hp;
    }
}

// ---------------- classifier: partials then reduce ----------------
#define CLS_P 16
#define CLS_CHUNK (SE / CLS_P)
__global__ void k_cls1(const float* __restrict__ h, const float* __restrict__ Wc,
                       float* __restrict__ part) {
    __shared__ float red[256];
    const int bb = blockIdx.x, p = blockIdx.y, t = threadIdx.x;
    const float* hr = h + (size_t)bb * SE;
    float a[CC];
#pragma unroll
    for (int c = 0; c < CC; c++) a[c] = 0.f;
    const int i0 = p * CLS_CHUNK;
    for (int i = i0 + t; i < i0 + CLS_CHUNK; i += 256) {
        const float hv = hr[i];
        const float* w = Wc + (size_t)i * CC;
#pragma unroll
        for (int c = 0; c < CC; c++) a[c] = fmaf(hv, w[c], a[c]);
    }
#pragma unroll
    for (int c = 0; c < CC; c++) {
        red[t] = a[c]; __syncthreads();
        for (int k = 128; k > 0; k >>= 1) {
            if (t < k) red[t] += red[t + k];
            __syncthreads();
        }
        if (t == 0) part[((size_t)bb * CLS_P + p) * CC + c] = red[0];
        __syncthreads();
    }
}
__global__ void k_cls2(const float* __restrict__ part, const float* __restrict__ bc,
                       float* __restrict__ out) {
    const int t = threadIdx.x;
    if (t < B * CC) {
        const int bb = t / CC, c = t % CC;
        float s = bc[c];
        for (int p = 0; p < CLS_P; p++) s += part[((size_t)bb * CLS_P + p) * CC + c];
        out[t] = s;
    }
}

// ---------------- host ----------------
extern "C" void kernel_launch(void* const* d_in, const int* in_sizes, int n_in,
                              void* d_out, int out_size) {
    const int*   x    = (const int*)  d_in[0];
    const float* emb  = (const float*)d_in[1];
    const float* Wq   = (const float*)d_in[2];
    const float* bq   = (const float*)d_in[3];
    const float* Wk   = (const float*)d_in[4];
    const float* bk   = (const float*)d_in[5];
    const float* Wv   = (const float*)d_in[6];
    const float* bv   = (const float*)d_in[7];
    const float* Wo   = (const float*)d_in[8];
    const float* bo   = (const float*)d_in[9];
    const float* ln1g = (const float*)d_in[10];
    const float* ln1b = (const float*)d_in[11];
    const float* W1   = (const float*)d_in[12];
    const float* b1   = (const float*)d_in[13];
    const float* W2   = (const float*)d_in[14];
    const float* b2   = (const float*)d_in[15];
    const float* ln2g = (const float*)d_in[16];
    const float* ln2b = (const float*)d_in[17];
    const float* Wc   = (const float*)d_in[18];
    const float* bc   = (const float*)d_in[19];
    float* out = (float*)d_out;

    float *h, *t, *bqkv;
    __half *hh, *qkv, *ch, *fh, *wh;
    cudaGetSymbolAddress((void**)&h,   g_h);
    cudaGetSymbolAddress((void**)&t,   g_t);
    cudaGetSymbolAddress((void**)&hh,  g_hh);
    cudaGetSymbolAddress((void**)&qkv, g_qkv);
    cudaGetSymbolAddress((void**)&ch,  g_ch);
    cudaGetSymbolAddress((void**)&fh,  g_fh);
    cudaGetSymbolAddress((void**)&wh,  g_wh);
    cudaGetSymbolAddress((void**)&bqkv, g_bqkv);

    constexpr int SMEM_QKV = 4 * (128 * 80 + 32 * (128 + 8) * 2); // 75776
    constexpr int SMEM_W   = 4 * (64 * 80 + 32 * (128 + 8) * 2);  // 55296
    cudaFuncSetAttribute(k_mma<128, 128>, cudaFuncAttributeMaxDynamicSharedMemorySize, SMEM_QKV);
    cudaFuncSetAttribute(k_mma<64, 128>,  cudaFuncAttributeMaxDynamicSharedMemorySize, SMEM_W);
    cudaFuncSetAttribute(k_attn,          cudaFuncAttributeMaxDynamicSharedMemorySize, AT_SMEM);

    __half *qh = qkv, *kh = qkv + (size_t)M4 * E, *vh = qkv + (size_t)2 * M4 * E;

    k_prep<<<dim3(LW / 4096, L), 256>>>(Wq, Wk, Wv, Wo, W1, W2, wh);
    k_pack3<<<dim3(3, L), 256>>>(bq, bk, bv, bqkv);
    k_embed<<<M4, 256>>>(x, emb, h, hh);

    const dim3 gQKV(6, 32, 3);     // BM=128
    const dim3 gEE64(6, 64);       // BM=64: Wo, FF2
    const dim3 gF164(24, 64);      // BM=64: FF1
    const dim3 gAt(4, NHEAD);      // fused attention

    for (int l = 0; l < L; l++) {
        const size_t wb = (size_t)l * LW;

        // fused QKV (launch #4 per layer-0 => ncu capture target)
        k_mma<128, 128><<<gQKV, 256, SMEM_QKV>>>(hh, wh + wb + OFF_Q,
            bqkv + (size_t)l * 3 * E, nullptr, nullptr, qkv,
            E, E, 0, (size_t)EE, (size_t)M4 * E, E, 1.f, 0);

        // fused attention: softmax(QK^T/8)V -> ch (fp16)
        k_attn<<<gAt, 256, AT_SMEM>>>(qh, kh, vh, ch);

        // Wo + residual -> LN1
        k_mma<64, 128><<<gEE64, 256, SMEM_W>>>(ch, wh + wb + OFF_O,
            bo + (size_t)l * E, h, t, nullptr,
            E, E, 0, 0, 0, 0, 1.f, 0);
        k_ln<<<M4 / 8, 256>>>(t, h, hh, ln1g + (size_t)l * E, ln1b + (size_t)l * E);

        // FFN
        k_mma<64, 128><<<gF164, 256, SMEM_W>>>(hh, wh + wb + OFF_1,
            b1 + (size_t)l * FF, nullptr, nullptr, fh,
            FF, E, 0, 0, 0, 0, 1.f, 1);
        k_mma<64, 128><<<gEE64, 256, SMEM_W>>>(fh, wh + wb + OFF_2,
            b2 + (size_t)l * E, h, t, nullptr,
            E, FF, 0, 0, 0, 0, 1.f, 0);
        k_ln<<<M4 / 8, 256>>>(t, h, hh, ln2g + (size_t)l * E, ln2b + (size_t)l * E);
    }

    // classifier (fp32 exact)
    k_cls1<<<dim3(B, CLS_P), 256>>>(h, Wc, t);
    k_cls2<<<1, 128>>>(t, bc, out);
}